// round 1
// baseline (speedup 1.0000x reference)
#include <cuda_runtime.h>
#include <math.h>

#define NB 4
#define NT 24
#define NP 4096
#define MM 128
#define TO 12
#define LTOK 1536
#define NTOK 6144
#define EDIM 512
#define NHEAD 8
#define DHEAD 64
#define MLPD 1024
#define NCLS 30
#define KSAMP 32
#define RAD2 0.09f

#define CONTR_OFF 120
#define FEAT_OFF (120 + NTOK*EDIM)

// ---------------- scratch (device globals; no cudaMalloc allowed) ----------
__device__ __align__(256) float g_anchor[NTOK*3];
__device__ __align__(256) int   g_ball[3*NTOK*KSAMP];
__device__ __align__(256) float g_x[NTOK*EDIM];
__device__ __align__(256) float g_h[NTOK*EDIM];
__device__ __align__(256) float g_qkv[NTOK*3*EDIM];
__device__ __align__(256) float g_o[NTOK*EDIM];
__device__ __align__(256) float g_f1[NTOK*MLPD];
__device__ __align__(256) float g_pool[NB*EDIM];
__device__ __align__(256) float g_hln[NB*EDIM];
__device__ __align__(256) float g_h1[NB*MLPD];

__device__ __forceinline__ float gelu_exact(float x){
    return 0.5f*x*(1.0f+erff(x*0.70710678118654752440f));
}

// ---------------- FPS: one block per (b, to) -------------------------------
// anchors[b,j] = xyzs[b, 2j]; select 128 farthest points, matching jnp.argmax
// (first-max tie-break) and plain (non-FMA) distance arithmetic.
__global__ __launch_bounds__(512) void fps_kernel(const float* __restrict__ xyzs) {
    int blk = blockIdx.x;               // 0..47
    int b = blk / TO, j = blk % TO;
    const float* P = xyzs + (size_t)(b*NT + 2*j)*NP*3;
    int tid = threadIdx.x;

    float px[8], py[8], pz[8], dist[8];
    #pragma unroll
    for (int i = 0; i < 8; i++) {
        int p = tid + i*512;
        px[i] = P[p*3+0]; py[i] = P[p*3+1]; pz[i] = P[p*3+2];
        dist[i] = 1e10f;
    }
    __shared__ float sbx, sby, sbz;
    __shared__ float swv[16];
    __shared__ int   swi[16];
    float* anch = g_anchor + (size_t)blk*MM*3;
    if (tid == 0) {
        sbx = P[0]; sby = P[1]; sbz = P[2];
        anch[0] = P[0]; anch[1] = P[1]; anch[2] = P[2];
    }
    __syncthreads();

    for (int s = 1; s < MM; s++) {
        float bx = sbx, by = sby, bz = sbz;
        float bestv = -1.0f; int besti = 0x7fffffff;
        #pragma unroll
        for (int i = 0; i < 8; i++) {
            float dx = __fsub_rn(px[i], bx);
            float dy = __fsub_rn(py[i], by);
            float dz = __fsub_rn(pz[i], bz);
            float d = __fadd_rn(__fadd_rn(__fmul_rn(dx,dx), __fmul_rn(dy,dy)), __fmul_rn(dz,dz));
            float nd = fminf(dist[i], d);
            dist[i] = nd;
            int p = tid + i*512;
            if (nd > bestv || (nd == bestv && p < besti)) { bestv = nd; besti = p; }
        }
        #pragma unroll
        for (int off = 16; off; off >>= 1) {
            float ov = __shfl_down_sync(0xffffffffu, bestv, off);
            int   oi = __shfl_down_sync(0xffffffffu, besti, off);
            if (ov > bestv || (ov == bestv && oi < besti)) { bestv = ov; besti = oi; }
        }
        if ((tid & 31) == 0) { swv[tid>>5] = bestv; swi[tid>>5] = besti; }
        __syncthreads();
        if (tid == 0) {
            float v = swv[0]; int ii = swi[0];
            #pragma unroll
            for (int w = 1; w < 16; w++)
                if (swv[w] > v || (swv[w] == v && swi[w] < ii)) { v = swv[w]; ii = swi[w]; }
            float x0 = P[ii*3+0], y0 = P[ii*3+1], z0 = P[ii*3+2];
            sbx = x0; sby = y0; sbz = z0;
            anch[s*3+0] = x0; anch[s*3+1] = y0; anch[s*3+2] = z0;
        }
        __syncthreads();
    }
}

// ---------------- Ball query: one warp per (o, token) ----------------------
__global__ __launch_bounds__(128) void ball_kernel(const float* __restrict__ xyzs) {
    int w = blockIdx.x*4 + (threadIdx.x >> 5);
    int lane = threadIdx.x & 31;
    int o = w / NTOK;
    int tok = w % NTOK;
    int b = tok / LTOK, loc = tok % LTOK, j = loc / MM;
    int pf = 2*j + o;
    int of = (pf == 0) ? 0 : (pf - 1);
    const float* P = xyzs + (size_t)(b*NT + of)*NP*3;
    float ax = g_anchor[tok*3+0], ay = g_anchor[tok*3+1], az = g_anchor[tok*3+2];
    int* out = g_ball + ((size_t)o*NTOK + tok)*KSAMP;

    int cnt = 0, first = 0; bool found = false;
    for (int base = 0; base < NP; base += 32) {
        int p = base + lane;
        float x = P[p*3+0], y = P[p*3+1], z = P[p*3+2];
        float dx = __fsub_rn(ax,x), dy = __fsub_rn(ay,y), dz = __fsub_rn(az,z);
        float d2 = __fadd_rn(__fadd_rn(__fmul_rn(dx,dx), __fmul_rn(dy,dy)), __fmul_rn(dz,dz));
        bool inside = d2 < RAD2;
        unsigned msk = __ballot_sync(0xffffffffu, inside);
        if (!found && msk) { first = base + __ffs(msk) - 1; found = true; }
        int pos = cnt + __popc(msk & ((1u << lane) - 1u));
        if (inside && pos < KSAMP) out[pos] = p;
        cnt += __popc(msk);
        if (cnt >= KSAMP) break;
    }
    if (lane >= cnt) out[lane] = found ? first : 0;
}

// ---------------- grouped conv + max pool: one block per token -------------
__global__ __launch_bounds__(128) void conv_kernel(
    const float* __restrict__ xyzs, const float* __restrict__ oldf,
    const float* __restrict__ Wd, const float* __restrict__ Wf,
    float* __restrict__ dout)
{
    int tok = blockIdx.x;
    int b = tok / LTOK, loc = tok % LTOK, j = loc / MM;
    int tid = threadIdx.x;
    __shared__ float sd[KSAMP][4];
    __shared__ float sf[KSAMP][2];
    float ax = g_anchor[tok*3+0], ay = g_anchor[tok*3+1], az = g_anchor[tok*3+2];

    float wd[4][4], wf[4][2], vmax[4];
    #pragma unroll
    for (int r = 0; r < 4; r++) {
        int d = tid + 128*r;
        wd[r][0] = Wd[d*4+0]; wd[r][1] = Wd[d*4+1]; wd[r][2] = Wd[d*4+2]; wd[r][3] = Wd[d*4+3];
        wf[r][0] = Wf[d*2+0]; wf[r][1] = Wf[d*2+1];
        vmax[r] = -3.402823466e38f;
    }
    for (int o = 0; o < 3; o++) {
        int pf = 2*j + o;
        int of = (pf == 0) ? 0 : (pf - 1);
        const float* P = xyzs + (size_t)(b*NT + of)*NP*3;
        const float* F = oldf + (size_t)(b*NT + of)*2*NP;
        __syncthreads();
        if (tid < KSAMP) {
            int idx = g_ball[((size_t)o*NTOK + tok)*KSAMP + tid];
            sd[tid][0] = P[idx*3+0] - ax;
            sd[tid][1] = P[idx*3+1] - ay;
            sd[tid][2] = P[idx*3+2] - az;
            sd[tid][3] = (float)(o - 1);
            sf[tid][0] = F[idx];
            sf[tid][1] = F[NP + idx];
        }
        __syncthreads();
        #pragma unroll 4
        for (int k = 0; k < KSAMP; k++) {
            float d0 = sd[k][0], d1 = sd[k][1], d2 = sd[k][2], d3 = sd[k][3];
            float f0 = sf[k][0], f1 = sf[k][1];
            #pragma unroll
            for (int r = 0; r < 4; r++) {
                float de = wd[r][0]*d0 + wd[r][1]*d1 + wd[r][2]*d2 + wd[r][3]*d3;
                float fe = wf[r][0]*f0 + wf[r][1]*f1;
                vmax[r] = fmaxf(vmax[r], de*fe);
            }
        }
    }
    #pragma unroll
    for (int r = 0; r < 4; r++)
        dout[FEAT_OFF + (size_t)tok*EDIM + tid + 128*r] = vmax[r];
}

// ---------------- pos + contrastive + relu(pos+feat) -----------------------
__global__ __launch_bounds__(512) void embed_kernel(
    const float* __restrict__ pw, const float* __restrict__ pb,
    const float* __restrict__ cw, const float* __restrict__ cb,
    float* __restrict__ dout)
{
    int tok = blockIdx.x;
    int d = threadIdx.x;
    int loc = tok % LTOK, j = loc / MM;
    float ax = g_anchor[tok*3+0], ay = g_anchor[tok*3+1], az = g_anchor[tok*3+2];
    float tv = (float)(j + 1);
    float pos = pw[d*4+0]*ax + pw[d*4+1]*ay + pw[d*4+2]*az + pw[d*4+3]*tv + pb[d];
    float con = cw[d*4+0]*ax + cw[d*4+1]*ay + cw[d*4+2]*az + cw[d*4+3]*tv + cb[d];
    dout[CONTR_OFF + (size_t)tok*EDIM + d] = con;
    float feat = dout[FEAT_OFF + (size_t)tok*EDIM + d];
    g_x[(size_t)tok*EDIM + d] = fmaxf(pos + feat, 0.0f);
}

// ---------------- LayerNorm (rows of 512) ----------------------------------
__global__ __launch_bounds__(256) void ln_kernel(
    const float* __restrict__ x, const float* __restrict__ s,
    const float* __restrict__ bb, float* __restrict__ out)
{
    int tok = blockIdx.x;
    int tid = threadIdx.x;
    const float* row = x + (size_t)tok*EDIM;
    float v0 = row[tid], v1 = row[tid + 256];
    float sum = v0 + v1, sq = v0*v0 + v1*v1;
    #pragma unroll
    for (int off = 16; off; off >>= 1) {
        sum += __shfl_xor_sync(0xffffffffu, sum, off);
        sq  += __shfl_xor_sync(0xffffffffu, sq, off);
    }
    __shared__ float ssum[8], ssq[8];
    if ((tid & 31) == 0) { ssum[tid>>5] = sum; ssq[tid>>5] = sq; }
    __syncthreads();
    float ts = 0.f, tq = 0.f;
    #pragma unroll
    for (int w = 0; w < 8; w++) { ts += ssum[w]; tq += ssq[w]; }
    float mu = ts * (1.0f/512.0f);
    float var = tq * (1.0f/512.0f) - mu*mu;
    float rstd = rsqrtf(var + 1e-5f);
    out[(size_t)tok*EDIM + tid]       = (v0 - mu)*rstd*s[tid] + bb[tid];
    out[(size_t)tok*EDIM + tid + 256] = (v1 - mu)*rstd*s[tid+256] + bb[tid+256];
}

// ---------------- generic SGEMM: C[M,N] = A[M,K] @ W[N,K]^T (+bias/res/act)
// BM=BN=64, BK=16, 256 threads, 4x4 microtile.
template<int ACT, bool RESID, bool HASB>
__global__ __launch_bounds__(256) void gemm_bt(
    const float* __restrict__ A, const float* __restrict__ W,
    const float* __restrict__ bias, float* __restrict__ C,
    int N, int K)
{
    __shared__ float As[16][64];
    __shared__ float Ws[16][64];
    int tid = threadIdx.x;
    int bm = blockIdx.y*64, bn = blockIdx.x*64;
    int lr = tid >> 2;
    int lc = (tid & 3) * 4;
    int tm = (tid & 15) * 4;
    int tn = (tid >> 4) * 4;
    const float* Ap = A + (size_t)(bm + lr)*K + lc;
    const float* Wp = W + (size_t)(bn + lr)*K + lc;
    float acc[4][4] = {};

    for (int k0 = 0; k0 < K; k0 += 16) {
        float4 a4 = *(const float4*)(Ap + k0);
        float4 w4 = *(const float4*)(Wp + k0);
        As[lc+0][lr] = a4.x; As[lc+1][lr] = a4.y; As[lc+2][lr] = a4.z; As[lc+3][lr] = a4.w;
        Ws[lc+0][lr] = w4.x; Ws[lc+1][lr] = w4.y; Ws[lc+2][lr] = w4.z; Ws[lc+3][lr] = w4.w;
        __syncthreads();
        #pragma unroll
        for (int kk = 0; kk < 16; kk++) {
            float4 av = *(const float4*)&As[kk][tm];
            float4 wv = *(const float4*)&Ws[kk][tn];
            float a[4] = {av.x, av.y, av.z, av.w};
            float w[4] = {wv.x, wv.y, wv.z, wv.w};
            #pragma unroll
            for (int i = 0; i < 4; i++)
                #pragma unroll
                for (int jj = 0; jj < 4; jj++)
                    acc[i][jj] += a[i]*w[jj];
        }
        __syncthreads();
    }
    #pragma unroll
    for (int i = 0; i < 4; i++) {
        #pragma unroll
        for (int jj = 0; jj < 4; jj++) {
            float v = acc[i][jj];
            if (HASB) v += bias[bn + tn + jj];
            if (ACT == 1) v = gelu_exact(v);
            size_t ci = (size_t)(bm + tm + i)*N + bn + tn + jj;
            if (RESID) v += C[ci];
            C[ci] = v;
        }
    }
}

// ---------------- flash attention: block = (qtile16, head, batch) ----------
__global__ __launch_bounds__(256) void attn_kernel(
    const float* __restrict__ qkv, float* __restrict__ o)
{
    int qt0 = blockIdx.x * 16;
    int h = blockIdx.y, b = blockIdx.z;
    int tid = threadIdx.x;
    int q = tid >> 4;   // 0..15
    int g = tid & 15;   // 0..15
    __shared__ float Qs[16][65];
    __shared__ float Ks[32][65];
    __shared__ float Vs[32][65];
    __shared__ float Ps[16][32];
    const float* base = qkv + (size_t)b*LTOK*(3*EDIM);

    {
        const float* src = base + (size_t)(qt0 + q)*(3*EDIM) + h*64 + g*4;
        float4 v = *(const float4*)src;
        Qs[q][g*4+0] = v.x; Qs[q][g*4+1] = v.y; Qs[q][g*4+2] = v.z; Qs[q][g*4+3] = v.w;
    }
    float m = -3.402823466e38f, ssum = 0.f;
    float a0 = 0.f, a1 = 0.f, a2 = 0.f, a3 = 0.f;
    const float scale = 0.125f;

    for (int kt0 = 0; kt0 < LTOK; kt0 += 32) {
        __syncthreads();
        {
            int kr = tid >> 3;
            int c = (tid & 7) * 8;
            const float* ksrc = base + (size_t)(kt0 + kr)*(3*EDIM) + EDIM + h*64 + c;
            const float* vsrc = base + (size_t)(kt0 + kr)*(3*EDIM) + 2*EDIM + h*64 + c;
            float4 k0 = *(const float4*)ksrc;     float4 k1 = *(const float4*)(ksrc+4);
            float4 v0 = *(const float4*)vsrc;     float4 v1 = *(const float4*)(vsrc+4);
            Ks[kr][c+0]=k0.x; Ks[kr][c+1]=k0.y; Ks[kr][c+2]=k0.z; Ks[kr][c+3]=k0.w;
            Ks[kr][c+4]=k1.x; Ks[kr][c+5]=k1.y; Ks[kr][c+6]=k1.z; Ks[kr][c+7]=k1.w;
            Vs[kr][c+0]=v0.x; Vs[kr][c+1]=v0.y; Vs[kr][c+2]=v0.z; Vs[kr][c+3]=v0.w;
            Vs[kr][c+4]=v1.x; Vs[kr][c+5]=v1.y; Vs[kr][c+6]=v1.z; Vs[kr][c+7]=v1.w;
        }
        __syncthreads();
        int k1i = 2*g, k2i = 2*g + 1;
        float s1 = 0.f, s2 = 0.f;
        #pragma unroll
        for (int d = 0; d < 64; d++) {
            float qv = Qs[q][d];
            s1 += qv * Ks[k1i][d];
            s2 += qv * Ks[k2i][d];
        }
        s1 *= scale; s2 *= scale;
        float tmax = fmaxf(s1, s2);
        #pragma unroll
        for (int off = 8; off; off >>= 1)
            tmax = fmaxf(tmax, __shfl_xor_sync(0xffffffffu, tmax, off));
        float mnew = fmaxf(m, tmax);
        float corr = expf(m - mnew);
        a0 *= corr; a1 *= corr; a2 *= corr; a3 *= corr; ssum *= corr;
        float p1 = expf(s1 - mnew), p2 = expf(s2 - mnew);
        float ps = p1 + p2;
        #pragma unroll
        for (int off = 8; off; off >>= 1)
            ps += __shfl_xor_sync(0xffffffffu, ps, off);
        ssum += ps;
        Ps[q][k1i] = p1; Ps[q][k2i] = p2;
        m = mnew;
        __syncwarp();
        #pragma unroll
        for (int k = 0; k < 32; k++) {
            float p = Ps[q][k];
            a0 += p * Vs[k][g*4+0];
            a1 += p * Vs[k][g*4+1];
            a2 += p * Vs[k][g*4+2];
            a3 += p * Vs[k][g*4+3];
        }
    }
    float inv = 1.0f / ssum;
    float* dst = o + (size_t)(b*LTOK + qt0 + q)*EDIM + h*64 + g*4;
    dst[0] = a0*inv; dst[1] = a1*inv; dst[2] = a2*inv; dst[3] = a3*inv;
}

// ---------------- head: max pool over tokens -------------------------------
__global__ __launch_bounds__(512) void pool_kernel() {
    int b = blockIdx.x;
    int d = threadIdx.x;
    float v = -3.402823466e38f;
    const float* p = g_x + (size_t)b*LTOK*EDIM + d;
    for (int i = 0; i < LTOK; i++) v = fmaxf(v, p[(size_t)i*EDIM]);
    g_pool[b*EDIM + d] = v;
}

__global__ __launch_bounds__(256) void head1_kernel(
    const float* __restrict__ W, const float* __restrict__ bias)
{
    int out = blockIdx.x*8 + (threadIdx.x >> 5);  // 0..4095 (b*1024 + j)
    int lane = threadIdx.x & 31;
    int b = out >> 10, jj = out & 1023;
    const float* xr = g_hln + b*EDIM;
    const float* wr = W + (size_t)jj*EDIM;
    float s = 0.f;
    for (int d = lane; d < EDIM; d += 32) s += xr[d]*wr[d];
    #pragma unroll
    for (int off = 16; off; off >>= 1) s += __shfl_xor_sync(0xffffffffu, s, off);
    if (lane == 0) g_h1[out] = gelu_exact(s + bias[jj]);
}

__global__ __launch_bounds__(128) void head2_kernel(
    const float* __restrict__ W, const float* __restrict__ bias,
    float* __restrict__ dout)
{
    int out = blockIdx.x*4 + (threadIdx.x >> 5);  // 0..119
    int lane = threadIdx.x & 31;
    int b = out / NCLS, c = out % NCLS;
    float s = 0.f;
    for (int d = lane; d < MLPD; d += 32) s += g_h1[b*MLPD + d]*W[(size_t)c*MLPD + d];
    #pragma unroll
    for (int off = 16; off; off >>= 1) s += __shfl_xor_sync(0xffffffffu, s, off);
    if (lane == 0) dout[out] = s + bias[c];
}

// ---------------- launch ---------------------------------------------------
extern "C" void kernel_launch(void* const* d_in, const int* in_sizes, int n_in,
                              void* d_out, int out_size) {
    const float* xyzs      = (const float*)d_in[0];
    const float* oldf      = (const float*)d_in[1];
    const float* conv_d_w  = (const float*)d_in[2];
    const float* conv_f_w  = (const float*)d_in[3];
    const float* pos_w     = (const float*)d_in[4];
    const float* pos_b     = (const float*)d_in[5];
    const float* contr_w   = (const float*)d_in[6];
    const float* contr_b   = (const float*)d_in[7];
    const float* ln1_s     = (const float*)d_in[8];
    const float* ln1_b     = (const float*)d_in[9];
    const float* qkv_w     = (const float*)d_in[10];
    const float* out_w     = (const float*)d_in[11];
    const float* out_b     = (const float*)d_in[12];
    const float* ln2_s     = (const float*)d_in[13];
    const float* ln2_b     = (const float*)d_in[14];
    const float* ff1_w     = (const float*)d_in[15];
    const float* ff1_b     = (const float*)d_in[16];
    const float* ff2_w     = (const float*)d_in[17];
    const float* ff2_b     = (const float*)d_in[18];
    const float* head_ln_s = (const float*)d_in[19];
    const float* head_ln_b = (const float*)d_in[20];
    const float* head1_w   = (const float*)d_in[21];
    const float* head1_b   = (const float*)d_in[22];
    const float* head2_w   = (const float*)d_in[23];
    const float* head2_b   = (const float*)d_in[24];
    float* out = (float*)d_out;

    float *px, *ph, *pqkv, *po, *pf1, *ppool, *phln;
    cudaGetSymbolAddress((void**)&px,    g_x);
    cudaGetSymbolAddress((void**)&ph,    g_h);
    cudaGetSymbolAddress((void**)&pqkv,  g_qkv);
    cudaGetSymbolAddress((void**)&po,    g_o);
    cudaGetSymbolAddress((void**)&pf1,   g_f1);
    cudaGetSymbolAddress((void**)&ppool, g_pool);
    cudaGetSymbolAddress((void**)&phln,  g_hln);

    fps_kernel<<<48, 512>>>(xyzs);
    ball_kernel<<<(3*NTOK)/4, 128>>>(xyzs);
    conv_kernel<<<NTOK, 128>>>(xyzs, oldf, conv_d_w, conv_f_w, out);
    embed_kernel<<<NTOK, 512>>>(pos_w, pos_b, contr_w, contr_b, out);

    for (int l = 0; l < 4; l++) {
        ln_kernel<<<NTOK, 256>>>(px, ln1_s + l*EDIM, ln1_b + l*EDIM, ph);
        gemm_bt<0, false, false><<<dim3(3*EDIM/64, NTOK/64), 256>>>(
            ph, qkv_w + (size_t)l*3*EDIM*EDIM, nullptr, pqkv, 3*EDIM, EDIM);
        attn_kernel<<<dim3(LTOK/16, NHEAD, NB), 256>>>(pqkv, po);
        gemm_bt<0, true, true><<<dim3(EDIM/64, NTOK/64), 256>>>(
            po, out_w + (size_t)l*EDIM*EDIM, out_b + l*EDIM, px, EDIM, EDIM);
        ln_kernel<<<NTOK, 256>>>(px, ln2_s + l*EDIM, ln2_b + l*EDIM, ph);
        gemm_bt<1, false, true><<<dim3(MLPD/64, NTOK/64), 256>>>(
            ph, ff1_w + (size_t)l*MLPD*EDIM, ff1_b + l*MLPD, pf1, MLPD, EDIM);
        gemm_bt<0, true, true><<<dim3(EDIM/64, NTOK/64), 256>>>(
            pf1, ff2_w + (size_t)l*EDIM*MLPD, ff2_b + l*EDIM, px, EDIM, MLPD);
    }

    pool_kernel<<<NB, 512>>>();
    ln_kernel<<<NB, 256>>>(ppool, head_ln_s, head_ln_b, phln);
    head1_kernel<<<(NB*MLPD)/8, 256>>>(head1_w, head1_b);
    head2_kernel<<<NB*NCLS/4, 128>>>(head2_w, head2_b, out);
}

// round 4
// speedup vs baseline: 2.6507x; 2.6507x over previous
#include <cuda_runtime.h>
#include <cuda_bf16.h>
#include <cstdint>
#include <math.h>

#define NB 4
#define NT 24
#define NP 4096
#define MM 128
#define TO 12
#define LTOK 1536
#define NTOK 6144
#define EDIM 512
#define NHEAD 8
#define DHEAD 64
#define MLPD 1024
#define NCLS 30
#define KSAMP 32
#define RAD2 0.09f

#define CONTR_OFF 120
#define FEAT_OFF (120 + NTOK*EDIM)
#define SSTR ((long long)LTOK*LTOK)

// ---------------- scratch (device globals; no cudaMalloc allowed) ----------
__device__ __align__(256) float g_anchor[NTOK*3];
__device__ __align__(256) int   g_ball[3*NTOK*KSAMP];
__device__ __align__(256) float g_x[NTOK*EDIM];
__device__ __align__(256) float g_h[NTOK*EDIM];
__device__ __align__(256) float g_qkv[NTOK*3*EDIM];
__device__ __align__(256) float g_o[NTOK*EDIM];
__device__ __align__(256) float g_f1[NTOK*MLPD];
__device__ __align__(256) float g_scores[(size_t)NB*NHEAD*LTOK*LTOK];
__device__ __align__(256) float g_pool[NB*EDIM];
__device__ __align__(256) float g_hln[NB*EDIM];
__device__ __align__(256) float g_h1[NB*MLPD];

__device__ __forceinline__ float gelu_exact(float x){
    return 0.5f*x*(1.0f+erff(x*0.70710678118654752440f));
}

// ==================== HMMA (mma.sync) helpers ==============================
__device__ __forceinline__ void mma16816(float* c, const unsigned* a, const unsigned* b){
    asm volatile("mma.sync.aligned.m16n8k16.row.col.f32.bf16.bf16.f32 "
        "{%0,%1,%2,%3}, {%4,%5,%6,%7}, {%8,%9}, {%0,%1,%2,%3};"
        : "+f"(c[0]),"+f"(c[1]),"+f"(c[2]),"+f"(c[3])
        : "r"(a[0]),"r"(a[1]),"r"(a[2]),"r"(a[3]), "r"(b[0]),"r"(b[1]));
}
// pack fp32 pair -> bf16x2 hi and residual lo
__device__ __forceinline__ void split2(float x, float y, unsigned& hi, unsigned& lo){
    __nv_bfloat16 hx = __float2bfloat16(x), hy = __float2bfloat16(y);
    float rx = x - __bfloat162float(hx), ry = y - __bfloat162float(hy);
    __nv_bfloat16 lx = __float2bfloat16(rx), ly = __float2bfloat16(ry);
    hi = (unsigned)__bfloat16_as_ushort(hx) | ((unsigned)__bfloat16_as_ushort(hy) << 16);
    lo = (unsigned)__bfloat16_as_ushort(lx) | ((unsigned)__bfloat16_as_ushort(ly) << 16);
}

#define LDT 40   // smem row stride in bf16 (32 + 8 pad)

// ============ GEMM (W row-major [N,K]): C = alpha*(A@W^T) (+bias)(gelu)(+C)
// BM=128, BN=128, BK=32, 256 threads, warps 2(M)x4(N), warp tile 64x32.
// 3-term bf16 split, fp32 accum.
__global__ __launch_bounds__(256) void tgemm_w(
    const float* __restrict__ A, const float* __restrict__ W,
    const float* __restrict__ bias, float* __restrict__ C,
    int K, int lda, int ldw, int ldc, float alpha,
    long long sAb, long long sAh, long long sWb, long long sWh,
    long long sCb, long long sCh,
    int act, int resid, int hasb)
{
    __shared__ __nv_bfloat16 AH[128][LDT];
    __shared__ __nv_bfloat16 AL[128][LDT];
    __shared__ __nv_bfloat16 WH[128][LDT];
    __shared__ __nv_bfloat16 WL[128][LDT];

    int tid = threadIdx.x, wid = tid >> 5, lane = tid & 31;
    int g = lane >> 2, tg = lane & 3;
    int rw = (wid >> 2) * 64, cw = (wid & 3) * 32;
    int z = blockIdx.z;
    const float* Ab = A + (long long)(z >> 3) * sAb + (long long)(z & 7) * sAh;
    const float* Wb = W + (long long)(z >> 3) * sWb + (long long)(z & 7) * sWh;
    float* Cb = C + (long long)(z >> 3) * sCb + (long long)(z & 7) * sCh;
    int bm = blockIdx.y * 128, bn = blockIdx.x * 128;

    float acc[4][4][4];
    #pragma unroll
    for (int i = 0; i < 4; i++)
        #pragma unroll
        for (int j = 0; j < 4; j++)
            #pragma unroll
            for (int q = 0; q < 4; q++) acc[i][j][q] = 0.f;

    int lr = tid >> 1;
    int lh = (tid & 1) * 16;
    int nch = K >> 5;
    for (int c = 0; c < nch; c++) {
        if (c) __syncthreads();
        const float* ap = Ab + (size_t)(bm + lr) * lda + c * 32 + lh;
        const float* wp = Wb + (size_t)(bn + lr) * ldw + c * 32 + lh;
        #pragma unroll
        for (int j = 0; j < 4; j++) {
            float4 a = *(const float4*)(ap + j*4);
            unsigned h0, l0, h1, l1;
            split2(a.x, a.y, h0, l0); split2(a.z, a.w, h1, l1);
            int cc = lh + j*4;
            *(unsigned*)&AH[lr][cc]   = h0; *(unsigned*)&AH[lr][cc+2] = h1;
            *(unsigned*)&AL[lr][cc]   = l0; *(unsigned*)&AL[lr][cc+2] = l1;
            float4 w = *(const float4*)(wp + j*4);
            split2(w.x, w.y, h0, l0); split2(w.z, w.w, h1, l1);
            *(unsigned*)&WH[lr][cc]   = h0; *(unsigned*)&WH[lr][cc+2] = h1;
            *(unsigned*)&WL[lr][cc]   = l0; *(unsigned*)&WL[lr][cc+2] = l1;
        }
        __syncthreads();
        #pragma unroll
        for (int ks = 0; ks < 2; ks++) {
            int k0 = ks * 16 + tg * 2;
            unsigned ah[4][4], al[4][4], bh[4][2], bl[4][2];
            #pragma unroll
            for (int mt = 0; mt < 4; mt++) {
                int r0 = rw + mt*16 + g;
                ah[mt][0] = *(const unsigned*)&AH[r0][k0];
                ah[mt][1] = *(const unsigned*)&AH[r0+8][k0];
                ah[mt][2] = *(const unsigned*)&AH[r0][k0+8];
                ah[mt][3] = *(const unsigned*)&AH[r0+8][k0+8];
                al[mt][0] = *(const unsigned*)&AL[r0][k0];
                al[mt][1] = *(const unsigned*)&AL[r0+8][k0];
                al[mt][2] = *(const unsigned*)&AL[r0][k0+8];
                al[mt][3] = *(const unsigned*)&AL[r0+8][k0+8];
            }
            #pragma unroll
            for (int nt = 0; nt < 4; nt++) {
                int c0 = cw + nt*8 + g;
                bh[nt][0] = *(const unsigned*)&WH[c0][k0];
                bh[nt][1] = *(const unsigned*)&WH[c0][k0+8];
                bl[nt][0] = *(const unsigned*)&WL[c0][k0];
                bl[nt][1] = *(const unsigned*)&WL[c0][k0+8];
            }
            #pragma unroll
            for (int mt = 0; mt < 4; mt++)
                #pragma unroll
                for (int nt = 0; nt < 4; nt++) {
                    mma16816(acc[mt][nt], ah[mt], bh[nt]);
                    mma16816(acc[mt][nt], ah[mt], bl[nt]);
                    mma16816(acc[mt][nt], al[mt], bh[nt]);
                }
        }
    }
    // epilogue
    #pragma unroll
    for (int mt = 0; mt < 4; mt++) {
        #pragma unroll
        for (int nt = 0; nt < 4; nt++) {
            int row = bm + rw + mt*16 + g;
            int col = bn + cw + nt*8 + tg*2;
            #pragma unroll
            for (int half = 0; half < 2; half++) {
                int r = row + half*8;
                float v0 = acc[mt][nt][half*2+0] * alpha;
                float v1 = acc[mt][nt][half*2+1] * alpha;
                if (hasb) { v0 += bias[col]; v1 += bias[col+1]; }
                if (act)  { v0 = gelu_exact(v0); v1 = gelu_exact(v1); }
                float* cp = Cb + (size_t)r * ldc + col;
                if (resid) {
                    float2 old = *(float2*)cp;
                    v0 += old.x; v1 += old.y;
                }
                float2 ov = {v0, v1};
                *(float2*)cp = ov;
            }
        }
    }
}

// ============ PV GEMM: C = A @ V, V col-major (V[n,k] at Vb + k*ldw + n)
// BM=128, BN=64, BK=32, 256 threads, warps 2(M)x4(N), warp tile 64x16.
__global__ __launch_bounds__(256) void tgemm_pv(
    const float* __restrict__ A, const float* __restrict__ W,
    float* __restrict__ C,
    int K, int lda, int ldw, int ldc,
    long long sAb, long long sAh, long long sWb, long long sWh,
    long long sCb, long long sCh)
{
    __shared__ __nv_bfloat16 AH[128][LDT];
    __shared__ __nv_bfloat16 AL[128][LDT];
    __shared__ __nv_bfloat16 VH[64][LDT];
    __shared__ __nv_bfloat16 VL[64][LDT];

    int tid = threadIdx.x, wid = tid >> 5, lane = tid & 31;
    int g = lane >> 2, tg = lane & 3;
    int rw = (wid >> 2) * 64, cw = (wid & 3) * 16;
    int z = blockIdx.z;
    const float* Ab = A + (long long)(z >> 3) * sAb + (long long)(z & 7) * sAh;
    const float* Wb = W + (long long)(z >> 3) * sWb + (long long)(z & 7) * sWh;
    float* Cb = C + (long long)(z >> 3) * sCb + (long long)(z & 7) * sCh;
    int bm = blockIdx.y * 128;

    float acc[4][2][4];
    #pragma unroll
    for (int i = 0; i < 4; i++)
        #pragma unroll
        for (int j = 0; j < 2; j++)
            #pragma unroll
            for (int q = 0; q < 4; q++) acc[i][j][q] = 0.f;

    int lr = tid >> 1;
    int lh = (tid & 1) * 16;
    int vk = tid >> 3;            // 0..31
    int vn = (tid & 7) * 8;       // 0..56
    int nch = K >> 5;
    for (int c = 0; c < nch; c++) {
        if (c) __syncthreads();
        const float* ap = Ab + (size_t)(bm + lr) * lda + c * 32 + lh;
        #pragma unroll
        for (int j = 0; j < 4; j++) {
            float4 a = *(const float4*)(ap + j*4);
            unsigned h0, l0, h1, l1;
            split2(a.x, a.y, h0, l0); split2(a.z, a.w, h1, l1);
            int cc = lh + j*4;
            *(unsigned*)&AH[lr][cc]   = h0; *(unsigned*)&AH[lr][cc+2] = h1;
            *(unsigned*)&AL[lr][cc]   = l0; *(unsigned*)&AL[lr][cc+2] = l1;
        }
        {
            const float* vp = Wb + (size_t)(c*32 + vk) * ldw + vn;
            float4 v0 = *(const float4*)vp;
            float4 v1 = *(const float4*)(vp + 4);
            float vv[8] = {v0.x, v0.y, v0.z, v0.w, v1.x, v1.y, v1.z, v1.w};
            #pragma unroll
            for (int i = 0; i < 8; i++) {
                __nv_bfloat16 h = __float2bfloat16(vv[i]);
                float rr = vv[i] - __bfloat162float(h);
                VH[vn + i][vk] = h;
                VL[vn + i][vk] = __float2bfloat16(rr);
            }
        }
        __syncthreads();
        #pragma unroll
        for (int ks = 0; ks < 2; ks++) {
            int k0 = ks * 16 + tg * 2;
            unsigned ah[4][4], al[4][4], bh[2][2], bl[2][2];
            #pragma unroll
            for (int mt = 0; mt < 4; mt++) {
                int r0 = rw + mt*16 + g;
                ah[mt][0] = *(const unsigned*)&AH[r0][k0];
                ah[mt][1] = *(const unsigned*)&AH[r0+8][k0];
                ah[mt][2] = *(const unsigned*)&AH[r0][k0+8];
                ah[mt][3] = *(const unsigned*)&AH[r0+8][k0+8];
                al[mt][0] = *(const unsigned*)&AL[r0][k0];
                al[mt][1] = *(const unsigned*)&AL[r0+8][k0];
                al[mt][2] = *(const unsigned*)&AL[r0][k0+8];
                al[mt][3] = *(const unsigned*)&AL[r0+8][k0+8];
            }
            #pragma unroll
            for (int nt = 0; nt < 2; nt++) {
                int c0 = cw + nt*8 + g;
                bh[nt][0] = *(const unsigned*)&VH[c0][k0];
                bh[nt][1] = *(const unsigned*)&VH[c0][k0+8];
                bl[nt][0] = *(const unsigned*)&VL[c0][k0];
                bl[nt][1] = *(const unsigned*)&VL[c0][k0+8];
            }
            #pragma unroll
            for (int mt = 0; mt < 4; mt++)
                #pragma unroll
                for (int nt = 0; nt < 2; nt++) {
                    mma16816(acc[mt][nt], ah[mt], bh[nt]);
                    mma16816(acc[mt][nt], ah[mt], bl[nt]);
                    mma16816(acc[mt][nt], al[mt], bh[nt]);
                }
        }
    }
    #pragma unroll
    for (int mt = 0; mt < 4; mt++) {
        #pragma unroll
        for (int nt = 0; nt < 2; nt++) {
            int row = bm + rw + mt*16 + g;
            int col = cw + nt*8 + tg*2;
            #pragma unroll
            for (int half = 0; half < 2; half++) {
                int r = row + half*8;
                float2 ov = {acc[mt][nt][half*2+0], acc[mt][nt][half*2+1]};
                *(float2*)(Cb + (size_t)r * ldc + col) = ov;
            }
        }
    }
}

// ---------------- softmax over rows of g_scores (len 1536) -----------------
__global__ __launch_bounds__(128) void softmax_kernel() {
    size_t row = blockIdx.x;
    float* p = g_scores + row * LTOK;
    int t = threadIdx.x;
    float4 v[3];
    #pragma unroll
    for (int i = 0; i < 3; i++) v[i] = ((float4*)p)[t + i*128];
    float mx = -3.402823466e38f;
    #pragma unroll
    for (int i = 0; i < 3; i++)
        mx = fmaxf(mx, fmaxf(fmaxf(v[i].x, v[i].y), fmaxf(v[i].z, v[i].w)));
    #pragma unroll
    for (int off = 16; off; off >>= 1) mx = fmaxf(mx, __shfl_xor_sync(0xffffffffu, mx, off));
    __shared__ float sm[4], ss[4];
    if ((t & 31) == 0) sm[t >> 5] = mx;
    __syncthreads();
    mx = fmaxf(fmaxf(sm[0], sm[1]), fmaxf(sm[2], sm[3]));
    float sum = 0.f;
    #pragma unroll
    for (int i = 0; i < 3; i++) {
        v[i].x = expf(v[i].x - mx); v[i].y = expf(v[i].y - mx);
        v[i].z = expf(v[i].z - mx); v[i].w = expf(v[i].w - mx);
        sum += v[i].x + v[i].y + v[i].z + v[i].w;
    }
    #pragma unroll
    for (int off = 16; off; off >>= 1) sum += __shfl_xor_sync(0xffffffffu, sum, off);
    if ((t & 31) == 0) ss[t >> 5] = sum;
    __syncthreads();
    sum = ss[0] + ss[1] + ss[2] + ss[3];
    float inv = 1.0f / sum;
    #pragma unroll
    for (int i = 0; i < 3; i++) {
        v[i].x *= inv; v[i].y *= inv; v[i].z *= inv; v[i].w *= inv;
        ((float4*)p)[t + i*128] = v[i];
    }
}

// ---------------- FPS: one block per (b, to) -------------------------------
__global__ __launch_bounds__(512) void fps_kernel(const float* __restrict__ xyzs) {
    int blk = blockIdx.x;
    int b = blk / TO, j = blk % TO;
    const float* P = xyzs + (size_t)(b*NT + 2*j)*NP*3;
    int tid = threadIdx.x;
    float px[8], py[8], pz[8], dist[8];
    #pragma unroll
    for (int i = 0; i < 8; i++) {
        int p = tid + i*512;
        px[i] = P[p*3+0]; py[i] = P[p*3+1]; pz[i] = P[p*3+2];
        dist[i] = 1e10f;
    }
    __shared__ float sbx, sby, sbz;
    __shared__ float swv[16];
    __shared__ int   swi[16];
    float* anch = g_anchor + (size_t)blk*MM*3;
    if (tid == 0) {
        sbx = P[0]; sby = P[1]; sbz = P[2];
        anch[0] = P[0]; anch[1] = P[1]; anch[2] = P[2];
    }
    __syncthreads();
    for (int s = 1; s < MM; s++) {
        float bx = sbx, by = sby, bz = sbz;
        float bestv = -1.0f; int besti = 0x7fffffff;
        #pragma unroll
        for (int i = 0; i < 8; i++) {
            float dx = __fsub_rn(px[i], bx);
            float dy = __fsub_rn(py[i], by);
            float dz = __fsub_rn(pz[i], bz);
            float d = __fadd_rn(__fadd_rn(__fmul_rn(dx,dx), __fmul_rn(dy,dy)), __fmul_rn(dz,dz));
            float nd = fminf(dist[i], d);
            dist[i] = nd;
            int p = tid + i*512;
            if (nd > bestv || (nd == bestv && p < besti)) { bestv = nd; besti = p; }
        }
        #pragma unroll
        for (int off = 16; off; off >>= 1) {
            float ov = __shfl_down_sync(0xffffffffu, bestv, off);
            int   oi = __shfl_down_sync(0xffffffffu, besti, off);
            if (ov > bestv || (ov == bestv && oi < besti)) { bestv = ov; besti = oi; }
        }
        if ((tid & 31) == 0) { swv[tid>>5] = bestv; swi[tid>>5] = besti; }
        __syncthreads();
        if (tid == 0) {
            float v = swv[0]; int ii = swi[0];
            #pragma unroll
            for (int w = 1; w < 16; w++)
                if (swv[w] > v || (swv[w] == v && swi[w] < ii)) { v = swv[w]; ii = swi[w]; }
            float x0 = P[ii*3+0], y0 = P[ii*3+1], z0 = P[ii*3+2];
            sbx = x0; sby = y0; sbz = z0;
            anch[s*3+0] = x0; anch[s*3+1] = y0; anch[s*3+2] = z0;
        }
        __syncthreads();
    }
}

// ---------------- Ball query: one warp per (o, token) ----------------------
__global__ __launch_bounds__(128) void ball_kernel(const float* __restrict__ xyzs) {
    int w = blockIdx.x*4 + (threadIdx.x >> 5);
    int lane = threadIdx.x & 31;
    int o = w / NTOK;
    int tok = w % NTOK;
    int b = tok / LTOK, loc = tok % LTOK, j = loc / MM;
    int pf = 2*j + o;
    int of = (pf == 0) ? 0 : (pf - 1);
    const float* P = xyzs + (size_t)(b*NT + of)*NP*3;
    float ax = g_anchor[tok*3+0], ay = g_anchor[tok*3+1], az = g_anchor[tok*3+2];
    int* out = g_ball + ((size_t)o*NTOK + tok)*KSAMP;
    int cnt = 0, first = 0; bool found = false;
    for (int base = 0; base < NP; base += 32) {
        int p = base + lane;
        float x = P[p*3+0], y = P[p*3+1], z = P[p*3+2];
        float dx = __fsub_rn(ax,x), dy = __fsub_rn(ay,y), dz = __fsub_rn(az,z);
        float d2 = __fadd_rn(__fadd_rn(__fmul_rn(dx,dx), __fmul_rn(dy,dy)), __fmul_rn(dz,dz));
        bool inside = d2 < RAD2;
        unsigned msk = __ballot_sync(0xffffffffu, inside);
        if (!found && msk) { first = base + __ffs(msk) - 1; found = true; }
        int pos = cnt + __popc(msk & ((1u << lane) - 1u));
        if (inside && pos < KSAMP) out[pos] = p;
        cnt += __popc(msk);
        if (cnt >= KSAMP) break;
    }
    if (lane >= cnt) out[lane] = found ? first : 0;
}

// ---------------- grouped conv + max pool ----------------------------------
__global__ __launch_bounds__(128) void conv_kernel(
    const float* __restrict__ xyzs, const float* __restrict__ oldf,
    const float* __restrict__ Wd, const float* __restrict__ Wf,
    float* __restrict__ dout)
{
    int tok = blockIdx.x;
    int b = tok / LTOK, loc = tok % LTOK, j = loc / MM;
    int tid = threadIdx.x;
    __shared__ float sd[KSAMP][4];
    __shared__ float sf[KSAMP][2];
    float ax = g_anchor[tok*3+0], ay = g_anchor[tok*3+1], az = g_anchor[tok*3+2];
    float wd[4][4], wf[4][2], vmax[4];
    #pragma unroll
    for (int r = 0; r < 4; r++) {
        int d = tid + 128*r;
        wd[r][0] = Wd[d*4+0]; wd[r][1] = Wd[d*4+1]; wd[r][2] = Wd[d*4+2]; wd[r][3] = Wd[d*4+3];
        wf[r][0] = Wf[d*2+0]; wf[r][1] = Wf[d*2+1];
        vmax[r] = -3.402823466e38f;
    }
    for (int o = 0; o < 3; o++) {
        int pf = 2*j + o;
        int of = (pf == 0) ? 0 : (pf - 1);
        const float* P = xyzs + (size_t)(b*NT + of)*NP*3;
        const float* F = oldf + (size_t)(b*NT + of)*2*NP;
        __syncthreads();
        if (tid < KSAMP) {
            int idx = g_ball[((size_t)o*NTOK + tok)*KSAMP + tid];
            sd[tid][0] = P[idx*3+0] - ax;
            sd[tid][1] = P[idx*3+1] - ay;
            sd[tid][2] = P[idx*3+2] - az;
            sd[tid][3] = (float)(o - 1);
            sf[tid][0] = F[idx];
            sf[tid][1] = F[NP + idx];
        }
        __syncthreads();
        #pragma unroll 4
        for (int k = 0; k < KSAMP; k++) {
            float d0 = sd[k][0], d1 = sd[k][1], d2 = sd[k][2], d3 = sd[k][3];
            float f0 = sf[k][0], f1 = sf[k][1];
            #pragma unroll
            for (int r = 0; r < 4; r++) {
                float de = wd[r][0]*d0 + wd[r][1]*d1 + wd[r][2]*d2 + wd[r][3]*d3;
                float fe = wf[r][0]*f0 + wf[r][1]*f1;
                vmax[r] = fmaxf(vmax[r], de*fe);
            }
        }
    }
    #pragma unroll
    for (int r = 0; r < 4; r++)
        dout[FEAT_OFF + (size_t)tok*EDIM + tid + 128*r] = vmax[r];
}

// ---------------- pos + contrastive + relu(pos+feat) -----------------------
__global__ __launch_bounds__(512) void embed_kernel(
    const float* __restrict__ pw, const float* __restrict__ pb,
    const float* __restrict__ cw, const float* __restrict__ cb,
    float* __restrict__ dout)
{
    int tok = blockIdx.x;
    int d = threadIdx.x;
    int loc = tok % LTOK, j = loc / MM;
    float ax = g_anchor[tok*3+0], ay = g_anchor[tok*3+1], az = g_anchor[tok*3+2];
    float tv = (float)(j + 1);
    float pos = pw[d*4+0]*ax + pw[d*4+1]*ay + pw[d*4+2]*az + pw[d*4+3]*tv + pb[d];
    float con = cw[d*4+0]*ax + cw[d*4+1]*ay + cw[d*4+2]*az + cw[d*4+3]*tv + cb[d];
    dout[CONTR_OFF + (size_t)tok*EDIM + d] = con;
    float feat = dout[FEAT_OFF + (size_t)tok*EDIM + d];
    g_x[(size_t)tok*EDIM + d] = fmaxf(pos + feat, 0.0f);
}

// ---------------- LayerNorm (rows of 512) ----------------------------------
__global__ __launch_bounds__(256) void ln_kernel(
    const float* __restrict__ x, const float* __restrict__ s,
    const float* __restrict__ bb, float* __restrict__ out)
{
    int tok = blockIdx.x;
    int tid = threadIdx.x;
    const float* row = x + (size_t)tok*EDIM;
    float v0 = row[tid], v1 = row[tid + 256];
    float sum = v0 + v1, sq = v0*v0 + v1*v1;
    #pragma unroll
    for (int off = 16; off; off >>= 1) {
        sum += __shfl_xor_sync(0xffffffffu, sum, off);
        sq  += __shfl_xor_sync(0xffffffffu, sq, off);
    }
    __shared__ float ssum[8], ssq[8];
    if ((tid & 31) == 0) { ssum[tid>>5] = sum; ssq[tid>>5] = sq; }
    __syncthreads();
    float ts = 0.f, tq = 0.f;
    #pragma unroll
    for (int w = 0; w < 8; w++) { ts += ssum[w]; tq += ssq[w]; }
    float mu = ts * (1.0f/512.0f);
    float var = tq * (1.0f/512.0f) - mu*mu;
    float rstd = rsqrtf(var + 1e-5f);
    out[(size_t)tok*EDIM + tid]       = (v0 - mu)*rstd*s[tid] + bb[tid];
    out[(size_t)tok*EDIM + tid + 256] = (v1 - mu)*rstd*s[tid+256] + bb[tid+256];
}

// ---------------- head ------------------------------------------------------
__global__ __launch_bounds__(512) void pool_kernel() {
    int b = blockIdx.x;
    int d = threadIdx.x;
    float v = -3.402823466e38f;
    const float* p = g_x + (size_t)b*LTOK*EDIM + d;
    for (int i = 0; i < LTOK; i++) v = fmaxf(v, p[(size_t)i*EDIM]);
    g_pool[b*EDIM + d] = v;
}
__global__ __launch_bounds__(256) void head1_kernel(
    const float* __restrict__ W, const float* __restrict__ bias)
{
    int out = blockIdx.x*8 + (threadIdx.x >> 5);
    int lane = threadIdx.x & 31;
    int b = out >> 10, jj = out & 1023;
    const float* xr = g_hln + b*EDIM;
    const float* wr = W + (size_t)jj*EDIM;
    float s = 0.f;
    for (int d = lane; d < EDIM; d += 32) s += xr[d]*wr[d];
    #pragma unroll
    for (int off = 16; off; off >>= 1) s += __shfl_xor_sync(0xffffffffu, s, off);
    if (lane == 0) g_h1[out] = gelu_exact(s + bias[jj]);
}
__global__ __launch_bounds__(128) void head2_kernel(
    const float* __restrict__ W, const float* __restrict__ bias,
    float* __restrict__ dout)
{
    int out = blockIdx.x*4 + (threadIdx.x >> 5);
    int lane = threadIdx.x & 31;
    int b = out / NCLS, c = out % NCLS;
    float s = 0.f;
    for (int d = lane; d < MLPD; d += 32) s += g_h1[b*MLPD + d]*W[(size_t)c*MLPD + d];
    #pragma unroll
    for (int off = 16; off; off >>= 1) s += __shfl_xor_sync(0xffffffffu, s, off);
    if (lane == 0) dout[out] = s + bias[c];
}

// ---------------- launch ---------------------------------------------------
extern "C" void kernel_launch(void* const* d_in, const int* in_sizes, int n_in,
                              void* d_out, int out_size) {
    const float* xyzs      = (const float*)d_in[0];
    const float* oldf      = (const float*)d_in[1];
    const float* conv_d_w  = (const float*)d_in[2];
    const float* conv_f_w  = (const float*)d_in[3];
    const float* pos_w     = (const float*)d_in[4];
    const float* pos_b     = (const float*)d_in[5];
    const float* contr_w   = (const float*)d_in[6];
    const float* contr_b   = (const float*)d_in[7];
    const float* ln1_s     = (const float*)d_in[8];
    const float* ln1_b     = (const float*)d_in[9];
    const float* qkv_w     = (const float*)d_in[10];
    const float* out_w     = (const float*)d_in[11];
    const float* out_b     = (const float*)d_in[12];
    const float* ln2_s     = (const float*)d_in[13];
    const float* ln2_b     = (const float*)d_in[14];
    const float* ff1_w     = (const float*)d_in[15];
    const float* ff1_b     = (const float*)d_in[16];
    const float* ff2_w     = (const float*)d_in[17];
    const float* ff2_b     = (const float*)d_in[18];
    const float* head_ln_s = (const float*)d_in[19];
    const float* head_ln_b = (const float*)d_in[20];
    const float* head1_w   = (const float*)d_in[21];
    const float* head1_b   = (const float*)d_in[22];
    const float* head2_w   = (const float*)d_in[23];
    const float* head2_b   = (const float*)d_in[24];
    float* out = (float*)d_out;

    float *px, *ph, *pqkv, *po, *pf1, *ppool, *phln, *psc;
    cudaGetSymbolAddress((void**)&px,    g_x);
    cudaGetSymbolAddress((void**)&ph,    g_h);
    cudaGetSymbolAddress((void**)&pqkv,  g_qkv);
    cudaGetSymbolAddress((void**)&po,    g_o);
    cudaGetSymbolAddress((void**)&pf1,   g_f1);
    cudaGetSymbolAddress((void**)&ppool, g_pool);
    cudaGetSymbolAddress((void**)&phln,  g_hln);
    cudaGetSymbolAddress((void**)&psc,   g_scores);

    fps_kernel<<<48, 512>>>(xyzs);
    ball_kernel<<<(3*NTOK)/4, 128>>>(xyzs);
    conv_kernel<<<NTOK, 128>>>(xyzs, oldf, conv_d_w, conv_f_w, out);
    embed_kernel<<<NTOK, 512>>>(pos_w, pos_b, contr_w, contr_b, out);

    const long long AS = (long long)LTOK * 1536;   // per-b row stride inside g_qkv
    const long long SS = SSTR;

    for (int l = 0; l < 4; l++) {
        ln_kernel<<<NTOK, 256>>>(px, ln1_s + l*EDIM, ln1_b + l*EDIM, ph);
        // QKV: [6144,512] @ [1536,512]^T -> g_qkv [6144,1536]
        tgemm_w<<<dim3(12,48,1), 256>>>(
            ph, qkv_w + (size_t)l*3*EDIM*EDIM, nullptr, pqkv,
            512, 512, 512, 1536, 1.0f, 0,0,0,0,0,0, 0,0,0);
        // scores = (Q @ K^T) * scale   batched over z = b*8 + h
        tgemm_w<<<dim3(12,12,32), 256>>>(
            pqkv, pqkv + 512, nullptr, psc,
            64, 1536, 1536, 1536, 0.125f,
            AS, 64, AS, 64, 8*SS, SS, 0,0,0);
        softmax_kernel<<<NB*NHEAD*LTOK, 128>>>();
        // O = P @ V
        tgemm_pv<<<dim3(1,12,32), 256>>>(
            psc, pqkv + 1024, po,
            1536, 1536, 1536, 512,
            8*SS, SS, AS, 64, (long long)LTOK*512, 64);
        // out proj + residual
        tgemm_w<<<dim3(4,48,1), 256>>>(
            po, out_w + (size_t)l*EDIM*EDIM, out_b + l*EDIM, px,
            512, 512, 512, 512, 1.0f, 0,0,0,0,0,0, 0,1,1);
        ln_kernel<<<NTOK, 256>>>(px, ln2_s + l*EDIM, ln2_b + l*EDIM, ph);
        // ff1 + gelu
        tgemm_w<<<dim3(8,48,1), 256>>>(
            ph, ff1_w + (size_t)l*MLPD*EDIM, ff1_b + l*MLPD, pf1,
            512, 512, 512, 1024, 1.0f, 0,0,0,0,0,0, 1,0,1);
        // ff2 + residual
        tgemm_w<<<dim3(4,48,1), 256>>>(
            pf1, ff2_w + (size_t)l*EDIM*MLPD, ff2_b + l*EDIM, px,
            1024, 1024, 1024, 512, 1.0f, 0,0,0,0,0,0, 0,1,1);
    }

    pool_kernel<<<NB, 512>>>();
    ln_kernel<<<NB, 256>>>(ppool, head_ln_s, head_ln_b, phln);
    head1_kernel<<<(NB*MLPD)/8, 256>>>(head1_w, head1_b);
    head2_kernel<<<NB*NCLS/4, 128>>>(head2_w, head2_b, out);
}

// round 5
// speedup vs baseline: 3.5845x; 1.3523x over previous
#include <cuda_runtime.h>
#include <cuda_bf16.h>
#include <cstdint>
#include <math.h>

#define NB 4
#define NT 24
#define NP 4096
#define MM 128
#define TO 12
#define LTOK 1536
#define NTOK 6144
#define EDIM 512
#define NHEAD 8
#define DHEAD 64
#define MLPD 1024
#define NCLS 30
#define KSAMP 32
#define RAD2 0.09f

#define CONTR_OFF 120
#define FEAT_OFF (120 + NTOK*EDIM)

// ---------------- scratch (device globals; no cudaMalloc allowed) ----------
__device__ __align__(256) float g_anchor[NTOK*3];
__device__ __align__(256) int   g_ball[3*NTOK*KSAMP];
__device__ __align__(256) float g_x[NTOK*EDIM];
__device__ __align__(256) float g_h[NTOK*EDIM];
__device__ __align__(256) float g_qkv[NTOK*3*EDIM];
__device__ __align__(256) float g_o[NTOK*EDIM];
__device__ __align__(256) float g_f1[NTOK*MLPD];
__device__ __align__(256) float g_pool[NB*EDIM];
__device__ __align__(256) float g_hln[NB*EDIM];
__device__ __align__(256) float g_h1[NB*MLPD];

__device__ __forceinline__ float gelu_exact(float x){
    return 0.5f*x*(1.0f+erff(x*0.70710678118654752440f));
}

// ==================== HMMA (mma.sync) helpers ==============================
__device__ __forceinline__ void mma16816(float* c, const unsigned* a, const unsigned* b){
    asm volatile("mma.sync.aligned.m16n8k16.row.col.f32.bf16.bf16.f32 "
        "{%0,%1,%2,%3}, {%4,%5,%6,%7}, {%8,%9}, {%0,%1,%2,%3};"
        : "+f"(c[0]),"+f"(c[1]),"+f"(c[2]),"+f"(c[3])
        : "r"(a[0]),"r"(a[1]),"r"(a[2]),"r"(a[3]), "r"(b[0]),"r"(b[1]));
}
// pack fp32 pair -> bf16x2 hi and residual lo
__device__ __forceinline__ void split2(float x, float y, unsigned& hi, unsigned& lo){
    __nv_bfloat16 hx = __float2bfloat16(x), hy = __float2bfloat16(y);
    float rx = x - __bfloat162float(hx), ry = y - __bfloat162float(hy);
    __nv_bfloat16 lx = __float2bfloat16(rx), ly = __float2bfloat16(ry);
    hi = (unsigned)__bfloat16_as_ushort(hx) | ((unsigned)__bfloat16_as_ushort(hy) << 16);
    lo = (unsigned)__bfloat16_as_ushort(lx) | ((unsigned)__bfloat16_as_ushort(ly) << 16);
}

#define LDT 40   // smem row stride in bf16 (32 + 8 pad) for projection GEMM

// ============ GEMM (W row-major [N,K]): C = alpha*(A@W^T) (+bias)(gelu)(+C)
// BM=128, BN=128, BK=32, 256 threads, warps 2(M)x4(N), warp tile 64x32.
__global__ __launch_bounds__(256) void tgemm_w(
    const float* __restrict__ A, const float* __restrict__ W,
    const float* __restrict__ bias, float* __restrict__ C,
    int K, int lda, int ldw, int ldc, float alpha,
    int act, int resid, int hasb)
{
    __shared__ __nv_bfloat16 AH[128][LDT];
    __shared__ __nv_bfloat16 AL[128][LDT];
    __shared__ __nv_bfloat16 WH[128][LDT];
    __shared__ __nv_bfloat16 WL[128][LDT];

    int tid = threadIdx.x, wid = tid >> 5, lane = tid & 31;
    int g = lane >> 2, tg = lane & 3;
    int rw = (wid >> 2) * 64, cw = (wid & 3) * 32;
    int bm = blockIdx.y * 128, bn = blockIdx.x * 128;

    float acc[4][4][4];
    #pragma unroll
    for (int i = 0; i < 4; i++)
        #pragma unroll
        for (int j = 0; j < 4; j++)
            #pragma unroll
            for (int q = 0; q < 4; q++) acc[i][j][q] = 0.f;

    int lr = tid >> 1;
    int lh = (tid & 1) * 16;
    int nch = K >> 5;
    for (int c = 0; c < nch; c++) {
        if (c) __syncthreads();
        const float* ap = A + (size_t)(bm + lr) * lda + c * 32 + lh;
        const float* wp = W + (size_t)(bn + lr) * ldw + c * 32 + lh;
        #pragma unroll
        for (int j = 0; j < 4; j++) {
            float4 a = *(const float4*)(ap + j*4);
            unsigned h0, l0, h1, l1;
            split2(a.x, a.y, h0, l0); split2(a.z, a.w, h1, l1);
            int cc = lh + j*4;
            *(unsigned*)&AH[lr][cc]   = h0; *(unsigned*)&AH[lr][cc+2] = h1;
            *(unsigned*)&AL[lr][cc]   = l0; *(unsigned*)&AL[lr][cc+2] = l1;
            float4 w = *(const float4*)(wp + j*4);
            split2(w.x, w.y, h0, l0); split2(w.z, w.w, h1, l1);
            *(unsigned*)&WH[lr][cc]   = h0; *(unsigned*)&WH[lr][cc+2] = h1;
            *(unsigned*)&WL[lr][cc]   = l0; *(unsigned*)&WL[lr][cc+2] = l1;
        }
        __syncthreads();
        #pragma unroll
        for (int ks = 0; ks < 2; ks++) {
            int k0 = ks * 16 + tg * 2;
            unsigned ah[4][4], al[4][4], bh[4][2], bl[4][2];
            #pragma unroll
            for (int mt = 0; mt < 4; mt++) {
                int r0 = rw + mt*16 + g;
                ah[mt][0] = *(const unsigned*)&AH[r0][k0];
                ah[mt][1] = *(const unsigned*)&AH[r0+8][k0];
                ah[mt][2] = *(const unsigned*)&AH[r0][k0+8];
                ah[mt][3] = *(const unsigned*)&AH[r0+8][k0+8];
                al[mt][0] = *(const unsigned*)&AL[r0][k0];
                al[mt][1] = *(const unsigned*)&AL[r0+8][k0];
                al[mt][2] = *(const unsigned*)&AL[r0][k0+8];
                al[mt][3] = *(const unsigned*)&AL[r0+8][k0+8];
            }
            #pragma unroll
            for (int nt = 0; nt < 4; nt++) {
                int c0 = cw + nt*8 + g;
                bh[nt][0] = *(const unsigned*)&WH[c0][k0];
                bh[nt][1] = *(const unsigned*)&WH[c0][k0+8];
                bl[nt][0] = *(const unsigned*)&WL[c0][k0];
                bl[nt][1] = *(const unsigned*)&WL[c0][k0+8];
            }
            #pragma unroll
            for (int mt = 0; mt < 4; mt++)
                #pragma unroll
                for (int nt = 0; nt < 4; nt++) {
                    mma16816(acc[mt][nt], ah[mt], bh[nt]);
                    mma16816(acc[mt][nt], ah[mt], bl[nt]);
                    mma16816(acc[mt][nt], al[mt], bh[nt]);
                }
        }
    }
    // epilogue
    #pragma unroll
    for (int mt = 0; mt < 4; mt++) {
        #pragma unroll
        for (int nt = 0; nt < 4; nt++) {
            int row = bm + rw + mt*16 + g;
            int col = bn + cw + nt*8 + tg*2;
            #pragma unroll
            for (int half = 0; half < 2; half++) {
                int r = row + half*8;
                float v0 = acc[mt][nt][half*2+0] * alpha;
                float v1 = acc[mt][nt][half*2+1] * alpha;
                if (hasb) { v0 += bias[col]; v1 += bias[col+1]; }
                if (act)  { v0 = gelu_exact(v0); v1 = gelu_exact(v1); }
                float* cp = C + (size_t)r * ldc + col;
                if (resid) {
                    float2 old = *(float2*)cp;
                    v0 += old.x; v1 += old.y;
                }
                float2 ov = {v0, v1};
                *(float2*)cp = ov;
            }
        }
    }
}

// ==================== flash attention ======================================
// Block: 128 queries x one (b,h). 8 warps x 16 query rows (FA2 layout).
// kv tiles of 128. 3-term bf16 split on QK and PV. Online softmax.
#define FQS 72    // Q/K smem row stride (bf16)
#define FVS 136   // V^T smem row stride (bf16)
#define FA_QH 0
#define FA_QL (FA_QH + 128*FQS*2)
#define FA_KH (FA_QL + 128*FQS*2)
#define FA_KL (FA_KH + 128*FQS*2)
#define FA_VH (FA_KL + 128*FQS*2)
#define FA_VL (FA_VH + 64*FVS*2)
#define FA_SMEM (FA_VL + 64*FVS*2)   // 108,544 bytes

__global__ __launch_bounds__(256) void flash_kernel(
    const float* __restrict__ qkv, float* __restrict__ o)
{
    extern __shared__ char fsm[];
    __nv_bfloat16* QH = (__nv_bfloat16*)(fsm + FA_QH);
    __nv_bfloat16* QL = (__nv_bfloat16*)(fsm + FA_QL);
    __nv_bfloat16* KH = (__nv_bfloat16*)(fsm + FA_KH);
    __nv_bfloat16* KL = (__nv_bfloat16*)(fsm + FA_KL);
    __nv_bfloat16* VH = (__nv_bfloat16*)(fsm + FA_VH);
    __nv_bfloat16* VL = (__nv_bfloat16*)(fsm + FA_VL);

    int tid = threadIdx.x, wid = tid >> 5, lane = tid & 31;
    int g = lane >> 2, tg = lane & 3;
    int z = blockIdx.y;
    int b = z >> 3, h = z & 7;
    const float* base = qkv + (size_t)b * LTOK * 1536;
    int q0 = blockIdx.x * 128;

    // ---- load Q tile (scaled by 1/8), split hi/lo ----
    {
        int r = tid >> 1, cb = (tid & 1) * 32;
        const float* qp = base + (size_t)(q0 + r) * 1536 + h*64 + cb;
        #pragma unroll
        for (int j = 0; j < 8; j++) {
            float4 a = *(const float4*)(qp + j*4);
            a.x *= 0.125f; a.y *= 0.125f; a.z *= 0.125f; a.w *= 0.125f;
            unsigned h0, l0, h1, l1;
            split2(a.x, a.y, h0, l0); split2(a.z, a.w, h1, l1);
            int cc = cb + j*4;
            *(unsigned*)&QH[r*FQS + cc]   = h0; *(unsigned*)&QH[r*FQS + cc+2] = h1;
            *(unsigned*)&QL[r*FQS + cc]   = l0; *(unsigned*)&QL[r*FQS + cc+2] = l1;
        }
    }

    float acco[8][4];
    #pragma unroll
    for (int i = 0; i < 8; i++)
        #pragma unroll
        for (int q = 0; q < 4; q++) acco[i][q] = 0.f;
    float m0 = -3.402823466e38f, m1 = -3.402823466e38f, l0s = 0.f, l1s = 0.f;

    for (int t = 0; t < LTOK/128; t++) {
        __syncthreads();
        // ---- load K tile, split ----
        {
            int r = tid >> 1, cb = (tid & 1) * 32;
            const float* kp = base + (size_t)(t*128 + r) * 1536 + 512 + h*64 + cb;
            #pragma unroll
            for (int j = 0; j < 8; j++) {
                float4 a = *(const float4*)(kp + j*4);
                unsigned h0, l0, h1, l1;
                split2(a.x, a.y, h0, l0); split2(a.z, a.w, h1, l1);
                int cc = cb + j*4;
                *(unsigned*)&KH[r*FQS + cc]   = h0; *(unsigned*)&KH[r*FQS + cc+2] = h1;
                *(unsigned*)&KL[r*FQS + cc]   = l0; *(unsigned*)&KL[r*FQS + cc+2] = l1;
            }
            // ---- load V tile transposed: VH[d][kv] ----
            const float* vp = base + (size_t)(t*128 + r) * 1536 + 1024 + h*64 + cb;
            #pragma unroll
            for (int j = 0; j < 8; j++) {
                float4 a = *(const float4*)(vp + j*4);
                float vv[4] = {a.x, a.y, a.z, a.w};
                #pragma unroll
                for (int i = 0; i < 4; i++) {
                    int d = cb + j*4 + i;
                    __nv_bfloat16 hi = __float2bfloat16(vv[i]);
                    float rr = vv[i] - __bfloat162float(hi);
                    VH[d*FVS + r] = hi;
                    VL[d*FVS + r] = __float2bfloat16(rr);
                }
            }
        }
        __syncthreads();

        // ---- S = Q @ K^T (128 kv cols per warp-row of 16 queries) ----
        float accs[16][4];
        #pragma unroll
        for (int nt = 0; nt < 16; nt++)
            #pragma unroll
            for (int q = 0; q < 4; q++) accs[nt][q] = 0.f;
        #pragma unroll
        for (int ks = 0; ks < 4; ks++) {
            int col = ks*16 + tg*2;
            int r0 = wid*16 + g;
            unsigned aqh[4], aql[4];
            aqh[0] = *(unsigned*)&QH[r0*FQS + col];
            aqh[1] = *(unsigned*)&QH[(r0+8)*FQS + col];
            aqh[2] = *(unsigned*)&QH[r0*FQS + col + 8];
            aqh[3] = *(unsigned*)&QH[(r0+8)*FQS + col + 8];
            aql[0] = *(unsigned*)&QL[r0*FQS + col];
            aql[1] = *(unsigned*)&QL[(r0+8)*FQS + col];
            aql[2] = *(unsigned*)&QL[r0*FQS + col + 8];
            aql[3] = *(unsigned*)&QL[(r0+8)*FQS + col + 8];
            #pragma unroll
            for (int nt = 0; nt < 16; nt++) {
                int kr = nt*8 + g;
                unsigned bkh[2], bkl[2];
                bkh[0] = *(unsigned*)&KH[kr*FQS + col];
                bkh[1] = *(unsigned*)&KH[kr*FQS + col + 8];
                bkl[0] = *(unsigned*)&KL[kr*FQS + col];
                bkl[1] = *(unsigned*)&KL[kr*FQS + col + 8];
                mma16816(accs[nt], aqh, bkh);
                mma16816(accs[nt], aqh, bkl);
                mma16816(accs[nt], aql, bkh);
            }
        }

        // ---- online softmax (rows g and g+8 of this warp's 16) ----
        float mx0 = -3.402823466e38f, mx1 = -3.402823466e38f;
        #pragma unroll
        for (int nt = 0; nt < 16; nt++) {
            mx0 = fmaxf(mx0, fmaxf(accs[nt][0], accs[nt][1]));
            mx1 = fmaxf(mx1, fmaxf(accs[nt][2], accs[nt][3]));
        }
        mx0 = fmaxf(mx0, __shfl_xor_sync(0xffffffffu, mx0, 1));
        mx0 = fmaxf(mx0, __shfl_xor_sync(0xffffffffu, mx0, 2));
        mx1 = fmaxf(mx1, __shfl_xor_sync(0xffffffffu, mx1, 1));
        mx1 = fmaxf(mx1, __shfl_xor_sync(0xffffffffu, mx1, 2));
        float mn0 = fmaxf(m0, mx0), mn1 = fmaxf(m1, mx1);
        float c0 = expf(m0 - mn0), c1 = expf(m1 - mn1);
        float s0 = 0.f, s1 = 0.f;
        #pragma unroll
        for (int nt = 0; nt < 16; nt++) {
            accs[nt][0] = expf(accs[nt][0] - mn0);
            accs[nt][1] = expf(accs[nt][1] - mn0);
            accs[nt][2] = expf(accs[nt][2] - mn1);
            accs[nt][3] = expf(accs[nt][3] - mn1);
            s0 += accs[nt][0] + accs[nt][1];
            s1 += accs[nt][2] + accs[nt][3];
        }
        s0 += __shfl_xor_sync(0xffffffffu, s0, 1);
        s0 += __shfl_xor_sync(0xffffffffu, s0, 2);
        s1 += __shfl_xor_sync(0xffffffffu, s1, 1);
        s1 += __shfl_xor_sync(0xffffffffu, s1, 2);
        l0s = l0s * c0 + s0;
        l1s = l1s * c1 + s1;
        m0 = mn0; m1 = mn1;
        #pragma unroll
        for (int i = 0; i < 8; i++) {
            acco[i][0] *= c0; acco[i][1] *= c0;
            acco[i][2] *= c1; acco[i][3] *= c1;
        }

        // ---- O += P @ V (P repacked from accumulators, FA2 trick) ----
        #pragma unroll
        for (int pks = 0; pks < 8; pks++) {
            unsigned aph[4], apl[4];
            split2(accs[2*pks][0],   accs[2*pks][1],   aph[0], apl[0]);
            split2(accs[2*pks][2],   accs[2*pks][3],   aph[1], apl[1]);
            split2(accs[2*pks+1][0], accs[2*pks+1][1], aph[2], apl[2]);
            split2(accs[2*pks+1][2], accs[2*pks+1][3], aph[3], apl[3]);
            int kcol = pks*16 + tg*2;
            #pragma unroll
            for (int nt2 = 0; nt2 < 8; nt2++) {
                int d = nt2*8 + g;
                unsigned bvh[2], bvl[2];
                bvh[0] = *(unsigned*)&VH[d*FVS + kcol];
                bvh[1] = *(unsigned*)&VH[d*FVS + kcol + 8];
                bvl[0] = *(unsigned*)&VL[d*FVS + kcol];
                bvl[1] = *(unsigned*)&VL[d*FVS + kcol + 8];
                mma16816(acco[nt2], aph, bvh);
                mma16816(acco[nt2], aph, bvl);
                mma16816(acco[nt2], apl, bvh);
            }
        }
    }

    // ---- epilogue: O /= l ----
    float inv0 = 1.0f / l0s, inv1 = 1.0f / l1s;
    int row = q0 + wid*16 + g;
    #pragma unroll
    for (int nt2 = 0; nt2 < 8; nt2++) {
        int col = h*64 + nt2*8 + tg*2;
        float2 v0 = {acco[nt2][0]*inv0, acco[nt2][1]*inv0};
        float2 v1 = {acco[nt2][2]*inv1, acco[nt2][3]*inv1};
        *(float2*)(o + (size_t)(b*LTOK + row)     * EDIM + col) = v0;
        *(float2*)(o + (size_t)(b*LTOK + row + 8) * EDIM + col) = v1;
    }
}

// ---------------- FPS: one block per (b, to) -------------------------------
__global__ __launch_bounds__(512) void fps_kernel(const float* __restrict__ xyzs) {
    int blk = blockIdx.x;
    int b = blk / TO, j = blk % TO;
    const float* P = xyzs + (size_t)(b*NT + 2*j)*NP*3;
    int tid = threadIdx.x;
    float px[8], py[8], pz[8], dist[8];
    #pragma unroll
    for (int i = 0; i < 8; i++) {
        int p = tid + i*512;
        px[i] = P[p*3+0]; py[i] = P[p*3+1]; pz[i] = P[p*3+2];
        dist[i] = 1e10f;
    }
    __shared__ float sbx, sby, sbz;
    __shared__ float swv[16];
    __shared__ int   swi[16];
    float* anch = g_anchor + (size_t)blk*MM*3;
    if (tid == 0) {
        sbx = P[0]; sby = P[1]; sbz = P[2];
        anch[0] = P[0]; anch[1] = P[1]; anch[2] = P[2];
    }
    __syncthreads();
    for (int s = 1; s < MM; s++) {
        float bx = sbx, by = sby, bz = sbz;
        float bestv = -1.0f; int besti = 0x7fffffff;
        #pragma unroll
        for (int i = 0; i < 8; i++) {
            float dx = __fsub_rn(px[i], bx);
            float dy = __fsub_rn(py[i], by);
            float dz = __fsub_rn(pz[i], bz);
            float d = __fadd_rn(__fadd_rn(__fmul_rn(dx,dx), __fmul_rn(dy,dy)), __fmul_rn(dz,dz));
            float nd = fminf(dist[i], d);
            dist[i] = nd;
            int p = tid + i*512;
            if (nd > bestv || (nd == bestv && p < besti)) { bestv = nd; besti = p; }
        }
        #pragma unroll
        for (int off = 16; off; off >>= 1) {
            float ov = __shfl_down_sync(0xffffffffu, bestv, off);
            int   oi = __shfl_down_sync(0xffffffffu, besti, off);
            if (ov > bestv || (ov == bestv && oi < besti)) { bestv = ov; besti = oi; }
        }
        if ((tid & 31) == 0) { swv[tid>>5] = bestv; swi[tid>>5] = besti; }
        __syncthreads();
        if (tid == 0) {
            float v = swv[0]; int ii = swi[0];
            #pragma unroll
            for (int w = 1; w < 16; w++)
                if (swv[w] > v || (swv[w] == v && swi[w] < ii)) { v = swv[w]; ii = swi[w]; }
            float x0 = P[ii*3+0], y0 = P[ii*3+1], z0 = P[ii*3+2];
            sbx = x0; sby = y0; sbz = z0;
            anch[s*3+0] = x0; anch[s*3+1] = y0; anch[s*3+2] = z0;
        }
        __syncthreads();
    }
}

// ---------------- Ball query: one warp per (o, token) ----------------------
__global__ __launch_bounds__(128) void ball_kernel(const float* __restrict__ xyzs) {
    int w = blockIdx.x*4 + (threadIdx.x >> 5);
    int lane = threadIdx.x & 31;
    int o = w / NTOK;
    int tok = w % NTOK;
    int b = tok / LTOK, loc = tok % LTOK, j = loc / MM;
    int pf = 2*j + o;
    int of = (pf == 0) ? 0 : (pf - 1);
    const float* P = xyzs + (size_t)(b*NT + of)*NP*3;
    float ax = g_anchor[tok*3+0], ay = g_anchor[tok*3+1], az = g_anchor[tok*3+2];
    int* out = g_ball + ((size_t)o*NTOK + tok)*KSAMP;
    int cnt = 0, first = 0; bool found = false;
    for (int base = 0; base < NP; base += 32) {
        int p = base + lane;
        float x = P[p*3+0], y = P[p*3+1], z = P[p*3+2];
        float dx = __fsub_rn(ax,x), dy = __fsub_rn(ay,y), dz = __fsub_rn(az,z);
        float d2 = __fadd_rn(__fadd_rn(__fmul_rn(dx,dx), __fmul_rn(dy,dy)), __fmul_rn(dz,dz));
        bool inside = d2 < RAD2;
        unsigned msk = __ballot_sync(0xffffffffu, inside);
        if (!found && msk) { first = base + __ffs(msk) - 1; found = true; }
        int pos = cnt + __popc(msk & ((1u << lane) - 1u));
        if (inside && pos < KSAMP) out[pos] = p;
        cnt += __popc(msk);
        if (cnt >= KSAMP) break;
    }
    if (lane >= cnt) out[lane] = found ? first : 0;
}

// ---------------- grouped conv + max pool ----------------------------------
__global__ __launch_bounds__(128) void conv_kernel(
    const float* __restrict__ xyzs, const float* __restrict__ oldf,
    const float* __restrict__ Wd, const float* __restrict__ Wf,
    float* __restrict__ dout)
{
    int tok = blockIdx.x;
    int b = tok / LTOK, loc = tok % LTOK, j = loc / MM;
    int tid = threadIdx.x;
    __shared__ float sd[KSAMP][4];
    __shared__ float sf[KSAMP][2];
    float ax = g_anchor[tok*3+0], ay = g_anchor[tok*3+1], az = g_anchor[tok*3+2];
    float wd[4][4], wf[4][2], vmax[4];
    #pragma unroll
    for (int r = 0; r < 4; r++) {
        int d = tid + 128*r;
        wd[r][0] = Wd[d*4+0]; wd[r][1] = Wd[d*4+1]; wd[r][2] = Wd[d*4+2]; wd[r][3] = Wd[d*4+3];
        wf[r][0] = Wf[d*2+0]; wf[r][1] = Wf[d*2+1];
        vmax[r] = -3.402823466e38f;
    }
    for (int o = 0; o < 3; o++) {
        int pf = 2*j + o;
        int of = (pf == 0) ? 0 : (pf - 1);
        const float* P = xyzs + (size_t)(b*NT + of)*NP*3;
        const float* F = oldf + (size_t)(b*NT + of)*2*NP;
        __syncthreads();
        if (tid < KSAMP) {
            int idx = g_ball[((size_t)o*NTOK + tok)*KSAMP + tid];
            sd[tid][0] = P[idx*3+0] - ax;
            sd[tid][1] = P[idx*3+1] - ay;
            sd[tid][2] = P[idx*3+2] - az;
            sd[tid][3] = (float)(o - 1);
            sf[tid][0] = F[idx];
            sf[tid][1] = F[NP + idx];
        }
        __syncthreads();
        #pragma unroll 4
        for (int k = 0; k < KSAMP; k++) {
            float d0 = sd[k][0], d1 = sd[k][1], d2 = sd[k][2], d3 = sd[k][3];
            float f0 = sf[k][0], f1 = sf[k][1];
            #pragma unroll
            for (int r = 0; r < 4; r++) {
                float de = wd[r][0]*d0 + wd[r][1]*d1 + wd[r][2]*d2 + wd[r][3]*d3;
                float fe = wf[r][0]*f0 + wf[r][1]*f1;
                vmax[r] = fmaxf(vmax[r], de*fe);
            }
        }
    }
    #pragma unroll
    for (int r = 0; r < 4; r++)
        dout[FEAT_OFF + (size_t)tok*EDIM + tid + 128*r] = vmax[r];
}

// ---------------- pos + contrastive + relu(pos+feat) -----------------------
__global__ __launch_bounds__(512) void embed_kernel(
    const float* __restrict__ pw, const float* __restrict__ pb,
    const float* __restrict__ cw, const float* __restrict__ cb,
    float* __restrict__ dout)
{
    int tok = blockIdx.x;
    int d = threadIdx.x;
    int loc = tok % LTOK, j = loc / MM;
    float ax = g_anchor[tok*3+0], ay = g_anchor[tok*3+1], az = g_anchor[tok*3+2];
    float tv = (float)(j + 1);
    float pos = pw[d*4+0]*ax + pw[d*4+1]*ay + pw[d*4+2]*az + pw[d*4+3]*tv + pb[d];
    float con = cw[d*4+0]*ax + cw[d*4+1]*ay + cw[d*4+2]*az + cw[d*4+3]*tv + cb[d];
    dout[CONTR_OFF + (size_t)tok*EDIM + d] = con;
    float feat = dout[FEAT_OFF + (size_t)tok*EDIM + d];
    g_x[(size_t)tok*EDIM + d] = fmaxf(pos + feat, 0.0f);
}

// ---------------- LayerNorm (rows of 512) ----------------------------------
__global__ __launch_bounds__(256) void ln_kernel(
    const float* __restrict__ x, const float* __restrict__ s,
    const float* __restrict__ bb, float* __restrict__ out)
{
    int tok = blockIdx.x;
    int tid = threadIdx.x;
    const float* row = x + (size_t)tok*EDIM;
    float v0 = row[tid], v1 = row[tid + 256];
    float sum = v0 + v1, sq = v0*v0 + v1*v1;
    #pragma unroll
    for (int off = 16; off; off >>= 1) {
        sum += __shfl_xor_sync(0xffffffffu, sum, off);
        sq  += __shfl_xor_sync(0xffffffffu, sq, off);
    }
    __shared__ float ssum[8], ssq[8];
    if ((tid & 31) == 0) { ssum[tid>>5] = sum; ssq[tid>>5] = sq; }
    __syncthreads();
    float ts = 0.f, tq = 0.f;
    #pragma unroll
    for (int w = 0; w < 8; w++) { ts += ssum[w]; tq += ssq[w]; }
    float mu = ts * (1.0f/512.0f);
    float var = tq * (1.0f/512.0f) - mu*mu;
    float rstd = rsqrtf(var + 1e-5f);
    out[(size_t)tok*EDIM + tid]       = (v0 - mu)*rstd*s[tid] + bb[tid];
    out[(size_t)tok*EDIM + tid + 256] = (v1 - mu)*rstd*s[tid+256] + bb[tid+256];
}

// ---------------- head ------------------------------------------------------
__global__ __launch_bounds__(512) void pool_kernel() {
    int b = blockIdx.x;
    int d = threadIdx.x;
    float v = -3.402823466e38f;
    const float* p = g_x + (size_t)b*LTOK*EDIM + d;
    for (int i = 0; i < LTOK; i++) v = fmaxf(v, p[(size_t)i*EDIM]);
    g_pool[b*EDIM + d] = v;
}
__global__ __launch_bounds__(256) void head1_kernel(
    const float* __restrict__ W, const float* __restrict__ bias)
{
    int out = blockIdx.x*8 + (threadIdx.x >> 5);
    int lane = threadIdx.x & 31;
    int b = out >> 10, jj = out & 1023;
    const float* xr = g_hln + b*EDIM;
    const float* wr = W + (size_t)jj*EDIM;
    float s = 0.f;
    for (int d = lane; d < EDIM; d += 32) s += xr[d]*wr[d];
    #pragma unroll
    for (int off = 16; off; off >>= 1) s += __shfl_xor_sync(0xffffffffu, s, off);
    if (lane == 0) g_h1[out] = gelu_exact(s + bias[jj]);
}
__global__ __launch_bounds__(128) void head2_kernel(
    const float* __restrict__ W, const float* __restrict__ bias,
    float* __restrict__ dout)
{
    int out = blockIdx.x*4 + (threadIdx.x >> 5);
    int lane = threadIdx.x & 31;
    int b = out / NCLS, c = out % NCLS;
    float s = 0.f;
    for (int d = lane; d < MLPD; d += 32) s += g_h1[b*MLPD + d]*W[(size_t)c*MLPD + d];
    #pragma unroll
    for (int off = 16; off; off >>= 1) s += __shfl_xor_sync(0xffffffffu, s, off);
    if (lane == 0) dout[out] = s + bias[c];
}

// ---------------- launch ---------------------------------------------------
extern "C" void kernel_launch(void* const* d_in, const int* in_sizes, int n_in,
                              void* d_out, int out_size) {
    const float* xyzs      = (const float*)d_in[0];
    const float* oldf      = (const float*)d_in[1];
    const float* conv_d_w  = (const float*)d_in[2];
    const float* conv_f_w  = (const float*)d_in[3];
    const float* pos_w     = (const float*)d_in[4];
    const float* pos_b     = (const float*)d_in[5];
    const float* contr_w   = (const float*)d_in[6];
    const float* contr_b   = (const float*)d_in[7];
    const float* ln1_s     = (const float*)d_in[8];
    const float* ln1_b     = (const float*)d_in[9];
    const float* qkv_w     = (const float*)d_in[10];
    const float* out_w     = (const float*)d_in[11];
    const float* out_b     = (const float*)d_in[12];
    const float* ln2_s     = (const float*)d_in[13];
    const float* ln2_b     = (const float*)d_in[14];
    const float* ff1_w     = (const float*)d_in[15];
    const float* ff1_b     = (const float*)d_in[16];
    const float* ff2_w     = (const float*)d_in[17];
    const float* ff2_b     = (const float*)d_in[18];
    const float* head_ln_s = (const float*)d_in[19];
    const float* head_ln_b = (const float*)d_in[20];
    const float* head1_w   = (const float*)d_in[21];
    const float* head1_b   = (const float*)d_in[22];
    const float* head2_w   = (const float*)d_in[23];
    const float* head2_b   = (const float*)d_in[24];
    float* out = (float*)d_out;

    float *px, *ph, *pqkv, *po, *pf1, *ppool, *phln;
    cudaGetSymbolAddress((void**)&px,    g_x);
    cudaGetSymbolAddress((void**)&ph,    g_h);
    cudaGetSymbolAddress((void**)&pqkv,  g_qkv);
    cudaGetSymbolAddress((void**)&po,    g_o);
    cudaGetSymbolAddress((void**)&pf1,   g_f1);
    cudaGetSymbolAddress((void**)&ppool, g_pool);
    cudaGetSymbolAddress((void**)&phln,  g_hln);

    cudaFuncSetAttribute(flash_kernel, cudaFuncAttributeMaxDynamicSharedMemorySize, FA_SMEM);

    fps_kernel<<<48, 512>>>(xyzs);
    ball_kernel<<<(3*NTOK)/4, 128>>>(xyzs);
    conv_kernel<<<NTOK, 128>>>(xyzs, oldf, conv_d_w, conv_f_w, out);
    embed_kernel<<<NTOK, 512>>>(pos_w, pos_b, contr_w, contr_b, out);

    for (int l = 0; l < 4; l++) {
        ln_kernel<<<NTOK, 256>>>(px, ln1_s + l*EDIM, ln1_b + l*EDIM, ph);
        // QKV: [6144,512] @ [1536,512]^T -> g_qkv [6144,1536]
        tgemm_w<<<dim3(12,48,1), 256>>>(
            ph, qkv_w + (size_t)l*3*EDIM*EDIM, nullptr, pqkv,
            512, 512, 512, 1536, 1.0f, 0,0,0);
        // fused attention -> g_o
        flash_kernel<<<dim3(LTOK/128, NB*NHEAD), 256, FA_SMEM>>>(pqkv, po);
        // out proj + residual
        tgemm_w<<<dim3(4,48,1), 256>>>(
            po, out_w + (size_t)l*EDIM*EDIM, out_b + l*EDIM, px,
            512, 512, 512, 512, 1.0f, 0,1,1);
        ln_kernel<<<NTOK, 256>>>(px, ln2_s + l*EDIM, ln2_b + l*EDIM, ph);
        // ff1 + gelu
        tgemm_w<<<dim3(8,48,1), 256>>>(
            ph, ff1_w + (size_t)l*MLPD*EDIM, ff1_b + l*MLPD, pf1,
            512, 512, 512, 1024, 1.0f, 1,0,1);
        // ff2 + residual
        tgemm_w<<<dim3(4,48,1), 256>>>(
            pf1, ff2_w + (size_t)l*EDIM*MLPD, ff2_b + l*EDIM, px,
            1024, 1024, 1024, 512, 1.0f, 0,1,1);
    }

    pool_kernel<<<NB, 512>>>();
    ln_kernel<<<NB, 256>>>(ppool, head_ln_s, head_ln_b, phln);
    head1_kernel<<<(NB*MLPD)/8, 256>>>(head1_w, head1_b);
    head2_kernel<<<NB*NCLS/4, 128>>>(head2_w, head2_b, out);
}

// round 6
// speedup vs baseline: 3.7363x; 1.0424x over previous
#include <cuda_runtime.h>
#include <cuda_bf16.h>
#include <cstdint>
#include <math.h>

#define NB 4
#define NT 24
#define NP 4096
#define MM 128
#define TO 12
#define LTOK 1536
#define NTOK 6144
#define EDIM 512
#define NHEAD 8
#define DHEAD 64
#define MLPD 1024
#define NCLS 30
#define KSAMP 32
#define RAD2 0.09f

#define CONTR_OFF 120
#define FEAT_OFF (120 + NTOK*EDIM)

// weight-split buffer offsets (elements)
#define WQKV_OFF 0
#define WOUT_OFF 3145728
#define WFF1_OFF 4194304
#define WFF2_OFF 6291456
#define WTOT     8388608

// ---------------- scratch (device globals; no cudaMalloc allowed) ----------
__device__ __align__(256) float g_anchor[NTOK*3];
__device__ __align__(256) int   g_ball[3*NTOK*KSAMP];
__device__ __align__(256) float g_x[NTOK*EDIM];
__device__ __align__(256) float g_pool[NB*EDIM];
__device__ __align__(256) float g_hln[NB*EDIM];
__device__ __align__(256) float g_h1[NB*MLPD];

__device__ __align__(256) __nv_bfloat16 g_wh[WTOT];
__device__ __align__(256) __nv_bfloat16 g_wl[WTOT];
__device__ __align__(256) __nv_bfloat16 g_hh[NTOK*EDIM];
__device__ __align__(256) __nv_bfloat16 g_hl[NTOK*EDIM];
__device__ __align__(256) __nv_bfloat16 g_qh[NTOK*1536];
__device__ __align__(256) __nv_bfloat16 g_ql[NTOK*1536];
__device__ __align__(256) __nv_bfloat16 g_oh[NTOK*EDIM];
__device__ __align__(256) __nv_bfloat16 g_ol[NTOK*EDIM];
__device__ __align__(256) __nv_bfloat16 g_f1h[NTOK*MLPD];
__device__ __align__(256) __nv_bfloat16 g_f1l[NTOK*MLPD];

__device__ __forceinline__ float gelu_exact(float x){
    return 0.5f*x*(1.0f+erff(x*0.70710678118654752440f));
}

// ==================== HMMA (mma.sync) helpers ==============================
__device__ __forceinline__ void mma16816(float* c, const unsigned* a, const unsigned* b){
    asm volatile("mma.sync.aligned.m16n8k16.row.col.f32.bf16.bf16.f32 "
        "{%0,%1,%2,%3}, {%4,%5,%6,%7}, {%8,%9}, {%0,%1,%2,%3};"
        : "+f"(c[0]),"+f"(c[1]),"+f"(c[2]),"+f"(c[3])
        : "r"(a[0]),"r"(a[1]),"r"(a[2]),"r"(a[3]), "r"(b[0]),"r"(b[1]));
}
__device__ __forceinline__ void split2(float x, float y, unsigned& hi, unsigned& lo){
    __nv_bfloat16 hx = __float2bfloat16(x), hy = __float2bfloat16(y);
    float rx = x - __bfloat162float(hx), ry = y - __bfloat162float(hy);
    __nv_bfloat16 lx = __float2bfloat16(rx), ly = __float2bfloat16(ry);
    hi = (unsigned)__bfloat16_as_ushort(hx) | ((unsigned)__bfloat16_as_ushort(hy) << 16);
    lo = (unsigned)__bfloat16_as_ushort(lx) | ((unsigned)__bfloat16_as_ushort(ly) << 16);
}

// ---------------- weight split prep ----------------------------------------
__global__ __launch_bounds__(256) void wsplit_kernel(
    const float* __restrict__ src, __nv_bfloat16* __restrict__ hi,
    __nv_bfloat16* __restrict__ lo, int n)
{
    int i = (blockIdx.x*256 + threadIdx.x)*4;
    if (i < n) {
        float4 v = *(const float4*)(src + i);
        unsigned h0, l0, h1, l1;
        split2(v.x, v.y, h0, l0); split2(v.z, v.w, h1, l1);
        *(unsigned*)(hi+i) = h0; *(unsigned*)(hi+i+2) = h1;
        *(unsigned*)(lo+i) = l0; *(unsigned*)(lo+i+2) = l1;
    }
}

#define LDT 40   // smem row stride in bf16 (32 + 8 pad)

// ============ GEMM, all-bf16 operands: C = A@W^T with flexible epilogue ====
// A hi/lo [M,K] bf16, W hi/lo [N,K] bf16 (row-major). BM=BN=128, BK=32.
// split==0: fp32 out (+bias)(gelu)(+resid). split==1: bf16 hi/lo out
// (+bias)(gelu); qscale scales cols<512 by 0.125 before split.
__global__ __launch_bounds__(256) void tgemm_b(
    const __nv_bfloat16* __restrict__ AH_, const __nv_bfloat16* __restrict__ AL_,
    const __nv_bfloat16* __restrict__ WH_, const __nv_bfloat16* __restrict__ WL_,
    const float* __restrict__ bias, float* __restrict__ Cf,
    __nv_bfloat16* __restrict__ CH_, __nv_bfloat16* __restrict__ CL_,
    int K, int lda, int ldw, int ldc,
    int act, int resid, int hasb, int split, int qscale)
{
    __shared__ __nv_bfloat16 AH[128][LDT];
    __shared__ __nv_bfloat16 AL[128][LDT];
    __shared__ __nv_bfloat16 WH[128][LDT];
    __shared__ __nv_bfloat16 WL[128][LDT];

    int tid = threadIdx.x, wid = tid >> 5, lane = tid & 31;
    int g = lane >> 2, tg = lane & 3;
    int rw = (wid >> 2) * 64, cw = (wid & 3) * 32;
    int bm = blockIdx.y * 128, bn = blockIdx.x * 128;

    float acc[4][4][4];
    #pragma unroll
    for (int i = 0; i < 4; i++)
        #pragma unroll
        for (int j = 0; j < 4; j++)
            #pragma unroll
            for (int q = 0; q < 4; q++) acc[i][j][q] = 0.f;

    int lr = tid >> 1;
    int lh = (tid & 1) * 16;
    int nch = K >> 5;
    for (int c = 0; c < nch; c++) {
        if (c) __syncthreads();
        size_t ao = (size_t)(bm + lr) * lda + c * 32 + lh;
        size_t wo = (size_t)(bn + lr) * ldw + c * 32 + lh;
        uint4 a0 = *(const uint4*)(AH_ + ao);
        uint4 a1 = *(const uint4*)(AH_ + ao + 8);
        uint4 a2 = *(const uint4*)(AL_ + ao);
        uint4 a3 = *(const uint4*)(AL_ + ao + 8);
        uint4 w0 = *(const uint4*)(WH_ + wo);
        uint4 w1 = *(const uint4*)(WH_ + wo + 8);
        uint4 w2 = *(const uint4*)(WL_ + wo);
        uint4 w3 = *(const uint4*)(WL_ + wo + 8);
        *(uint4*)&AH[lr][lh]   = a0; *(uint4*)&AH[lr][lh+8] = a1;
        *(uint4*)&AL[lr][lh]   = a2; *(uint4*)&AL[lr][lh+8] = a3;
        *(uint4*)&WH[lr][lh]   = w0; *(uint4*)&WH[lr][lh+8] = w1;
        *(uint4*)&WL[lr][lh]   = w2; *(uint4*)&WL[lr][lh+8] = w3;
        __syncthreads();
        #pragma unroll
        for (int ks = 0; ks < 2; ks++) {
            int k0 = ks * 16 + tg * 2;
            unsigned ah[4][4], al[4][4], bh[4][2], bl[4][2];
            #pragma unroll
            for (int mt = 0; mt < 4; mt++) {
                int r0 = rw + mt*16 + g;
                ah[mt][0] = *(const unsigned*)&AH[r0][k0];
                ah[mt][1] = *(const unsigned*)&AH[r0+8][k0];
                ah[mt][2] = *(const unsigned*)&AH[r0][k0+8];
                ah[mt][3] = *(const unsigned*)&AH[r0+8][k0+8];
                al[mt][0] = *(const unsigned*)&AL[r0][k0];
                al[mt][1] = *(const unsigned*)&AL[r0+8][k0];
                al[mt][2] = *(const unsigned*)&AL[r0][k0+8];
                al[mt][3] = *(const unsigned*)&AL[r0+8][k0+8];
            }
            #pragma unroll
            for (int nt = 0; nt < 4; nt++) {
                int c0 = cw + nt*8 + g;
                bh[nt][0] = *(const unsigned*)&WH[c0][k0];
                bh[nt][1] = *(const unsigned*)&WH[c0][k0+8];
                bl[nt][0] = *(const unsigned*)&WL[c0][k0];
                bl[nt][1] = *(const unsigned*)&WL[c0][k0+8];
            }
            #pragma unroll
            for (int mt = 0; mt < 4; mt++)
                #pragma unroll
                for (int nt = 0; nt < 4; nt++) {
                    mma16816(acc[mt][nt], ah[mt], bh[nt]);
                    mma16816(acc[mt][nt], ah[mt], bl[nt]);
                    mma16816(acc[mt][nt], al[mt], bh[nt]);
                }
        }
    }
    // epilogue
    #pragma unroll
    for (int mt = 0; mt < 4; mt++) {
        #pragma unroll
        for (int nt = 0; nt < 4; nt++) {
            int row = bm + rw + mt*16 + g;
            int col = bn + cw + nt*8 + tg*2;
            #pragma unroll
            for (int half = 0; half < 2; half++) {
                int r = row + half*8;
                float v0 = acc[mt][nt][half*2+0];
                float v1 = acc[mt][nt][half*2+1];
                if (hasb) { v0 += bias[col]; v1 += bias[col+1]; }
                if (act)  { v0 = gelu_exact(v0); v1 = gelu_exact(v1); }
                if (split) {
                    if (qscale && col < 512) { v0 *= 0.125f; v1 *= 0.125f; }
                    unsigned hh, ll;
                    split2(v0, v1, hh, ll);
                    *(unsigned*)(CH_ + (size_t)r*ldc + col) = hh;
                    *(unsigned*)(CL_ + (size_t)r*ldc + col) = ll;
                } else {
                    float* cp = Cf + (size_t)r * ldc + col;
                    if (resid) {
                        float2 old = *(float2*)cp;
                        v0 += old.x; v1 += old.y;
                    }
                    float2 ov = {v0, v1};
                    *(float2*)cp = ov;
                }
            }
        }
    }
}

// ==================== flash attention (bf16 pre-split inputs) ==============
#define FQS 72    // Q/K smem row stride (bf16)
#define FVS 136   // V^T smem row stride (bf16)
#define FA_QH 0
#define FA_QL (FA_QH + 128*FQS*2)
#define FA_KH (FA_QL + 128*FQS*2)
#define FA_KL (FA_KH + 128*FQS*2)
#define FA_VH (FA_KL + 128*FQS*2)
#define FA_VL (FA_VH + 64*FVS*2)
#define FA_SMEM (FA_VL + 64*FVS*2)   // 108,544 bytes

__global__ __launch_bounds__(256) void flash_kernel(
    const __nv_bfloat16* __restrict__ qh, const __nv_bfloat16* __restrict__ ql,
    __nv_bfloat16* __restrict__ oh, __nv_bfloat16* __restrict__ ol)
{
    extern __shared__ char fsm[];
    __nv_bfloat16* QH = (__nv_bfloat16*)(fsm + FA_QH);
    __nv_bfloat16* QL = (__nv_bfloat16*)(fsm + FA_QL);
    __nv_bfloat16* KH = (__nv_bfloat16*)(fsm + FA_KH);
    __nv_bfloat16* KL = (__nv_bfloat16*)(fsm + FA_KL);
    __nv_bfloat16* VH = (__nv_bfloat16*)(fsm + FA_VH);
    __nv_bfloat16* VL = (__nv_bfloat16*)(fsm + FA_VL);

    int tid = threadIdx.x, wid = tid >> 5, lane = tid & 31;
    int g = lane >> 2, tg = lane & 3;
    int z = blockIdx.y;
    int b = z >> 3, h = z & 7;
    size_t base = (size_t)b * LTOK * 1536;
    int q0 = blockIdx.x * 128;

    // ---- load Q tile (already scaled + split at QKV epilogue) ----
    {
        int r = tid >> 1, cb = (tid & 1) * 32;
        size_t off = base + (size_t)(q0 + r) * 1536 + h*64 + cb;
        #pragma unroll
        for (int j = 0; j < 4; j++) {
            *(uint4*)&QH[r*FQS + cb + j*8] = *(const uint4*)(qh + off + j*8);
            *(uint4*)&QL[r*FQS + cb + j*8] = *(const uint4*)(ql + off + j*8);
        }
    }

    float acco[8][4];
    #pragma unroll
    for (int i = 0; i < 8; i++)
        #pragma unroll
        for (int q = 0; q < 4; q++) acco[i][q] = 0.f;
    float m0 = -3.402823466e38f, m1 = -3.402823466e38f, l0s = 0.f, l1s = 0.f;

    for (int t = 0; t < LTOK/128; t++) {
        __syncthreads();
        {
            int r = tid >> 1, cb = (tid & 1) * 32;
            size_t koff = base + (size_t)(t*128 + r) * 1536 + 512 + h*64 + cb;
            #pragma unroll
            for (int j = 0; j < 4; j++) {
                *(uint4*)&KH[r*FQS + cb + j*8] = *(const uint4*)(qh + koff + j*8);
                *(uint4*)&KL[r*FQS + cb + j*8] = *(const uint4*)(ql + koff + j*8);
            }
            // V transposed: VH[d][kv]
            size_t voff = base + (size_t)(t*128 + r) * 1536 + 1024 + h*64 + cb;
            #pragma unroll
            for (int j = 0; j < 4; j++) {
                uint4 vh4 = *(const uint4*)(qh + voff + j*8);
                uint4 vl4 = *(const uint4*)(ql + voff + j*8);
                const unsigned short* hs = (const unsigned short*)&vh4;
                const unsigned short* ls = (const unsigned short*)&vl4;
                #pragma unroll
                for (int i = 0; i < 8; i++) {
                    int d = cb + j*8 + i;
                    *(unsigned short*)&VH[d*FVS + r] = hs[i];
                    *(unsigned short*)&VL[d*FVS + r] = ls[i];
                }
            }
        }
        __syncthreads();

        // ---- S = Q @ K^T ----
        float accs[16][4];
        #pragma unroll
        for (int nt = 0; nt < 16; nt++)
            #pragma unroll
            for (int q = 0; q < 4; q++) accs[nt][q] = 0.f;
        #pragma unroll
        for (int ks = 0; ks < 4; ks++) {
            int col = ks*16 + tg*2;
            int r0 = wid*16 + g;
            unsigned aqh[4], aql[4];
            aqh[0] = *(unsigned*)&QH[r0*FQS + col];
            aqh[1] = *(unsigned*)&QH[(r0+8)*FQS + col];
            aqh[2] = *(unsigned*)&QH[r0*FQS + col + 8];
            aqh[3] = *(unsigned*)&QH[(r0+8)*FQS + col + 8];
            aql[0] = *(unsigned*)&QL[r0*FQS + col];
            aql[1] = *(unsigned*)&QL[(r0+8)*FQS + col];
            aql[2] = *(unsigned*)&QL[r0*FQS + col + 8];
            aql[3] = *(unsigned*)&QL[(r0+8)*FQS + col + 8];
            #pragma unroll
            for (int nt = 0; nt < 16; nt++) {
                int kr = nt*8 + g;
                unsigned bkh[2], bkl[2];
                bkh[0] = *(unsigned*)&KH[kr*FQS + col];
                bkh[1] = *(unsigned*)&KH[kr*FQS + col + 8];
                bkl[0] = *(unsigned*)&KL[kr*FQS + col];
                bkl[1] = *(unsigned*)&KL[kr*FQS + col + 8];
                mma16816(accs[nt], aqh, bkh);
                mma16816(accs[nt], aqh, bkl);
                mma16816(accs[nt], aql, bkh);
            }
        }

        // ---- online softmax ----
        float mx0 = -3.402823466e38f, mx1 = -3.402823466e38f;
        #pragma unroll
        for (int nt = 0; nt < 16; nt++) {
            mx0 = fmaxf(mx0, fmaxf(accs[nt][0], accs[nt][1]));
            mx1 = fmaxf(mx1, fmaxf(accs[nt][2], accs[nt][3]));
        }
        mx0 = fmaxf(mx0, __shfl_xor_sync(0xffffffffu, mx0, 1));
        mx0 = fmaxf(mx0, __shfl_xor_sync(0xffffffffu, mx0, 2));
        mx1 = fmaxf(mx1, __shfl_xor_sync(0xffffffffu, mx1, 1));
        mx1 = fmaxf(mx1, __shfl_xor_sync(0xffffffffu, mx1, 2));
        float mn0 = fmaxf(m0, mx0), mn1 = fmaxf(m1, mx1);
        float c0 = expf(m0 - mn0), c1 = expf(m1 - mn1);
        float s0 = 0.f, s1 = 0.f;
        #pragma unroll
        for (int nt = 0; nt < 16; nt++) {
            accs[nt][0] = expf(accs[nt][0] - mn0);
            accs[nt][1] = expf(accs[nt][1] - mn0);
            accs[nt][2] = expf(accs[nt][2] - mn1);
            accs[nt][3] = expf(accs[nt][3] - mn1);
            s0 += accs[nt][0] + accs[nt][1];
            s1 += accs[nt][2] + accs[nt][3];
        }
        s0 += __shfl_xor_sync(0xffffffffu, s0, 1);
        s0 += __shfl_xor_sync(0xffffffffu, s0, 2);
        s1 += __shfl_xor_sync(0xffffffffu, s1, 1);
        s1 += __shfl_xor_sync(0xffffffffu, s1, 2);
        l0s = l0s * c0 + s0;
        l1s = l1s * c1 + s1;
        m0 = mn0; m1 = mn1;
        #pragma unroll
        for (int i = 0; i < 8; i++) {
            acco[i][0] *= c0; acco[i][1] *= c0;
            acco[i][2] *= c1; acco[i][3] *= c1;
        }

        // ---- O += P @ V ----
        #pragma unroll
        for (int pks = 0; pks < 8; pks++) {
            unsigned aph[4], apl[4];
            split2(accs[2*pks][0],   accs[2*pks][1],   aph[0], apl[0]);
            split2(accs[2*pks][2],   accs[2*pks][3],   aph[1], apl[1]);
            split2(accs[2*pks+1][0], accs[2*pks+1][1], aph[2], apl[2]);
            split2(accs[2*pks+1][2], accs[2*pks+1][3], aph[3], apl[3]);
            int kcol = pks*16 + tg*2;
            #pragma unroll
            for (int nt2 = 0; nt2 < 8; nt2++) {
                int d = nt2*8 + g;
                unsigned bvh[2], bvl[2];
                bvh[0] = *(unsigned*)&VH[d*FVS + kcol];
                bvh[1] = *(unsigned*)&VH[d*FVS + kcol + 8];
                bvl[0] = *(unsigned*)&VL[d*FVS + kcol];
                bvl[1] = *(unsigned*)&VL[d*FVS + kcol + 8];
                mma16816(acco[nt2], aph, bvh);
                mma16816(acco[nt2], aph, bvl);
                mma16816(acco[nt2], apl, bvh);
            }
        }
    }

    // ---- epilogue: O /= l, write bf16 hi/lo ----
    float inv0 = 1.0f / l0s, inv1 = 1.0f / l1s;
    int row = q0 + wid*16 + g;
    #pragma unroll
    for (int nt2 = 0; nt2 < 8; nt2++) {
        int col = h*64 + nt2*8 + tg*2;
        unsigned hh, ll;
        split2(acco[nt2][0]*inv0, acco[nt2][1]*inv0, hh, ll);
        *(unsigned*)(oh + (size_t)(b*LTOK + row) * EDIM + col) = hh;
        *(unsigned*)(ol + (size_t)(b*LTOK + row) * EDIM + col) = ll;
        split2(acco[nt2][2]*inv1, acco[nt2][3]*inv1, hh, ll);
        *(unsigned*)(oh + (size_t)(b*LTOK + row + 8) * EDIM + col) = hh;
        *(unsigned*)(ol + (size_t)(b*LTOK + row + 8) * EDIM + col) = ll;
    }
}

// ---------------- FPS -------------------------------------------------------
__global__ __launch_bounds__(512) void fps_kernel(const float* __restrict__ xyzs) {
    int blk = blockIdx.x;
    int b = blk / TO, j = blk % TO;
    const float* P = xyzs + (size_t)(b*NT + 2*j)*NP*3;
    int tid = threadIdx.x;
    float px[8], py[8], pz[8], dist[8];
    #pragma unroll
    for (int i = 0; i < 8; i++) {
        int p = tid + i*512;
        px[i] = P[p*3+0]; py[i] = P[p*3+1]; pz[i] = P[p*3+2];
        dist[i] = 1e10f;
    }
    __shared__ float sbx, sby, sbz;
    __shared__ float swv[16];
    __shared__ int   swi[16];
    float* anch = g_anchor + (size_t)blk*MM*3;
    if (tid == 0) {
        sbx = P[0]; sby = P[1]; sbz = P[2];
        anch[0] = P[0]; anch[1] = P[1]; anch[2] = P[2];
    }
    __syncthreads();
    for (int s = 1; s < MM; s++) {
        float bx = sbx, by = sby, bz = sbz;
        float bestv = -1.0f; int besti = 0x7fffffff;
        #pragma unroll
        for (int i = 0; i < 8; i++) {
            float dx = __fsub_rn(px[i], bx);
            float dy = __fsub_rn(py[i], by);
            float dz = __fsub_rn(pz[i], bz);
            float d = __fadd_rn(__fadd_rn(__fmul_rn(dx,dx), __fmul_rn(dy,dy)), __fmul_rn(dz,dz));
            float nd = fminf(dist[i], d);
            dist[i] = nd;
            int p = tid + i*512;
            if (nd > bestv || (nd == bestv && p < besti)) { bestv = nd; besti = p; }
        }
        #pragma unroll
        for (int off = 16; off; off >>= 1) {
            float ov = __shfl_down_sync(0xffffffffu, bestv, off);
            int   oi = __shfl_down_sync(0xffffffffu, besti, off);
            if (ov > bestv || (ov == bestv && oi < besti)) { bestv = ov; besti = oi; }
        }
        if ((tid & 31) == 0) { swv[tid>>5] = bestv; swi[tid>>5] = besti; }
        __syncthreads();
        if (tid == 0) {
            float v = swv[0]; int ii = swi[0];
            #pragma unroll
            for (int w = 1; w < 16; w++)
                if (swv[w] > v || (swv[w] == v && swi[w] < ii)) { v = swv[w]; ii = swi[w]; }
            float x0 = P[ii*3+0], y0 = P[ii*3+1], z0 = P[ii*3+2];
            sbx = x0; sby = y0; sbz = z0;
            anch[s*3+0] = x0; anch[s*3+1] = y0; anch[s*3+2] = z0;
        }
        __syncthreads();
    }
}

// ---------------- Ball query ------------------------------------------------
__global__ __launch_bounds__(128) void ball_kernel(const float* __restrict__ xyzs) {
    int w = blockIdx.x*4 + (threadIdx.x >> 5);
    int lane = threadIdx.x & 31;
    int o = w / NTOK;
    int tok = w % NTOK;
    int b = tok / LTOK, loc = tok % LTOK, j = loc / MM;
    int pf = 2*j + o;
    int of = (pf == 0) ? 0 : (pf - 1);
    const float* P = xyzs + (size_t)(b*NT + of)*NP*3;
    float ax = g_anchor[tok*3+0], ay = g_anchor[tok*3+1], az = g_anchor[tok*3+2];
    int* out = g_ball + ((size_t)o*NTOK + tok)*KSAMP;
    int cnt = 0, first = 0; bool found = false;
    for (int base = 0; base < NP; base += 32) {
        int p = base + lane;
        float x = P[p*3+0], y = P[p*3+1], z = P[p*3+2];
        float dx = __fsub_rn(ax,x), dy = __fsub_rn(ay,y), dz = __fsub_rn(az,z);
        float d2 = __fadd_rn(__fadd_rn(__fmul_rn(dx,dx), __fmul_rn(dy,dy)), __fmul_rn(dz,dz));
        bool inside = d2 < RAD2;
        unsigned msk = __ballot_sync(0xffffffffu, inside);
        if (!found && msk) { first = base + __ffs(msk) - 1; found = true; }
        int pos = cnt + __popc(msk & ((1u << lane) - 1u));
        if (inside && pos < KSAMP) out[pos] = p;
        cnt += __popc(msk);
        if (cnt >= KSAMP) break;
    }
    if (lane >= cnt) out[lane] = found ? first : 0;
}

// ---------------- grouped conv + max pool ----------------------------------
__global__ __launch_bounds__(128) void conv_kernel(
    const float* __restrict__ xyzs, const float* __restrict__ oldf,
    const float* __restrict__ Wd, const float* __restrict__ Wf,
    float* __restrict__ dout)
{
    int tok = blockIdx.x;
    int b = tok / LTOK, loc = tok % LTOK, j = loc / MM;
    int tid = threadIdx.x;
    __shared__ float sd[KSAMP][4];
    __shared__ float sf[KSAMP][2];
    float ax = g_anchor[tok*3+0], ay = g_anchor[tok*3+1], az = g_anchor[tok*3+2];
    float wd[4][4], wf[4][2], vmax[4];
    #pragma unroll
    for (int r = 0; r < 4; r++) {
        int d = tid + 128*r;
        wd[r][0] = Wd[d*4+0]; wd[r][1] = Wd[d*4+1]; wd[r][2] = Wd[d*4+2]; wd[r][3] = Wd[d*4+3];
        wf[r][0] = Wf[d*2+0]; wf[r][1] = Wf[d*2+1];
        vmax[r] = -3.402823466e38f;
    }
    for (int o = 0; o < 3; o++) {
        int pf = 2*j + o;
        int of = (pf == 0) ? 0 : (pf - 1);
        const float* P = xyzs + (size_t)(b*NT + of)*NP*3;
        const float* F = oldf + (size_t)(b*NT + of)*2*NP;
        __syncthreads();
        if (tid < KSAMP) {
            int idx = g_ball[((size_t)o*NTOK + tok)*KSAMP + tid];
            sd[tid][0] = P[idx*3+0] - ax;
            sd[tid][1] = P[idx*3+1] - ay;
            sd[tid][2] = P[idx*3+2] - az;
            sd[tid][3] = (float)(o - 1);
            sf[tid][0] = F[idx];
            sf[tid][1] = F[NP + idx];
        }
        __syncthreads();
        #pragma unroll 4
        for (int k = 0; k < KSAMP; k++) {
            float d0 = sd[k][0], d1 = sd[k][1], d2 = sd[k][2], d3 = sd[k][3];
            float f0 = sf[k][0], f1 = sf[k][1];
            #pragma unroll
            for (int r = 0; r < 4; r++) {
                float de = wd[r][0]*d0 + wd[r][1]*d1 + wd[r][2]*d2 + wd[r][3]*d3;
                float fe = wf[r][0]*f0 + wf[r][1]*f1;
                vmax[r] = fmaxf(vmax[r], de*fe);
            }
        }
    }
    #pragma unroll
    for (int r = 0; r < 4; r++)
        dout[FEAT_OFF + (size_t)tok*EDIM + tid + 128*r] = vmax[r];
}

// ---------------- pos + contrastive + relu(pos+feat) -----------------------
__global__ __launch_bounds__(512) void embed_kernel(
    const float* __restrict__ pw, const float* __restrict__ pb,
    const float* __restrict__ cw, const float* __restrict__ cb,
    float* __restrict__ dout)
{
    int tok = blockIdx.x;
    int d = threadIdx.x;
    int loc = tok % LTOK, j = loc / MM;
    float ax = g_anchor[tok*3+0], ay = g_anchor[tok*3+1], az = g_anchor[tok*3+2];
    float tv = (float)(j + 1);
    float pos = pw[d*4+0]*ax + pw[d*4+1]*ay + pw[d*4+2]*az + pw[d*4+3]*tv + pb[d];
    float con = cw[d*4+0]*ax + cw[d*4+1]*ay + cw[d*4+2]*az + cw[d*4+3]*tv + cb[d];
    dout[CONTR_OFF + (size_t)tok*EDIM + d] = con;
    float feat = dout[FEAT_OFF + (size_t)tok*EDIM + d];
    g_x[(size_t)tok*EDIM + d] = fmaxf(pos + feat, 0.0f);
}

// ---------------- LayerNorm -> bf16 hi/lo ----------------------------------
__global__ __launch_bounds__(256) void ln_split_kernel(
    const float* __restrict__ x, const float* __restrict__ s,
    const float* __restrict__ bb,
    __nv_bfloat16* __restrict__ outh, __nv_bfloat16* __restrict__ outl)
{
    int tok = blockIdx.x;
    int tid = threadIdx.x;
    const float* row = x + (size_t)tok*EDIM;
    float v0 = row[tid], v1 = row[tid + 256];
    float sum = v0 + v1, sq = v0*v0 + v1*v1;
    #pragma unroll
    for (int off = 16; off; off >>= 1) {
        sum += __shfl_xor_sync(0xffffffffu, sum, off);
        sq  += __shfl_xor_sync(0xffffffffu, sq, off);
    }
    __shared__ float ssum[8], ssq[8];
    if ((tid & 31) == 0) { ssum[tid>>5] = sum; ssq[tid>>5] = sq; }
    __syncthreads();
    float ts = 0.f, tq = 0.f;
    #pragma unroll
    for (int w = 0; w < 8; w++) { ts += ssum[w]; tq += ssq[w]; }
    float mu = ts * (1.0f/512.0f);
    float var = tq * (1.0f/512.0f) - mu*mu;
    float rstd = rsqrtf(var + 1e-5f);
    float y0 = (v0 - mu)*rstd*s[tid] + bb[tid];
    float y1 = (v1 - mu)*rstd*s[tid+256] + bb[tid+256];
    __nv_bfloat16 h0 = __float2bfloat16(y0);
    __nv_bfloat16 h1 = __float2bfloat16(y1);
    outh[(size_t)tok*EDIM + tid]       = h0;
    outh[(size_t)tok*EDIM + tid + 256] = h1;
    outl[(size_t)tok*EDIM + tid]       = __float2bfloat16(y0 - __bfloat162float(h0));
    outl[(size_t)tok*EDIM + tid + 256] = __float2bfloat16(y1 - __bfloat162float(h1));
}

// ---------------- fp32 LayerNorm (head) ------------------------------------
__global__ __launch_bounds__(256) void ln_kernel(
    const float* __restrict__ x, const float* __restrict__ s,
    const float* __restrict__ bb, float* __restrict__ out)
{
    int tok = blockIdx.x;
    int tid = threadIdx.x;
    const float* row = x + (size_t)tok*EDIM;
    float v0 = row[tid], v1 = row[tid + 256];
    float sum = v0 + v1, sq = v0*v0 + v1*v1;
    #pragma unroll
    for (int off = 16; off; off >>= 1) {
        sum += __shfl_xor_sync(0xffffffffu, sum, off);
        sq  += __shfl_xor_sync(0xffffffffu, sq, off);
    }
    __shared__ float ssum[8], ssq[8];
    if ((tid & 31) == 0) { ssum[tid>>5] = sum; ssq[tid>>5] = sq; }
    __syncthreads();
    float ts = 0.f, tq = 0.f;
    #pragma unroll
    for (int w = 0; w < 8; w++) { ts += ssum[w]; tq += ssq[w]; }
    float mu = ts * (1.0f/512.0f);
    float var = tq * (1.0f/512.0f) - mu*mu;
    float rstd = rsqrtf(var + 1e-5f);
    out[(size_t)tok*EDIM + tid]       = (v0 - mu)*rstd*s[tid] + bb[tid];
    out[(size_t)tok*EDIM + tid + 256] = (v1 - mu)*rstd*s[tid+256] + bb[tid+256];
}

// ---------------- head ------------------------------------------------------
__global__ __launch_bounds__(512) void pool_kernel() {
    int b = blockIdx.x;
    int d = threadIdx.x;
    float v = -3.402823466e38f;
    const float* p = g_x + (size_t)b*LTOK*EDIM + d;
    for (int i = 0; i < LTOK; i++) v = fmaxf(v, p[(size_t)i*EDIM]);
    g_pool[b*EDIM + d] = v;
}
__global__ __launch_bounds__(256) void head1_kernel(
    const float* __restrict__ W, const float* __restrict__ bias)
{
    int out = blockIdx.x*8 + (threadIdx.x >> 5);
    int lane = threadIdx.x & 31;
    int b = out >> 10, jj = out & 1023;
    const float* xr = g_hln + b*EDIM;
    const float* wr = W + (size_t)jj*EDIM;
    float s = 0.f;
    for (int d = lane; d < EDIM; d += 32) s += xr[d]*wr[d];
    #pragma unroll
    for (int off = 16; off; off >>= 1) s += __shfl_xor_sync(0xffffffffu, s, off);
    if (lane == 0) g_h1[out] = gelu_exact(s + bias[jj]);
}
__global__ __launch_bounds__(128) void head2_kernel(
    const float* __restrict__ W, const float* __restrict__ bias,
    float* __restrict__ dout)
{
    int out = blockIdx.x*4 + (threadIdx.x >> 5);
    int lane = threadIdx.x & 31;
    int b = out / NCLS, c = out % NCLS;
    float s = 0.f;
    for (int d = lane; d < MLPD; d += 32) s += g_h1[b*MLPD + d]*W[(size_t)c*MLPD + d];
    #pragma unroll
    for (int off = 16; off; off >>= 1) s += __shfl_xor_sync(0xffffffffu, s, off);
    if (lane == 0) dout[out] = s + bias[c];
}

// ---------------- launch ---------------------------------------------------
extern "C" void kernel_launch(void* const* d_in, const int* in_sizes, int n_in,
                              void* d_out, int out_size) {
    const float* xyzs      = (const float*)d_in[0];
    const float* oldf      = (const float*)d_in[1];
    const float* conv_d_w  = (const float*)d_in[2];
    const float* conv_f_w  = (const float*)d_in[3];
    const float* pos_w     = (const float*)d_in[4];
    const float* pos_b     = (const float*)d_in[5];
    const float* contr_w   = (const float*)d_in[6];
    const float* contr_b   = (const float*)d_in[7];
    const float* ln1_s     = (const float*)d_in[8];
    const float* ln1_b     = (const float*)d_in[9];
    const float* qkv_w     = (const float*)d_in[10];
    const float* out_w     = (const float*)d_in[11];
    const float* out_b     = (const float*)d_in[12];
    const float* ln2_s     = (const float*)d_in[13];
    const float* ln2_b     = (const float*)d_in[14];
    const float* ff1_w     = (const float*)d_in[15];
    const float* ff1_b     = (const float*)d_in[16];
    const float* ff2_w     = (const float*)d_in[17];
    const float* ff2_b     = (const float*)d_in[18];
    const float* head_ln_s = (const float*)d_in[19];
    const float* head_ln_b = (const float*)d_in[20];
    const float* head1_w   = (const float*)d_in[21];
    const float* head1_b   = (const float*)d_in[22];
    const float* head2_w   = (const float*)d_in[23];
    const float* head2_b   = (const float*)d_in[24];
    float* out = (float*)d_out;

    float *px, *ppool, *phln;
    __nv_bfloat16 *pwh, *pwl, *phh, *phl, *pqh, *pql, *poh, *pol, *pf1h, *pf1l;
    cudaGetSymbolAddress((void**)&px,    g_x);
    cudaGetSymbolAddress((void**)&ppool, g_pool);
    cudaGetSymbolAddress((void**)&phln,  g_hln);
    cudaGetSymbolAddress((void**)&pwh,   g_wh);
    cudaGetSymbolAddress((void**)&pwl,   g_wl);
    cudaGetSymbolAddress((void**)&phh,   g_hh);
    cudaGetSymbolAddress((void**)&phl,   g_hl);
    cudaGetSymbolAddress((void**)&pqh,   g_qh);
    cudaGetSymbolAddress((void**)&pql,   g_ql);
    cudaGetSymbolAddress((void**)&poh,   g_oh);
    cudaGetSymbolAddress((void**)&pol,   g_ol);
    cudaGetSymbolAddress((void**)&pf1h,  g_f1h);
    cudaGetSymbolAddress((void**)&pf1l,  g_f1l);

    cudaFuncSetAttribute(flash_kernel, cudaFuncAttributeMaxDynamicSharedMemorySize, FA_SMEM);

    // ---- one-time weight splits (graph-safe, deterministic) ----
    wsplit_kernel<<<3145728/1024, 256>>>(qkv_w, pwh + WQKV_OFF, pwl + WQKV_OFF, 3145728);
    wsplit_kernel<<<1048576/1024, 256>>>(out_w, pwh + WOUT_OFF, pwl + WOUT_OFF, 1048576);
    wsplit_kernel<<<2097152/1024, 256>>>(ff1_w, pwh + WFF1_OFF, pwl + WFF1_OFF, 2097152);
    wsplit_kernel<<<2097152/1024, 256>>>(ff2_w, pwh + WFF2_OFF, pwl + WFF2_OFF, 2097152);

    fps_kernel<<<48, 512>>>(xyzs);
    ball_kernel<<<(3*NTOK)/4, 128>>>(xyzs);
    conv_kernel<<<NTOK, 128>>>(xyzs, oldf, conv_d_w, conv_f_w, out);
    embed_kernel<<<NTOK, 512>>>(pos_w, pos_b, contr_w, contr_b, out);

    for (int l = 0; l < 4; l++) {
        ln_split_kernel<<<NTOK, 256>>>(px, ln1_s + l*EDIM, ln1_b + l*EDIM, phh, phl);
        // QKV: split output (Q pre-scaled by 1/8)
        tgemm_b<<<dim3(12,48,1), 256>>>(
            phh, phl, pwh + WQKV_OFF + (size_t)l*1536*512, pwl + WQKV_OFF + (size_t)l*1536*512,
            nullptr, nullptr, pqh, pql,
            512, 512, 512, 1536, 0,0,0, 1,1);
        // fused attention -> o hi/lo
        flash_kernel<<<dim3(LTOK/128, NB*NHEAD), 256, FA_SMEM>>>(pqh, pql, poh, pol);
        // out proj + residual (fp32 out)
        tgemm_b<<<dim3(4,48,1), 256>>>(
            poh, pol, pwh + WOUT_OFF + (size_t)l*512*512, pwl + WOUT_OFF + (size_t)l*512*512,
            out_b + l*EDIM, px, nullptr, nullptr,
            512, 512, 512, 512, 0,1,1, 0,0);
        ln_split_kernel<<<NTOK, 256>>>(px, ln2_s + l*EDIM, ln2_b + l*EDIM, phh, phl);
        // ff1 + gelu: split output
        tgemm_b<<<dim3(8,48,1), 256>>>(
            phh, phl, pwh + WFF1_OFF + (size_t)l*1024*512, pwl + WFF1_OFF + (size_t)l*1024*512,
            ff1_b + l*MLPD, nullptr, pf1h, pf1l,
            512, 512, 512, 1024, 1,0,1, 1,0);
        // ff2 + residual (fp32 out)
        tgemm_b<<<dim3(4,48,1), 256>>>(
            pf1h, pf1l, pwh + WFF2_OFF + (size_t)l*512*1024, pwl + WFF2_OFF + (size_t)l*512*1024,
            ff2_b + l*EDIM, px, nullptr, nullptr,
            1024, 1024, 1024, 512, 0,1,1, 0,0);
    }

    pool_kernel<<<NB, 512>>>();
    ln_kernel<<<NB, 256>>>(ppool, head_ln_s, head_ln_b, phln);
    head1_kernel<<<(NB*MLPD)/8, 256>>>(head1_w, head1_b);
    head2_kernel<<<NB*NCLS/4, 128>>>(head2_w, head2_b, out);
}

// round 7
// speedup vs baseline: 4.4894x; 1.2015x over previous
#include <cuda_runtime.h>
#include <cuda_bf16.h>
#include <cstdint>
#include <math.h>

#define NB 4
#define NT 24
#define NP 4096
#define MM 128
#define TO 12
#define LTOK 1536
#define NTOK 6144
#define EDIM 512
#define NHEAD 8
#define DHEAD 64
#define MLPD 1024
#define NCLS 30
#define KSAMP 32
#define RAD2 0.09f

#define CONTR_OFF 120
#define FEAT_OFF (120 + NTOK*EDIM)

// weight-split buffer offsets (elements)
#define WQKV_OFF 0
#define WOUT_OFF 3145728
#define WFF1_OFF 4194304
#define WFF2_OFF 6291456
#define WTOT     8388608

// ---------------- scratch (device globals; no cudaMalloc allowed) ----------
__device__ __align__(256) float g_anchor[NTOK*3];
__device__ __align__(256) int   g_ball[3*NTOK*KSAMP];
__device__ __align__(256) float g_x[NTOK*EDIM];
__device__ __align__(256) float g_pool[NB*EDIM];
__device__ __align__(256) float g_hln[NB*EDIM];
__device__ __align__(256) float g_h1[NB*MLPD];

__device__ __align__(256) __nv_bfloat16 g_wh[WTOT];
__device__ __align__(256) __nv_bfloat16 g_wl[WTOT];
__device__ __align__(256) __nv_bfloat16 g_hh[NTOK*EDIM];
__device__ __align__(256) __nv_bfloat16 g_hl[NTOK*EDIM];
__device__ __align__(256) __nv_bfloat16 g_qh[NTOK*1536];
__device__ __align__(256) __nv_bfloat16 g_ql[NTOK*1536];
__device__ __align__(256) __nv_bfloat16 g_oh[NTOK*EDIM];
__device__ __align__(256) __nv_bfloat16 g_ol[NTOK*EDIM];
__device__ __align__(256) __nv_bfloat16 g_f1h[NTOK*MLPD];
__device__ __align__(256) __nv_bfloat16 g_f1l[NTOK*MLPD];

__device__ __forceinline__ float gelu_exact(float x){
    return 0.5f*x*(1.0f+erff(x*0.70710678118654752440f));
}

// ==================== PTX helpers ==========================================
__device__ __forceinline__ void mma16816(float* c, const unsigned* a, const unsigned* b){
    asm volatile("mma.sync.aligned.m16n8k16.row.col.f32.bf16.bf16.f32 "
        "{%0,%1,%2,%3}, {%4,%5,%6,%7}, {%8,%9}, {%0,%1,%2,%3};"
        : "+f"(c[0]),"+f"(c[1]),"+f"(c[2]),"+f"(c[3])
        : "r"(a[0]),"r"(a[1]),"r"(a[2]),"r"(a[3]), "r"(b[0]),"r"(b[1]));
}
__device__ __forceinline__ void split2(float x, float y, unsigned& hi, unsigned& lo){
    __nv_bfloat16 hx = __float2bfloat16(x), hy = __float2bfloat16(y);
    float rx = x - __bfloat162float(hx), ry = y - __bfloat162float(hy);
    __nv_bfloat16 lx = __float2bfloat16(rx), ly = __float2bfloat16(ry);
    hi = (unsigned)__bfloat16_as_ushort(hx) | ((unsigned)__bfloat16_as_ushort(hy) << 16);
    lo = (unsigned)__bfloat16_as_ushort(lx) | ((unsigned)__bfloat16_as_ushort(ly) << 16);
}
__device__ __forceinline__ unsigned smem_u32(const void* p){
    unsigned a;
    asm("{ .reg .u64 t; cvta.to.shared.u64 t, %1; cvt.u32.u64 %0, t; }" : "=r"(a) : "l"(p));
    return a;
}
__device__ __forceinline__ void ldmx4(unsigned* r, unsigned addr){
    asm volatile("ldmatrix.sync.aligned.m8n8.x4.shared.b16 {%0,%1,%2,%3}, [%4];"
        : "=r"(r[0]),"=r"(r[1]),"=r"(r[2]),"=r"(r[3]) : "r"(addr));
}
__device__ __forceinline__ void ldmx4t(unsigned* r, unsigned addr){
    asm volatile("ldmatrix.sync.aligned.m8n8.x4.trans.shared.b16 {%0,%1,%2,%3}, [%4];"
        : "=r"(r[0]),"=r"(r[1]),"=r"(r[2]),"=r"(r[3]) : "r"(addr));
}
#define CP16(d, s) asm volatile("cp.async.cg.shared.global [%0], [%1], 16;" :: "r"(d), "l"(s) : "memory")
#define CPC() asm volatile("cp.async.commit_group;" ::: "memory")
#define CPW1() asm volatile("cp.async.wait_group 1;" ::: "memory")
#define CPW0() asm volatile("cp.async.wait_group 0;" ::: "memory")

// ---------------- weight split prep ----------------------------------------
__global__ __launch_bounds__(256) void wsplit_kernel(
    const float* __restrict__ src, __nv_bfloat16* __restrict__ hi,
    __nv_bfloat16* __restrict__ lo, int n)
{
    int i = (blockIdx.x*256 + threadIdx.x)*4;
    if (i < n) {
        float4 v = *(const float4*)(src + i);
        unsigned h0, l0, h1, l1;
        split2(v.x, v.y, h0, l0); split2(v.z, v.w, h1, l1);
        *(unsigned*)(hi+i) = h0; *(unsigned*)(hi+i+2) = h1;
        *(unsigned*)(lo+i) = l0; *(unsigned*)(lo+i+2) = l1;
    }
}

#define LDT 40                       // smem row stride in bf16 (32 + 8 pad)
#define GARR (128*LDT*2)             // 10240 B per array
#define GSTAGE (4*GARR)              // 40960 B per stage
#define G_SMEM (2*GSTAGE)            // 81920 B

// ============ GEMM, pre-split bf16, cp.async double-buffered, ldmatrix =====
// C = A@W^T; A hi/lo [M,K], W hi/lo [N,K] row-major. BM=BN=128, BK=32.
__global__ __launch_bounds__(256) void tgemm_b(
    const __nv_bfloat16* __restrict__ AH_, const __nv_bfloat16* __restrict__ AL_,
    const __nv_bfloat16* __restrict__ WH_, const __nv_bfloat16* __restrict__ WL_,
    const float* __restrict__ bias, float* __restrict__ Cf,
    __nv_bfloat16* __restrict__ CH_, __nv_bfloat16* __restrict__ CL_,
    int K, int lda, int ldw, int ldc,
    int act, int resid, int hasb, int split, int qscale)
{
    extern __shared__ char smem[];
    unsigned sb = smem_u32(smem);

    int tid = threadIdx.x, wid = tid >> 5, lane = tid & 31;
    int g = lane >> 2, tg = lane & 3;
    int q8 = lane >> 3, lr8 = lane & 7;
    int rw = (wid >> 2) * 64, cw = (wid & 3) * 32;
    int bm = blockIdx.y * 128, bn = blockIdx.x * 128;

    float acc[4][4][4];
    #pragma unroll
    for (int i = 0; i < 4; i++)
        #pragma unroll
        for (int j = 0; j < 4; j++)
            #pragma unroll
            for (int p = 0; p < 4; p++) acc[i][j][p] = 0.f;

    int row = tid >> 1, half = tid & 1;
    int nch = K >> 5;

    // prefetch chunk 0 -> stage 0
    {
        unsigned dst = sb + (row*LDT + half*16)*2;
        const __nv_bfloat16* a = AH_ + (size_t)(bm+row)*lda + half*16;
        const __nv_bfloat16* a2 = AL_ + (size_t)(bm+row)*lda + half*16;
        const __nv_bfloat16* w = WH_ + (size_t)(bn+row)*ldw + half*16;
        const __nv_bfloat16* w2 = WL_ + (size_t)(bn+row)*ldw + half*16;
        CP16(dst, a); CP16(dst+16, a+8);
        CP16(dst+GARR, a2); CP16(dst+GARR+16, a2+8);
        CP16(dst+2*GARR, w); CP16(dst+2*GARR+16, w+8);
        CP16(dst+3*GARR, w2); CP16(dst+3*GARR+16, w2+8);
        CPC();
    }

    for (int c = 0; c < nch; c++) {
        if (c + 1 < nch) {
            unsigned dst = sb + ((c+1)&1)*GSTAGE + (row*LDT + half*16)*2;
            const __nv_bfloat16* a = AH_ + (size_t)(bm+row)*lda + (c+1)*32 + half*16;
            const __nv_bfloat16* a2 = AL_ + (size_t)(bm+row)*lda + (c+1)*32 + half*16;
            const __nv_bfloat16* w = WH_ + (size_t)(bn+row)*ldw + (c+1)*32 + half*16;
            const __nv_bfloat16* w2 = WL_ + (size_t)(bn+row)*ldw + (c+1)*32 + half*16;
            CP16(dst, a); CP16(dst+16, a+8);
            CP16(dst+GARR, a2); CP16(dst+GARR+16, a2+8);
            CP16(dst+2*GARR, w); CP16(dst+2*GARR+16, w+8);
            CP16(dst+3*GARR, w2); CP16(dst+3*GARR+16, w2+8);
            CPC();
            CPW1();
        } else {
            CPW0();
        }
        __syncthreads();
        unsigned sAH = sb + (c&1)*GSTAGE;
        unsigned sAL = sAH + GARR;
        unsigned sWH = sAH + 2*GARR;
        unsigned sWL = sAH + 3*GARR;
        #pragma unroll
        for (int ks = 0; ks < 2; ks++) {
            int k0 = ks * 16;
            unsigned ah[4][4], al[4][4], bh[2][4], bl[2][4];
            #pragma unroll
            for (int mt = 0; mt < 4; mt++) {
                unsigned off = (unsigned)((rw + mt*16 + (q8&1)*8 + lr8)*LDT + k0 + (q8>>1)*8)*2;
                ldmx4(ah[mt], sAH + off);
                ldmx4(al[mt], sAL + off);
            }
            #pragma unroll
            for (int ntp = 0; ntp < 2; ntp++) {
                unsigned off = (unsigned)((cw + ntp*16 + (q8>>1)*8 + lr8)*LDT + k0 + (q8&1)*8)*2;
                ldmx4(bh[ntp], sWH + off);
                ldmx4(bl[ntp], sWL + off);
            }
            #pragma unroll
            for (int mt = 0; mt < 4; mt++)
                #pragma unroll
                for (int nt = 0; nt < 4; nt++) {
                    const unsigned* ph = &bh[nt>>1][(nt&1)*2];
                    const unsigned* pl = &bl[nt>>1][(nt&1)*2];
                    mma16816(acc[mt][nt], ah[mt], ph);
                    mma16816(acc[mt][nt], ah[mt], pl);
                    mma16816(acc[mt][nt], al[mt], ph);
                }
        }
        __syncthreads();
    }
    // epilogue
    #pragma unroll
    for (int mt = 0; mt < 4; mt++) {
        #pragma unroll
        for (int nt = 0; nt < 4; nt++) {
            int r0 = bm + rw + mt*16 + g;
            int col = bn + cw + nt*8 + tg*2;
            #pragma unroll
            for (int half2 = 0; half2 < 2; half2++) {
                int r = r0 + half2*8;
                float v0 = acc[mt][nt][half2*2+0];
                float v1 = acc[mt][nt][half2*2+1];
                if (hasb) { v0 += bias[col]; v1 += bias[col+1]; }
                if (act)  { v0 = gelu_exact(v0); v1 = gelu_exact(v1); }
                if (split) {
                    if (qscale && col < 512) { v0 *= 0.125f; v1 *= 0.125f; }
                    unsigned hh, ll;
                    split2(v0, v1, hh, ll);
                    *(unsigned*)(CH_ + (size_t)r*ldc + col) = hh;
                    *(unsigned*)(CL_ + (size_t)r*ldc + col) = ll;
                } else {
                    float* cp = Cf + (size_t)r * ldc + col;
                    if (resid) {
                        float2 old = *(float2*)cp;
                        v0 += old.x; v1 += old.y;
                    }
                    float2 ov = {v0, v1};
                    *(float2*)cp = ov;
                }
            }
        }
    }
}

// ==================== flash attention (pre-split bf16, ldmatrix, cp.async) =
#define FQS 72
#define FARR (128*FQS*2)             // 18432 B
#define FQH 0
#define FQL FARR
#define FST(s) (2*FARR + (s)*4*FARR) // stage: KH, KL, VH, VL
#define FA_SMEM (2*FARR + 2*4*FARR)  // 184320 B

__global__ __launch_bounds__(256) void flash_kernel(
    const __nv_bfloat16* __restrict__ qh, const __nv_bfloat16* __restrict__ ql,
    __nv_bfloat16* __restrict__ oh, __nv_bfloat16* __restrict__ ol)
{
    extern __shared__ char fsm[];
    unsigned sb = smem_u32(fsm);

    int tid = threadIdx.x, wid = tid >> 5, lane = tid & 31;
    int g = lane >> 2, tg = lane & 3;
    int q8 = lane >> 3, lr8 = lane & 7;
    int z = blockIdx.y;
    int b = z >> 3, h = z & 7;
    size_t base = (size_t)b * LTOK * 1536;
    int q0 = blockIdx.x * 128;

    int row = tid >> 1, half = tid & 1;

    // prefetch Q + tile 0 (one group)
    {
        unsigned dq = sb + (row*FQS + half*32)*2;
        const __nv_bfloat16* sq = qh + base + (size_t)(q0+row)*1536 + h*64 + half*32;
        const __nv_bfloat16* sq2 = ql + base + (size_t)(q0+row)*1536 + h*64 + half*32;
        #pragma unroll
        for (int j = 0; j < 4; j++) {
            CP16(dq + j*16, sq + j*8);
            CP16(dq + FARR + j*16, sq2 + j*8);
        }
        unsigned dk = sb + FST(0) + (row*FQS + half*32)*2;
        const __nv_bfloat16* sk = qh + base + (size_t)row*1536 + 512 + h*64 + half*32;
        const __nv_bfloat16* sk2 = ql + base + (size_t)row*1536 + 512 + h*64 + half*32;
        const __nv_bfloat16* sv = qh + base + (size_t)row*1536 + 1024 + h*64 + half*32;
        const __nv_bfloat16* sv2 = ql + base + (size_t)row*1536 + 1024 + h*64 + half*32;
        #pragma unroll
        for (int j = 0; j < 4; j++) {
            CP16(dk + j*16, sk + j*8);
            CP16(dk + FARR + j*16, sk2 + j*8);
            CP16(dk + 2*FARR + j*16, sv + j*8);
            CP16(dk + 3*FARR + j*16, sv2 + j*8);
        }
        CPC();
    }

    float acco[8][4];
    #pragma unroll
    for (int i = 0; i < 8; i++)
        #pragma unroll
        for (int p = 0; p < 4; p++) acco[i][p] = 0.f;
    float m0 = -3.402823466e38f, m1 = -3.402823466e38f, l0s = 0.f, l1s = 0.f;

    for (int t = 0; t < LTOK/128; t++) {
        if (t + 1 < LTOK/128) {
            unsigned dk = sb + FST((t+1)&1) + (row*FQS + half*32)*2;
            size_t ro = base + (size_t)((t+1)*128+row)*1536 + h*64 + half*32;
            const __nv_bfloat16* sk = qh + ro + 512;
            const __nv_bfloat16* sk2 = ql + ro + 512;
            const __nv_bfloat16* sv = qh + ro + 1024;
            const __nv_bfloat16* sv2 = ql + ro + 1024;
            #pragma unroll
            for (int j = 0; j < 4; j++) {
                CP16(dk + j*16, sk + j*8);
                CP16(dk + FARR + j*16, sk2 + j*8);
                CP16(dk + 2*FARR + j*16, sv + j*8);
                CP16(dk + 3*FARR + j*16, sv2 + j*8);
            }
            CPC();
            CPW1();
        } else {
            CPW0();
        }
        __syncthreads();
        unsigned sKH = sb + FST(t&1);
        unsigned sKL = sKH + FARR;
        unsigned sVH = sKH + 2*FARR;
        unsigned sVL = sKH + 3*FARR;

        // ---- S = Q @ K^T ----
        float accs[16][4];
        #pragma unroll
        for (int nt = 0; nt < 16; nt++)
            #pragma unroll
            for (int p = 0; p < 4; p++) accs[nt][p] = 0.f;
        #pragma unroll
        for (int ks = 0; ks < 4; ks++) {
            int k0 = ks*16;
            unsigned aqh[4], aql[4];
            unsigned aoff = (unsigned)((wid*16 + (q8&1)*8 + lr8)*FQS + k0 + (q8>>1)*8)*2;
            ldmx4(aqh, sb + FQH + aoff);
            ldmx4(aql, sb + FQL + aoff);
            #pragma unroll
            for (int ntp = 0; ntp < 8; ntp++) {
                unsigned boff = (unsigned)((ntp*16 + (q8>>1)*8 + lr8)*FQS + k0 + (q8&1)*8)*2;
                unsigned bh4[4], bl4[4];
                ldmx4(bh4, sKH + boff);
                ldmx4(bl4, sKL + boff);
                mma16816(accs[2*ntp],   aqh, bh4);
                mma16816(accs[2*ntp],   aqh, bl4);
                mma16816(accs[2*ntp],   aql, bh4);
                mma16816(accs[2*ntp+1], aqh, bh4+2);
                mma16816(accs[2*ntp+1], aqh, bl4+2);
                mma16816(accs[2*ntp+1], aql, bh4+2);
            }
        }

        // ---- online softmax ----
        float mx0 = -3.402823466e38f, mx1 = -3.402823466e38f;
        #pragma unroll
        for (int nt = 0; nt < 16; nt++) {
            mx0 = fmaxf(mx0, fmaxf(accs[nt][0], accs[nt][1]));
            mx1 = fmaxf(mx1, fmaxf(accs[nt][2], accs[nt][3]));
        }
        mx0 = fmaxf(mx0, __shfl_xor_sync(0xffffffffu, mx0, 1));
        mx0 = fmaxf(mx0, __shfl_xor_sync(0xffffffffu, mx0, 2));
        mx1 = fmaxf(mx1, __shfl_xor_sync(0xffffffffu, mx1, 1));
        mx1 = fmaxf(mx1, __shfl_xor_sync(0xffffffffu, mx1, 2));
        float mn0 = fmaxf(m0, mx0), mn1 = fmaxf(m1, mx1);
        float c0 = __expf(m0 - mn0), c1 = __expf(m1 - mn1);
        float s0 = 0.f, s1 = 0.f;
        #pragma unroll
        for (int nt = 0; nt < 16; nt++) {
            accs[nt][0] = __expf(accs[nt][0] - mn0);
            accs[nt][1] = __expf(accs[nt][1] - mn0);
            accs[nt][2] = __expf(accs[nt][2] - mn1);
            accs[nt][3] = __expf(accs[nt][3] - mn1);
            s0 += accs[nt][0] + accs[nt][1];
            s1 += accs[nt][2] + accs[nt][3];
        }
        s0 += __shfl_xor_sync(0xffffffffu, s0, 1);
        s0 += __shfl_xor_sync(0xffffffffu, s0, 2);
        s1 += __shfl_xor_sync(0xffffffffu, s1, 1);
        s1 += __shfl_xor_sync(0xffffffffu, s1, 2);
        l0s = l0s * c0 + s0;
        l1s = l1s * c1 + s1;
        m0 = mn0; m1 = mn1;
        #pragma unroll
        for (int i = 0; i < 8; i++) {
            acco[i][0] *= c0; acco[i][1] *= c0;
            acco[i][2] *= c1; acco[i][3] *= c1;
        }

        // ---- O += P @ V (V fragments via ldmatrix.trans, no smem transpose)
        #pragma unroll
        for (int pks = 0; pks < 8; pks++) {
            unsigned aph[4], apl[4];
            split2(accs[2*pks][0],   accs[2*pks][1],   aph[0], apl[0]);
            split2(accs[2*pks][2],   accs[2*pks][3],   aph[1], apl[1]);
            split2(accs[2*pks+1][0], accs[2*pks+1][1], aph[2], apl[2]);
            split2(accs[2*pks+1][2], accs[2*pks+1][3], aph[3], apl[3]);
            #pragma unroll
            for (int ntp2 = 0; ntp2 < 4; ntp2++) {
                unsigned voff = (unsigned)((pks*16 + (q8&1)*8 + lr8)*FQS + ntp2*16 + (q8>>1)*8)*2;
                unsigned bvh[4], bvl[4];
                ldmx4t(bvh, sVH + voff);
                ldmx4t(bvl, sVL + voff);
                mma16816(acco[2*ntp2],   aph, bvh);
                mma16816(acco[2*ntp2],   aph, bvl);
                mma16816(acco[2*ntp2],   apl, bvh);
                mma16816(acco[2*ntp2+1], aph, bvh+2);
                mma16816(acco[2*ntp2+1], aph, bvl+2);
                mma16816(acco[2*ntp2+1], apl, bvh+2);
            }
        }
        __syncthreads();
    }

    // ---- epilogue: O /= l, write bf16 hi/lo ----
    float inv0 = 1.0f / l0s, inv1 = 1.0f / l1s;
    int orow = q0 + wid*16 + g;
    #pragma unroll
    for (int nt2 = 0; nt2 < 8; nt2++) {
        int col = h*64 + nt2*8 + tg*2;
        unsigned hh, ll;
        split2(acco[nt2][0]*inv0, acco[nt2][1]*inv0, hh, ll);
        *(unsigned*)(oh + (size_t)(b*LTOK + orow) * EDIM + col) = hh;
        *(unsigned*)(ol + (size_t)(b*LTOK + orow) * EDIM + col) = ll;
        split2(acco[nt2][2]*inv1, acco[nt2][3]*inv1, hh, ll);
        *(unsigned*)(oh + (size_t)(b*LTOK + orow + 8) * EDIM + col) = hh;
        *(unsigned*)(ol + (size_t)(b*LTOK + orow + 8) * EDIM + col) = ll;
    }
}

// ---------------- FPS -------------------------------------------------------
__global__ __launch_bounds__(512) void fps_kernel(const float* __restrict__ xyzs) {
    int blk = blockIdx.x;
    int b = blk / TO, j = blk % TO;
    const float* P = xyzs + (size_t)(b*NT + 2*j)*NP*3;
    int tid = threadIdx.x;
    float px[8], py[8], pz[8], dist[8];
    #pragma unroll
    for (int i = 0; i < 8; i++) {
        int p = tid + i*512;
        px[i] = P[p*3+0]; py[i] = P[p*3+1]; pz[i] = P[p*3+2];
        dist[i] = 1e10f;
    }
    __shared__ float sbx, sby, sbz;
    __shared__ float swv[16];
    __shared__ int   swi[16];
    float* anch = g_anchor + (size_t)blk*MM*3;
    if (tid == 0) {
        sbx = P[0]; sby = P[1]; sbz = P[2];
        anch[0] = P[0]; anch[1] = P[1]; anch[2] = P[2];
    }
    __syncthreads();
    for (int s = 1; s < MM; s++) {
        float bx = sbx, by = sby, bz = sbz;
        float bestv = -1.0f; int besti = 0x7fffffff;
        #pragma unroll
        for (int i = 0; i < 8; i++) {
            float dx = __fsub_rn(px[i], bx);
            float dy = __fsub_rn(py[i], by);
            float dz = __fsub_rn(pz[i], bz);
            float d = __fadd_rn(__fadd_rn(__fmul_rn(dx,dx), __fmul_rn(dy,dy)), __fmul_rn(dz,dz));
            float nd = fminf(dist[i], d);
            dist[i] = nd;
            int p = tid + i*512;
            if (nd > bestv || (nd == bestv && p < besti)) { bestv = nd; besti = p; }
        }
        #pragma unroll
        for (int off = 16; off; off >>= 1) {
            float ov = __shfl_down_sync(0xffffffffu, bestv, off);
            int   oi = __shfl_down_sync(0xffffffffu, besti, off);
            if (ov > bestv || (ov == bestv && oi < besti)) { bestv = ov; besti = oi; }
        }
        if ((tid & 31) == 0) { swv[tid>>5] = bestv; swi[tid>>5] = besti; }
        __syncthreads();
        if (tid == 0) {
            float v = swv[0]; int ii = swi[0];
            #pragma unroll
            for (int w = 1; w < 16; w++)
                if (swv[w] > v || (swv[w] == v && swi[w] < ii)) { v = swv[w]; ii = swi[w]; }
            float x0 = P[ii*3+0], y0 = P[ii*3+1], z0 = P[ii*3+2];
            sbx = x0; sby = y0; sbz = z0;
            anch[s*3+0] = x0; anch[s*3+1] = y0; anch[s*3+2] = z0;
        }
        __syncthreads();
    }
}

// ---------------- Ball query ------------------------------------------------
__global__ __launch_bounds__(128) void ball_kernel(const float* __restrict__ xyzs) {
    int w = blockIdx.x*4 + (threadIdx.x >> 5);
    int lane = threadIdx.x & 31;
    int o = w / NTOK;
    int tok = w % NTOK;
    int b = tok / LTOK, loc = tok % LTOK, j = loc / MM;
    int pf = 2*j + o;
    int of = (pf == 0) ? 0 : (pf - 1);
    const float* P = xyzs + (size_t)(b*NT + of)*NP*3;
    float ax = g_anchor[tok*3+0], ay = g_anchor[tok*3+1], az = g_anchor[tok*3+2];
    int* out = g_ball + ((size_t)o*NTOK + tok)*KSAMP;
    int cnt = 0, first = 0; bool found = false;
    for (int base = 0; base < NP; base += 32) {
        int p = base + lane;
        float x = P[p*3+0], y = P[p*3+1], z = P[p*3+2];
        float dx = __fsub_rn(ax,x), dy = __fsub_rn(ay,y), dz = __fsub_rn(az,z);
        float d2 = __fadd_rn(__fadd_rn(__fmul_rn(dx,dx), __fmul_rn(dy,dy)), __fmul_rn(dz,dz));
        bool inside = d2 < RAD2;
        unsigned msk = __ballot_sync(0xffffffffu, inside);
        if (!found && msk) { first = base + __ffs(msk) - 1; found = true; }
        int pos = cnt + __popc(msk & ((1u << lane) - 1u));
        if (inside && pos < KSAMP) out[pos] = p;
        cnt += __popc(msk);
        if (cnt >= KSAMP) break;
    }
    if (lane >= cnt) out[lane] = found ? first : 0;
}

// ---------------- grouped conv + max pool ----------------------------------
__global__ __launch_bounds__(128) void conv_kernel(
    const float* __restrict__ xyzs, const float* __restrict__ oldf,
    const float* __restrict__ Wd, const float* __restrict__ Wf,
    float* __restrict__ dout)
{
    int tok = blockIdx.x;
    int b = tok / LTOK, loc = tok % LTOK, j = loc / MM;
    int tid = threadIdx.x;
    __shared__ float sd[KSAMP][4];
    __shared__ float sf[KSAMP][2];
    float ax = g_anchor[tok*3+0], ay = g_anchor[tok*3+1], az = g_anchor[tok*3+2];
    float wd[4][4], wf[4][2], vmax[4];
    #pragma unroll
    for (int r = 0; r < 4; r++) {
        int d = tid + 128*r;
        wd[r][0] = Wd[d*4+0]; wd[r][1] = Wd[d*4+1]; wd[r][2] = Wd[d*4+2]; wd[r][3] = Wd[d*4+3];
        wf[r][0] = Wf[d*2+0]; wf[r][1] = Wf[d*2+1];
        vmax[r] = -3.402823466e38f;
    }
    for (int o = 0; o < 3; o++) {
        int pf = 2*j + o;
        int of = (pf == 0) ? 0 : (pf - 1);
        const float* P = xyzs + (size_t)(b*NT + of)*NP*3;
        const float* F = oldf + (size_t)(b*NT + of)*2*NP;
        __syncthreads();
        if (tid < KSAMP) {
            int idx = g_ball[((size_t)o*NTOK + tok)*KSAMP + tid];
            sd[tid][0] = P[idx*3+0] - ax;
            sd[tid][1] = P[idx*3+1] - ay;
            sd[tid][2] = P[idx*3+2] - az;
            sd[tid][3] = (float)(o - 1);
            sf[tid][0] = F[idx];
            sf[tid][1] = F[NP + idx];
        }
        __syncthreads();
        #pragma unroll 4
        for (int k = 0; k < KSAMP; k++) {
            float d0 = sd[k][0], d1 = sd[k][1], d2 = sd[k][2], d3 = sd[k][3];
            float f0 = sf[k][0], f1 = sf[k][1];
            #pragma unroll
            for (int r = 0; r < 4; r++) {
                float de = wd[r][0]*d0 + wd[r][1]*d1 + wd[r][2]*d2 + wd[r][3]*d3;
                float fe = wf[r][0]*f0 + wf[r][1]*f1;
                vmax[r] = fmaxf(vmax[r], de*fe);
            }
        }
    }
    #pragma unroll
    for (int r = 0; r < 4; r++)
        dout[FEAT_OFF + (size_t)tok*EDIM + tid + 128*r] = vmax[r];
}

// ---------------- pos + contrastive + relu(pos+feat) -----------------------
__global__ __launch_bounds__(512) void embed_kernel(
    const float* __restrict__ pw, const float* __restrict__ pb,
    const float* __restrict__ cw, const float* __restrict__ cb,
    float* __restrict__ dout)
{
    int tok = blockIdx.x;
    int d = threadIdx.x;
    int loc = tok % LTOK, j = loc / MM;
    float ax = g_anchor[tok*3+0], ay = g_anchor[tok*3+1], az = g_anchor[tok*3+2];
    float tv = (float)(j + 1);
    float pos = pw[d*4+0]*ax + pw[d*4+1]*ay + pw[d*4+2]*az + pw[d*4+3]*tv + pb[d];
    float con = cw[d*4+0]*ax + cw[d*4+1]*ay + cw[d*4+2]*az + cw[d*4+3]*tv + cb[d];
    dout[CONTR_OFF + (size_t)tok*EDIM + d] = con;
    float feat = dout[FEAT_OFF + (size_t)tok*EDIM + d];
    g_x[(size_t)tok*EDIM + d] = fmaxf(pos + feat, 0.0f);
}

// ---------------- LayerNorm -> bf16 hi/lo ----------------------------------
__global__ __launch_bounds__(256) void ln_split_kernel(
    const float* __restrict__ x, const float* __restrict__ s,
    const float* __restrict__ bb,
    __nv_bfloat16* __restrict__ outh, __nv_bfloat16* __restrict__ outl)
{
    int tok = blockIdx.x;
    int tid = threadIdx.x;
    const float* row = x + (size_t)tok*EDIM;
    float v0 = row[tid], v1 = row[tid + 256];
    float sum = v0 + v1, sq = v0*v0 + v1*v1;
    #pragma unroll
    for (int off = 16; off; off >>= 1) {
        sum += __shfl_xor_sync(0xffffffffu, sum, off);
        sq  += __shfl_xor_sync(0xffffffffu, sq, off);
    }
    __shared__ float ssum[8], ssq[8];
    if ((tid & 31) == 0) { ssum[tid>>5] = sum; ssq[tid>>5] = sq; }
    __syncthreads();
    float ts = 0.f, tq = 0.f;
    #pragma unroll
    for (int w = 0; w < 8; w++) { ts += ssum[w]; tq += ssq[w]; }
    float mu = ts * (1.0f/512.0f);
    float var = tq * (1.0f/512.0f) - mu*mu;
    float rstd = rsqrtf(var + 1e-5f);
    float y0 = (v0 - mu)*rstd*s[tid] + bb[tid];
    float y1 = (v1 - mu)*rstd*s[tid+256] + bb[tid+256];
    __nv_bfloat16 h0 = __float2bfloat16(y0);
    __nv_bfloat16 h1 = __float2bfloat16(y1);
    outh[(size_t)tok*EDIM + tid]       = h0;
    outh[(size_t)tok*EDIM + tid + 256] = h1;
    outl[(size_t)tok*EDIM + tid]       = __float2bfloat16(y0 - __bfloat162float(h0));
    outl[(size_t)tok*EDIM + tid + 256] = __float2bfloat16(y1 - __bfloat162float(h1));
}

// ---------------- fp32 LayerNorm (head) ------------------------------------
__global__ __launch_bounds__(256) void ln_kernel(
    const float* __restrict__ x, const float* __restrict__ s,
    const float* __restrict__ bb, float* __restrict__ out)
{
    int tok = blockIdx.x;
    int tid = threadIdx.x;
    const float* row = x + (size_t)tok*EDIM;
    float v0 = row[tid], v1 = row[tid + 256];
    float sum = v0 + v1, sq = v0*v0 + v1*v1;
    #pragma unroll
    for (int off = 16; off; off >>= 1) {
        sum += __shfl_xor_sync(0xffffffffu, sum, off);
        sq  += __shfl_xor_sync(0xffffffffu, sq, off);
    }
    __shared__ float ssum[8], ssq[8];
    if ((tid & 31) == 0) { ssum[tid>>5] = sum; ssq[tid>>5] = sq; }
    __syncthreads();
    float ts = 0.f, tq = 0.f;
    #pragma unroll
    for (int w = 0; w < 8; w++) { ts += ssum[w]; tq += ssq[w]; }
    float mu = ts * (1.0f/512.0f);
    float var = tq * (1.0f/512.0f) - mu*mu;
    float rstd = rsqrtf(var + 1e-5f);
    out[(size_t)tok*EDIM + tid]       = (v0 - mu)*rstd*s[tid] + bb[tid];
    out[(size_t)tok*EDIM + tid + 256] = (v1 - mu)*rstd*s[tid+256] + bb[tid+256];
}

// ---------------- head ------------------------------------------------------
__global__ __launch_bounds__(512) void pool_kernel() {
    int b = blockIdx.x;
    int d = threadIdx.x;
    float v = -3.402823466e38f;
    const float* p = g_x + (size_t)b*LTOK*EDIM + d;
    for (int i = 0; i < LTOK; i++) v = fmaxf(v, p[(size_t)i*EDIM]);
    g_pool[b*EDIM + d] = v;
}
__global__ __launch_bounds__(256) void head1_kernel(
    const float* __restrict__ W, const float* __restrict__ bias)
{
    int out = blockIdx.x*8 + (threadIdx.x >> 5);
    int lane = threadIdx.x & 31;
    int b = out >> 10, jj = out & 1023;
    const float* xr = g_hln + b*EDIM;
    const float* wr = W + (size_t)jj*EDIM;
    float s = 0.f;
    for (int d = lane; d < EDIM; d += 32) s += xr[d]*wr[d];
    #pragma unroll
    for (int off = 16; off; off >>= 1) s += __shfl_xor_sync(0xffffffffu, s, off);
    if (lane == 0) g_h1[out] = gelu_exact(s + bias[jj]);
}
__global__ __launch_bounds__(128) void head2_kernel(
    const float* __restrict__ W, const float* __restrict__ bias,
    float* __restrict__ dout)
{
    int out = blockIdx.x*4 + (threadIdx.x >> 5);
    int lane = threadIdx.x & 31;
    int b = out / NCLS, c = out % NCLS;
    float s = 0.f;
    for (int d = lane; d < MLPD; d += 32) s += g_h1[b*MLPD + d]*W[(size_t)c*MLPD + d];
    #pragma unroll
    for (int off = 16; off; off >>= 1) s += __shfl_xor_sync(0xffffffffu, s, off);
    if (lane == 0) dout[out] = s + bias[c];
}

// ---------------- launch ---------------------------------------------------
extern "C" void kernel_launch(void* const* d_in, const int* in_sizes, int n_in,
                              void* d_out, int out_size) {
    const float* xyzs      = (const float*)d_in[0];
    const float* oldf      = (const float*)d_in[1];
    const float* conv_d_w  = (const float*)d_in[2];
    const float* conv_f_w  = (const float*)d_in[3];
    const float* pos_w     = (const float*)d_in[4];
    const float* pos_b     = (const float*)d_in[5];
    const float* contr_w   = (const float*)d_in[6];
    const float* contr_b   = (const float*)d_in[7];
    const float* ln1_s     = (const float*)d_in[8];
    const float* ln1_b     = (const float*)d_in[9];
    const float* qkv_w     = (const float*)d_in[10];
    const float* out_w     = (const float*)d_in[11];
    const float* out_b     = (const float*)d_in[12];
    const float* ln2_s     = (const float*)d_in[13];
    const float* ln2_b     = (const float*)d_in[14];
    const float* ff1_w     = (const float*)d_in[15];
    const float* ff1_b     = (const float*)d_in[16];
    const float* ff2_w     = (const float*)d_in[17];
    const float* ff2_b     = (const float*)d_in[18];
    const float* head_ln_s = (const float*)d_in[19];
    const float* head_ln_b = (const float*)d_in[20];
    const float* head1_w   = (const float*)d_in[21];
    const float* head1_b   = (const float*)d_in[22];
    const float* head2_w   = (const float*)d_in[23];
    const float* head2_b   = (const float*)d_in[24];
    float* out = (float*)d_out;

    float *px, *ppool, *phln;
    __nv_bfloat16 *pwh, *pwl, *phh, *phl, *pqh, *pql, *poh, *pol, *pf1h, *pf1l;
    cudaGetSymbolAddress((void**)&px,    g_x);
    cudaGetSymbolAddress((void**)&ppool, g_pool);
    cudaGetSymbolAddress((void**)&phln,  g_hln);
    cudaGetSymbolAddress((void**)&pwh,   g_wh);
    cudaGetSymbolAddress((void**)&pwl,   g_wl);
    cudaGetSymbolAddress((void**)&phh,   g_hh);
    cudaGetSymbolAddress((void**)&phl,   g_hl);
    cudaGetSymbolAddress((void**)&pqh,   g_qh);
    cudaGetSymbolAddress((void**)&pql,   g_ql);
    cudaGetSymbolAddress((void**)&poh,   g_oh);
    cudaGetSymbolAddress((void**)&pol,   g_ol);
    cudaGetSymbolAddress((void**)&pf1h,  g_f1h);
    cudaGetSymbolAddress((void**)&pf1l,  g_f1l);

    cudaFuncSetAttribute(flash_kernel, cudaFuncAttributeMaxDynamicSharedMemorySize, FA_SMEM);
    cudaFuncSetAttribute(tgemm_b, cudaFuncAttributeMaxDynamicSharedMemorySize, G_SMEM);

    // ---- one-time weight splits (graph-safe, deterministic) ----
    wsplit_kernel<<<3145728/1024, 256>>>(qkv_w, pwh + WQKV_OFF, pwl + WQKV_OFF, 3145728);
    wsplit_kernel<<<1048576/1024, 256>>>(out_w, pwh + WOUT_OFF, pwl + WOUT_OFF, 1048576);
    wsplit_kernel<<<2097152/1024, 256>>>(ff1_w, pwh + WFF1_OFF, pwl + WFF1_OFF, 2097152);
    wsplit_kernel<<<2097152/1024, 256>>>(ff2_w, pwh + WFF2_OFF, pwl + WFF2_OFF, 2097152);

    fps_kernel<<<48, 512>>>(xyzs);
    ball_kernel<<<(3*NTOK)/4, 128>>>(xyzs);
    conv_kernel<<<NTOK, 128>>>(xyzs, oldf, conv_d_w, conv_f_w, out);
    embed_kernel<<<NTOK, 512>>>(pos_w, pos_b, contr_w, contr_b, out);

    for (int l = 0; l < 4; l++) {
        ln_split_kernel<<<NTOK, 256>>>(px, ln1_s + l*EDIM, ln1_b + l*EDIM, phh, phl);
        // QKV: split output (Q pre-scaled by 1/8)
        tgemm_b<<<dim3(12,48,1), 256, G_SMEM>>>(
            phh, phl, pwh + WQKV_OFF + (size_t)l*1536*512, pwl + WQKV_OFF + (size_t)l*1536*512,
            nullptr, nullptr, pqh, pql,
            512, 512, 512, 1536, 0,0,0, 1,1);
        // fused attention -> o hi/lo
        flash_kernel<<<dim3(LTOK/128, NB*NHEAD), 256, FA_SMEM>>>(pqh, pql, poh, pol);
        // out proj + residual (fp32 out)
        tgemm_b<<<dim3(4,48,1), 256, G_SMEM>>>(
            poh, pol, pwh + WOUT_OFF + (size_t)l*512*512, pwl + WOUT_OFF + (size_t)l*512*512,
            out_b + l*EDIM, px, nullptr, nullptr,
            512, 512, 512, 512, 0,1,1, 0,0);
        ln_split_kernel<<<NTOK, 256>>>(px, ln2_s + l*EDIM, ln2_b + l*EDIM, phh, phl);
        // ff1 + gelu: split output
        tgemm_b<<<dim3(8,48,1), 256, G_SMEM>>>(
            phh, phl, pwh + WFF1_OFF + (size_t)l*1024*512, pwl + WFF1_OFF + (size_t)l*1024*512,
            ff1_b + l*MLPD, nullptr, pf1h, pf1l,
            512, 512, 512, 1024, 1,0,1, 1,0);
        // ff2 + residual (fp32 out)
        tgemm_b<<<dim3(4,48,1), 256, G_SMEM>>>(
            pf1h, pf1l, pwh + WFF2_OFF + (size_t)l*512*1024, pwl + WFF2_OFF + (size_t)l*512*1024,
            ff2_b + l*EDIM, px, nullptr, nullptr,
            1024, 1024, 1024, 512, 0,1,1, 0,0);
    }

    pool_kernel<<<NB, 512>>>();
    ln_kernel<<<NB, 256>>>(ppool, head_ln_s, head_ln_b, phln);
    head1_kernel<<<(NB*MLPD)/8, 256>>>(head1_w, head1_b);
    head2_kernel<<<NB*NCLS/4, 128>>>(head2_w, head2_b, out);
}

// round 8
// speedup vs baseline: 4.5660x; 1.0171x over previous
#include <cuda_runtime.h>
#include <cuda_bf16.h>
#include <cstdint>
#include <math.h>

#define NB 4
#define NT 24
#define NP 4096
#define MM 128
#define TO 12
#define LTOK 1536
#define NTOK 6144
#define EDIM 512
#define NHEAD 8
#define DHEAD 64
#define MLPD 1024
#define NCLS 30
#define KSAMP 32
#define RAD2 0.09f

#define CONTR_OFF 120
#define FEAT_OFF (120 + NTOK*EDIM)

// weight-split buffer offsets (elements)
#define WQKV_OFF 0
#define WOUT_OFF 3145728
#define WFF1_OFF 4194304
#define WFF2_OFF 6291456
#define WTOT     8388608

// ---------------- scratch (device globals; no cudaMalloc allowed) ----------
__device__ __align__(256) float g_anchor[NTOK*3];
__device__ __align__(256) int   g_ball[3*NTOK*KSAMP];
__device__ __align__(256) float g_x[NTOK*EDIM];
__device__ __align__(256) float g_pool[NB*EDIM];
__device__ __align__(256) float g_hln[NB*EDIM];
__device__ __align__(256) float g_h1[NB*MLPD];

__device__ __align__(256) __nv_bfloat16 g_wh[WTOT];
__device__ __align__(256) __nv_bfloat16 g_wl[WTOT];
__device__ __align__(256) __nv_bfloat16 g_hh[NTOK*EDIM];
__device__ __align__(256) __nv_bfloat16 g_hl[NTOK*EDIM];
__device__ __align__(256) __nv_bfloat16 g_qh[NTOK*1536];
__device__ __align__(256) __nv_bfloat16 g_ql[NTOK*1536];
__device__ __align__(256) __nv_bfloat16 g_oh[NTOK*EDIM];
__device__ __align__(256) __nv_bfloat16 g_ol[NTOK*EDIM];
__device__ __align__(256) __nv_bfloat16 g_f1h[NTOK*MLPD];
__device__ __align__(256) __nv_bfloat16 g_f1l[NTOK*MLPD];

__device__ __forceinline__ float gelu_exact(float x){
    return 0.5f*x*(1.0f+erff(x*0.70710678118654752440f));
}

// ==================== PTX helpers ==========================================
__device__ __forceinline__ void mma16816(float* c, const unsigned* a, const unsigned* b){
    asm volatile("mma.sync.aligned.m16n8k16.row.col.f32.bf16.bf16.f32 "
        "{%0,%1,%2,%3}, {%4,%5,%6,%7}, {%8,%9}, {%0,%1,%2,%3};"
        : "+f"(c[0]),"+f"(c[1]),"+f"(c[2]),"+f"(c[3])
        : "r"(a[0]),"r"(a[1]),"r"(a[2]),"r"(a[3]), "r"(b[0]),"r"(b[1]));
}
__device__ __forceinline__ void split2(float x, float y, unsigned& hi, unsigned& lo){
    __nv_bfloat16 hx = __float2bfloat16(x), hy = __float2bfloat16(y);
    float rx = x - __bfloat162float(hx), ry = y - __bfloat162float(hy);
    __nv_bfloat16 lx = __float2bfloat16(rx), ly = __float2bfloat16(ry);
    hi = (unsigned)__bfloat16_as_ushort(hx) | ((unsigned)__bfloat16_as_ushort(hy) << 16);
    lo = (unsigned)__bfloat16_as_ushort(lx) | ((unsigned)__bfloat16_as_ushort(ly) << 16);
}
__device__ __forceinline__ unsigned smem_u32(const void* p){
    unsigned a;
    asm("{ .reg .u64 t; cvta.to.shared.u64 t, %1; cvt.u32.u64 %0, t; }" : "=r"(a) : "l"(p));
    return a;
}
__device__ __forceinline__ void ldmx4(unsigned* r, unsigned addr){
    asm volatile("ldmatrix.sync.aligned.m8n8.x4.shared.b16 {%0,%1,%2,%3}, [%4];"
        : "=r"(r[0]),"=r"(r[1]),"=r"(r[2]),"=r"(r[3]) : "r"(addr));
}
__device__ __forceinline__ void ldmx4t(unsigned* r, unsigned addr){
    asm volatile("ldmatrix.sync.aligned.m8n8.x4.trans.shared.b16 {%0,%1,%2,%3}, [%4];"
        : "=r"(r[0]),"=r"(r[1]),"=r"(r[2]),"=r"(r[3]) : "r"(addr));
}
#define CP16(d, s) asm volatile("cp.async.cg.shared.global [%0], [%1], 16;" :: "r"(d), "l"(s) : "memory")
#define CPC() asm volatile("cp.async.commit_group;" ::: "memory")
#define CPW1() asm volatile("cp.async.wait_group 1;" ::: "memory")
#define CPW0() asm volatile("cp.async.wait_group 0;" ::: "memory")

// ---------------- weight split prep ----------------------------------------
__global__ __launch_bounds__(256) void wsplit_kernel(
    const float* __restrict__ src, __nv_bfloat16* __restrict__ hi,
    __nv_bfloat16* __restrict__ lo, int n)
{
    int i = (blockIdx.x*256 + threadIdx.x)*4;
    if (i < n) {
        float4 v = *(const float4*)(src + i);
        unsigned h0, l0, h1, l1;
        split2(v.x, v.y, h0, l0); split2(v.z, v.w, h1, l1);
        *(unsigned*)(hi+i) = h0; *(unsigned*)(hi+i+2) = h1;
        *(unsigned*)(lo+i) = l0; *(unsigned*)(lo+i+2) = l1;
    }
}

#define LDT 40                       // smem row stride in bf16 (32 + 8 pad)
#define GARR (128*LDT*2)             // 10240 B per 128-row array
#define GSTAGE (4*GARR)              // 40960 B per stage
#define G_SMEM (2*GSTAGE)            // 81920 B

// ============ GEMM BN=128, pre-split bf16, cp.async, ldmatrix ==============
__global__ __launch_bounds__(256) void tgemm_b(
    const __nv_bfloat16* __restrict__ AH_, const __nv_bfloat16* __restrict__ AL_,
    const __nv_bfloat16* __restrict__ WH_, const __nv_bfloat16* __restrict__ WL_,
    const float* __restrict__ bias, float* __restrict__ Cf,
    __nv_bfloat16* __restrict__ CH_, __nv_bfloat16* __restrict__ CL_,
    int K, int lda, int ldw, int ldc,
    int act, int resid, int hasb, int split, int qscale)
{
    extern __shared__ char smem[];
    unsigned sb = smem_u32(smem);

    int tid = threadIdx.x, wid = tid >> 5, lane = tid & 31;
    int g = lane >> 2, tg = lane & 3;
    int q8 = lane >> 3, lr8 = lane & 7;
    int rw = (wid >> 2) * 64, cw = (wid & 3) * 32;
    int bm = blockIdx.y * 128, bn = blockIdx.x * 128;

    float acc[4][4][4];
    #pragma unroll
    for (int i = 0; i < 4; i++)
        #pragma unroll
        for (int j = 0; j < 4; j++)
            #pragma unroll
            for (int p = 0; p < 4; p++) acc[i][j][p] = 0.f;

    int row = tid >> 1, half = tid & 1;
    int nch = K >> 5;

    {
        unsigned dst = sb + (row*LDT + half*16)*2;
        const __nv_bfloat16* a = AH_ + (size_t)(bm+row)*lda + half*16;
        const __nv_bfloat16* a2 = AL_ + (size_t)(bm+row)*lda + half*16;
        const __nv_bfloat16* w = WH_ + (size_t)(bn+row)*ldw + half*16;
        const __nv_bfloat16* w2 = WL_ + (size_t)(bn+row)*ldw + half*16;
        CP16(dst, a); CP16(dst+16, a+8);
        CP16(dst+GARR, a2); CP16(dst+GARR+16, a2+8);
        CP16(dst+2*GARR, w); CP16(dst+2*GARR+16, w+8);
        CP16(dst+3*GARR, w2); CP16(dst+3*GARR+16, w2+8);
        CPC();
    }

    for (int c = 0; c < nch; c++) {
        if (c + 1 < nch) {
            unsigned dst = sb + ((c+1)&1)*GSTAGE + (row*LDT + half*16)*2;
            const __nv_bfloat16* a = AH_ + (size_t)(bm+row)*lda + (c+1)*32 + half*16;
            const __nv_bfloat16* a2 = AL_ + (size_t)(bm+row)*lda + (c+1)*32 + half*16;
            const __nv_bfloat16* w = WH_ + (size_t)(bn+row)*ldw + (c+1)*32 + half*16;
            const __nv_bfloat16* w2 = WL_ + (size_t)(bn+row)*ldw + (c+1)*32 + half*16;
            CP16(dst, a); CP16(dst+16, a+8);
            CP16(dst+GARR, a2); CP16(dst+GARR+16, a2+8);
            CP16(dst+2*GARR, w); CP16(dst+2*GARR+16, w+8);
            CP16(dst+3*GARR, w2); CP16(dst+3*GARR+16, w2+8);
            CPC();
            CPW1();
        } else {
            CPW0();
        }
        __syncthreads();
        unsigned sAH = sb + (c&1)*GSTAGE;
        unsigned sAL = sAH + GARR;
        unsigned sWH = sAH + 2*GARR;
        unsigned sWL = sAH + 3*GARR;
        #pragma unroll
        for (int ks = 0; ks < 2; ks++) {
            int k0 = ks * 16;
            unsigned ah[4][4], al[4][4], bh[2][4], bl[2][4];
            #pragma unroll
            for (int mt = 0; mt < 4; mt++) {
                unsigned off = (unsigned)((rw + mt*16 + (q8&1)*8 + lr8)*LDT + k0 + (q8>>1)*8)*2;
                ldmx4(ah[mt], sAH + off);
                ldmx4(al[mt], sAL + off);
            }
            #pragma unroll
            for (int ntp = 0; ntp < 2; ntp++) {
                unsigned off = (unsigned)((cw + ntp*16 + (q8>>1)*8 + lr8)*LDT + k0 + (q8&1)*8)*2;
                ldmx4(bh[ntp], sWH + off);
                ldmx4(bl[ntp], sWL + off);
            }
            #pragma unroll
            for (int mt = 0; mt < 4; mt++)
                #pragma unroll
                for (int nt = 0; nt < 4; nt++) {
                    const unsigned* ph = &bh[nt>>1][(nt&1)*2];
                    const unsigned* pl = &bl[nt>>1][(nt&1)*2];
                    mma16816(acc[mt][nt], ah[mt], ph);
                    mma16816(acc[mt][nt], ah[mt], pl);
                    mma16816(acc[mt][nt], al[mt], ph);
                }
        }
        __syncthreads();
    }
    #pragma unroll
    for (int mt = 0; mt < 4; mt++) {
        #pragma unroll
        for (int nt = 0; nt < 4; nt++) {
            int r0 = bm + rw + mt*16 + g;
            int col = bn + cw + nt*8 + tg*2;
            #pragma unroll
            for (int half2 = 0; half2 < 2; half2++) {
                int r = r0 + half2*8;
                float v0 = acc[mt][nt][half2*2+0];
                float v1 = acc[mt][nt][half2*2+1];
                if (hasb) { v0 += bias[col]; v1 += bias[col+1]; }
                if (act)  { v0 = gelu_exact(v0); v1 = gelu_exact(v1); }
                if (split) {
                    if (qscale && col < 512) { v0 *= 0.125f; v1 *= 0.125f; }
                    unsigned hh, ll;
                    split2(v0, v1, hh, ll);
                    *(unsigned*)(CH_ + (size_t)r*ldc + col) = hh;
                    *(unsigned*)(CL_ + (size_t)r*ldc + col) = ll;
                } else {
                    float* cp = Cf + (size_t)r * ldc + col;
                    if (resid) {
                        float2 old = *(float2*)cp;
                        v0 += old.x; v1 += old.y;
                    }
                    float2 ov = {v0, v1};
                    *(float2*)cp = ov;
                }
            }
        }
    }
}

// ============ GEMM BN=64 (better wave fill for narrow N) ===================
#define G64_WARR (64*LDT*2)              // 5120 B
#define G64_STAGE (2*GARR + 2*G64_WARR)  // 30720 B
#define G64_SMEM (2*G64_STAGE)           // 61440 B

__global__ __launch_bounds__(256) void tgemm_b64(
    const __nv_bfloat16* __restrict__ AH_, const __nv_bfloat16* __restrict__ AL_,
    const __nv_bfloat16* __restrict__ WH_, const __nv_bfloat16* __restrict__ WL_,
    const float* __restrict__ bias, float* __restrict__ Cf,
    __nv_bfloat16* __restrict__ CH_, __nv_bfloat16* __restrict__ CL_,
    int K, int lda, int ldw, int ldc,
    int act, int resid, int hasb, int split)
{
    extern __shared__ char smem[];
    unsigned sb = smem_u32(smem);

    int tid = threadIdx.x, wid = tid >> 5, lane = tid & 31;
    int g = lane >> 2, tg = lane & 3;
    int q8 = lane >> 3, lr8 = lane & 7;
    int rw = (wid >> 2) * 64, cw = (wid & 3) * 16;
    int bm = blockIdx.y * 128, bn = blockIdx.x * 64;

    float acc[4][2][4];
    #pragma unroll
    for (int i = 0; i < 4; i++)
        #pragma unroll
        for (int j = 0; j < 2; j++)
            #pragma unroll
            for (int p = 0; p < 4; p++) acc[i][j][p] = 0.f;

    int row = tid >> 1, half = tid & 1;        // A load map: 128 rows x 32 cols
    int roww = tid >> 2, colq = (tid & 3) * 8; // W load map: 64 rows x 32 cols
    int nch = K >> 5;

    {
        unsigned dstA = sb + (row*LDT + half*16)*2;
        const __nv_bfloat16* a = AH_ + (size_t)(bm+row)*lda + half*16;
        const __nv_bfloat16* a2 = AL_ + (size_t)(bm+row)*lda + half*16;
        CP16(dstA, a); CP16(dstA+16, a+8);
        CP16(dstA+GARR, a2); CP16(dstA+GARR+16, a2+8);
        unsigned dstW = sb + 2*GARR + (roww*LDT + colq)*2;
        const __nv_bfloat16* w = WH_ + (size_t)(bn+roww)*ldw + colq;
        const __nv_bfloat16* w2 = WL_ + (size_t)(bn+roww)*ldw + colq;
        CP16(dstW, w);
        CP16(dstW+G64_WARR, w2);
        CPC();
    }

    for (int c = 0; c < nch; c++) {
        if (c + 1 < nch) {
            unsigned st = ((c+1)&1)*G64_STAGE;
            unsigned dstA = sb + st + (row*LDT + half*16)*2;
            const __nv_bfloat16* a = AH_ + (size_t)(bm+row)*lda + (c+1)*32 + half*16;
            const __nv_bfloat16* a2 = AL_ + (size_t)(bm+row)*lda + (c+1)*32 + half*16;
            CP16(dstA, a); CP16(dstA+16, a+8);
            CP16(dstA+GARR, a2); CP16(dstA+GARR+16, a2+8);
            unsigned dstW = sb + st + 2*GARR + (roww*LDT + colq)*2;
            const __nv_bfloat16* w = WH_ + (size_t)(bn+roww)*ldw + (c+1)*32 + colq;
            const __nv_bfloat16* w2 = WL_ + (size_t)(bn+roww)*ldw + (c+1)*32 + colq;
            CP16(dstW, w);
            CP16(dstW+G64_WARR, w2);
            CPC();
            CPW1();
        } else {
            CPW0();
        }
        __syncthreads();
        unsigned sAH = sb + (c&1)*G64_STAGE;
        unsigned sAL = sAH + GARR;
        unsigned sWH = sAH + 2*GARR;
        unsigned sWL = sWH + G64_WARR;
        #pragma unroll
        for (int ks = 0; ks < 2; ks++) {
            int k0 = ks * 16;
            unsigned ah[4][4], al[4][4], bh4[4], bl4[4];
            #pragma unroll
            for (int mt = 0; mt < 4; mt++) {
                unsigned off = (unsigned)((rw + mt*16 + (q8&1)*8 + lr8)*LDT + k0 + (q8>>1)*8)*2;
                ldmx4(ah[mt], sAH + off);
                ldmx4(al[mt], sAL + off);
            }
            {
                unsigned off = (unsigned)((cw + (q8>>1)*8 + lr8)*LDT + k0 + (q8&1)*8)*2;
                ldmx4(bh4, sWH + off);
                ldmx4(bl4, sWL + off);
            }
            #pragma unroll
            for (int mt = 0; mt < 4; mt++)
                #pragma unroll
                for (int nt = 0; nt < 2; nt++) {
                    mma16816(acc[mt][nt], ah[mt], bh4 + nt*2);
                    mma16816(acc[mt][nt], ah[mt], bl4 + nt*2);
                    mma16816(acc[mt][nt], al[mt], bh4 + nt*2);
                }
        }
        __syncthreads();
    }
    #pragma unroll
    for (int mt = 0; mt < 4; mt++) {
        #pragma unroll
        for (int nt = 0; nt < 2; nt++) {
            int r0 = bm + rw + mt*16 + g;
            int col = bn + cw + nt*8 + tg*2;
            #pragma unroll
            for (int half2 = 0; half2 < 2; half2++) {
                int r = r0 + half2*8;
                float v0 = acc[mt][nt][half2*2+0];
                float v1 = acc[mt][nt][half2*2+1];
                if (hasb) { v0 += bias[col]; v1 += bias[col+1]; }
                if (act)  { v0 = gelu_exact(v0); v1 = gelu_exact(v1); }
                if (split) {
                    unsigned hh, ll;
                    split2(v0, v1, hh, ll);
                    *(unsigned*)(CH_ + (size_t)r*ldc + col) = hh;
                    *(unsigned*)(CL_ + (size_t)r*ldc + col) = ll;
                } else {
                    float* cp = Cf + (size_t)r * ldc + col;
                    if (resid) {
                        float2 old = *(float2*)cp;
                        v0 += old.x; v1 += old.y;
                    }
                    float2 ov = {v0, v1};
                    *(float2*)cp = ov;
                }
            }
        }
    }
}

// ==================== flash attention (pre-split bf16, ldmatrix, cp.async) =
#define FQS 72
#define FARR (128*FQS*2)             // 18432 B
#define FQH 0
#define FQL FARR
#define FST(s) (2*FARR + (s)*4*FARR)
#define FA_SMEM (2*FARR + 2*4*FARR)  // 184320 B

__global__ __launch_bounds__(256) void flash_kernel(
    const __nv_bfloat16* __restrict__ qh, const __nv_bfloat16* __restrict__ ql,
    __nv_bfloat16* __restrict__ oh, __nv_bfloat16* __restrict__ ol)
{
    extern __shared__ char fsm[];
    unsigned sb = smem_u32(fsm);

    int tid = threadIdx.x, wid = tid >> 5, lane = tid & 31;
    int g = lane >> 2, tg = lane & 3;
    int q8 = lane >> 3, lr8 = lane & 7;
    int z = blockIdx.y;
    int b = z >> 3, h = z & 7;
    size_t base = (size_t)b * LTOK * 1536;
    int q0 = blockIdx.x * 128;

    int row = tid >> 1, half = tid & 1;

    {
        unsigned dq = sb + (row*FQS + half*32)*2;
        const __nv_bfloat16* sq = qh + base + (size_t)(q0+row)*1536 + h*64 + half*32;
        const __nv_bfloat16* sq2 = ql + base + (size_t)(q0+row)*1536 + h*64 + half*32;
        #pragma unroll
        for (int j = 0; j < 4; j++) {
            CP16(dq + j*16, sq + j*8);
            CP16(dq + FARR + j*16, sq2 + j*8);
        }
        unsigned dk = sb + FST(0) + (row*FQS + half*32)*2;
        const __nv_bfloat16* sk = qh + base + (size_t)row*1536 + 512 + h*64 + half*32;
        const __nv_bfloat16* sk2 = ql + base + (size_t)row*1536 + 512 + h*64 + half*32;
        const __nv_bfloat16* sv = qh + base + (size_t)row*1536 + 1024 + h*64 + half*32;
        const __nv_bfloat16* sv2 = ql + base + (size_t)row*1536 + 1024 + h*64 + half*32;
        #pragma unroll
        for (int j = 0; j < 4; j++) {
            CP16(dk + j*16, sk + j*8);
            CP16(dk + FARR + j*16, sk2 + j*8);
            CP16(dk + 2*FARR + j*16, sv + j*8);
            CP16(dk + 3*FARR + j*16, sv2 + j*8);
        }
        CPC();
    }

    float acco[8][4];
    #pragma unroll
    for (int i = 0; i < 8; i++)
        #pragma unroll
        for (int p = 0; p < 4; p++) acco[i][p] = 0.f;
    float m0 = -3.402823466e38f, m1 = -3.402823466e38f, l0s = 0.f, l1s = 0.f;

    for (int t = 0; t < LTOK/128; t++) {
        if (t + 1 < LTOK/128) {
            unsigned dk = sb + FST((t+1)&1) + (row*FQS + half*32)*2;
            size_t ro = base + (size_t)((t+1)*128+row)*1536 + h*64 + half*32;
            const __nv_bfloat16* sk = qh + ro + 512;
            const __nv_bfloat16* sk2 = ql + ro + 512;
            const __nv_bfloat16* sv = qh + ro + 1024;
            const __nv_bfloat16* sv2 = ql + ro + 1024;
            #pragma unroll
            for (int j = 0; j < 4; j++) {
                CP16(dk + j*16, sk + j*8);
                CP16(dk + FARR + j*16, sk2 + j*8);
                CP16(dk + 2*FARR + j*16, sv + j*8);
                CP16(dk + 3*FARR + j*16, sv2 + j*8);
            }
            CPC();
            CPW1();
        } else {
            CPW0();
        }
        __syncthreads();
        unsigned sKH = sb + FST(t&1);
        unsigned sKL = sKH + FARR;
        unsigned sVH = sKH + 2*FARR;
        unsigned sVL = sKH + 3*FARR;

        float accs[16][4];
        #pragma unroll
        for (int nt = 0; nt < 16; nt++)
            #pragma unroll
            for (int p = 0; p < 4; p++) accs[nt][p] = 0.f;
        #pragma unroll
        for (int ks = 0; ks < 4; ks++) {
            int k0 = ks*16;
            unsigned aqh[4], aql[4];
            unsigned aoff = (unsigned)((wid*16 + (q8&1)*8 + lr8)*FQS + k0 + (q8>>1)*8)*2;
            ldmx4(aqh, sb + FQH + aoff);
            ldmx4(aql, sb + FQL + aoff);
            #pragma unroll
            for (int ntp = 0; ntp < 8; ntp++) {
                unsigned boff = (unsigned)((ntp*16 + (q8>>1)*8 + lr8)*FQS + k0 + (q8&1)*8)*2;
                unsigned bh4[4], bl4[4];
                ldmx4(bh4, sKH + boff);
                ldmx4(bl4, sKL + boff);
                mma16816(accs[2*ntp],   aqh, bh4);
                mma16816(accs[2*ntp],   aqh, bl4);
                mma16816(accs[2*ntp],   aql, bh4);
                mma16816(accs[2*ntp+1], aqh, bh4+2);
                mma16816(accs[2*ntp+1], aqh, bl4+2);
                mma16816(accs[2*ntp+1], aql, bh4+2);
            }
        }

        float mx0 = -3.402823466e38f, mx1 = -3.402823466e38f;
        #pragma unroll
        for (int nt = 0; nt < 16; nt++) {
            mx0 = fmaxf(mx0, fmaxf(accs[nt][0], accs[nt][1]));
            mx1 = fmaxf(mx1, fmaxf(accs[nt][2], accs[nt][3]));
        }
        mx0 = fmaxf(mx0, __shfl_xor_sync(0xffffffffu, mx0, 1));
        mx0 = fmaxf(mx0, __shfl_xor_sync(0xffffffffu, mx0, 2));
        mx1 = fmaxf(mx1, __shfl_xor_sync(0xffffffffu, mx1, 1));
        mx1 = fmaxf(mx1, __shfl_xor_sync(0xffffffffu, mx1, 2));
        float mn0 = fmaxf(m0, mx0), mn1 = fmaxf(m1, mx1);
        float c0 = __expf(m0 - mn0), c1 = __expf(m1 - mn1);
        float s0 = 0.f, s1 = 0.f;
        #pragma unroll
        for (int nt = 0; nt < 16; nt++) {
            accs[nt][0] = __expf(accs[nt][0] - mn0);
            accs[nt][1] = __expf(accs[nt][1] - mn0);
            accs[nt][2] = __expf(accs[nt][2] - mn1);
            accs[nt][3] = __expf(accs[nt][3] - mn1);
            s0 += accs[nt][0] + accs[nt][1];
            s1 += accs[nt][2] + accs[nt][3];
        }
        s0 += __shfl_xor_sync(0xffffffffu, s0, 1);
        s0 += __shfl_xor_sync(0xffffffffu, s0, 2);
        s1 += __shfl_xor_sync(0xffffffffu, s1, 1);
        s1 += __shfl_xor_sync(0xffffffffu, s1, 2);
        l0s = l0s * c0 + s0;
        l1s = l1s * c1 + s1;
        m0 = mn0; m1 = mn1;
        #pragma unroll
        for (int i = 0; i < 8; i++) {
            acco[i][0] *= c0; acco[i][1] *= c0;
            acco[i][2] *= c1; acco[i][3] *= c1;
        }

        #pragma unroll
        for (int pks = 0; pks < 8; pks++) {
            unsigned aph[4], apl[4];
            split2(accs[2*pks][0],   accs[2*pks][1],   aph[0], apl[0]);
            split2(accs[2*pks][2],   accs[2*pks][3],   aph[1], apl[1]);
            split2(accs[2*pks+1][0], accs[2*pks+1][1], aph[2], apl[2]);
            split2(accs[2*pks+1][2], accs[2*pks+1][3], aph[3], apl[3]);
            #pragma unroll
            for (int ntp2 = 0; ntp2 < 4; ntp2++) {
                unsigned voff = (unsigned)((pks*16 + (q8&1)*8 + lr8)*FQS + ntp2*16 + (q8>>1)*8)*2;
                unsigned bvh[4], bvl[4];
                ldmx4t(bvh, sVH + voff);
                ldmx4t(bvl, sVL + voff);
                mma16816(acco[2*ntp2],   aph, bvh);
                mma16816(acco[2*ntp2],   aph, bvl);
                mma16816(acco[2*ntp2],   apl, bvh);
                mma16816(acco[2*ntp2+1], aph, bvh+2);
                mma16816(acco[2*ntp2+1], aph, bvl+2);
                mma16816(acco[2*ntp2+1], apl, bvh+2);
            }
        }
        __syncthreads();
    }

    float inv0 = 1.0f / l0s, inv1 = 1.0f / l1s;
    int orow = q0 + wid*16 + g;
    #pragma unroll
    for (int nt2 = 0; nt2 < 8; nt2++) {
        int col = h*64 + nt2*8 + tg*2;
        unsigned hh, ll;
        split2(acco[nt2][0]*inv0, acco[nt2][1]*inv0, hh, ll);
        *(unsigned*)(oh + (size_t)(b*LTOK + orow) * EDIM + col) = hh;
        *(unsigned*)(ol + (size_t)(b*LTOK + orow) * EDIM + col) = ll;
        split2(acco[nt2][2]*inv1, acco[nt2][3]*inv1, hh, ll);
        *(unsigned*)(oh + (size_t)(b*LTOK + orow + 8) * EDIM + col) = hh;
        *(unsigned*)(ol + (size_t)(b*LTOK + orow + 8) * EDIM + col) = ll;
    }
}

// ---------------- FPS -------------------------------------------------------
__global__ __launch_bounds__(512) void fps_kernel(const float* __restrict__ xyzs) {
    int blk = blockIdx.x;
    int b = blk / TO, j = blk % TO;
    const float* P = xyzs + (size_t)(b*NT + 2*j)*NP*3;
    int tid = threadIdx.x;
    float px[8], py[8], pz[8], dist[8];
    #pragma unroll
    for (int i = 0; i < 8; i++) {
        int p = tid + i*512;
        px[i] = P[p*3+0]; py[i] = P[p*3+1]; pz[i] = P[p*3+2];
        dist[i] = 1e10f;
    }
    __shared__ float sbx, sby, sbz;
    __shared__ float swv[16];
    __shared__ int   swi[16];
    float* anch = g_anchor + (size_t)blk*MM*3;
    if (tid == 0) {
        sbx = P[0]; sby = P[1]; sbz = P[2];
        anch[0] = P[0]; anch[1] = P[1]; anch[2] = P[2];
    }
    __syncthreads();
    for (int s = 1; s < MM; s++) {
        float bx = sbx, by = sby, bz = sbz;
        float bestv = -1.0f; int besti = 0x7fffffff;
        #pragma unroll
        for (int i = 0; i < 8; i++) {
            float dx = __fsub_rn(px[i], bx);
            float dy = __fsub_rn(py[i], by);
            float dz = __fsub_rn(pz[i], bz);
            float d = __fadd_rn(__fadd_rn(__fmul_rn(dx,dx), __fmul_rn(dy,dy)), __fmul_rn(dz,dz));
            float nd = fminf(dist[i], d);
            dist[i] = nd;
            int p = tid + i*512;
            if (nd > bestv || (nd == bestv && p < besti)) { bestv = nd; besti = p; }
        }
        #pragma unroll
        for (int off = 16; off; off >>= 1) {
            float ov = __shfl_down_sync(0xffffffffu, bestv, off);
            int   oi = __shfl_down_sync(0xffffffffu, besti, off);
            if (ov > bestv || (ov == bestv && oi < besti)) { bestv = ov; besti = oi; }
        }
        if ((tid & 31) == 0) { swv[tid>>5] = bestv; swi[tid>>5] = besti; }
        __syncthreads();
        if (tid == 0) {
            float v = swv[0]; int ii = swi[0];
            #pragma unroll
            for (int w = 1; w < 16; w++)
                if (swv[w] > v || (swv[w] == v && swi[w] < ii)) { v = swv[w]; ii = swi[w]; }
            float x0 = P[ii*3+0], y0 = P[ii*3+1], z0 = P[ii*3+2];
            sbx = x0; sby = y0; sbz = z0;
            anch[s*3+0] = x0; anch[s*3+1] = y0; anch[s*3+2] = z0;
        }
        __syncthreads();
    }
}

// ---------------- Ball query ------------------------------------------------
__global__ __launch_bounds__(128) void ball_kernel(const float* __restrict__ xyzs) {
    int w = blockIdx.x*4 + (threadIdx.x >> 5);
    int lane = threadIdx.x & 31;
    int o = w / NTOK;
    int tok = w % NTOK;
    int b = tok / LTOK, loc = tok % LTOK, j = loc / MM;
    int pf = 2*j + o;
    int of = (pf == 0) ? 0 : (pf - 1);
    const float* P = xyzs + (size_t)(b*NT + of)*NP*3;
    float ax = g_anchor[tok*3+0], ay = g_anchor[tok*3+1], az = g_anchor[tok*3+2];
    int* out = g_ball + ((size_t)o*NTOK + tok)*KSAMP;
    int cnt = 0, first = 0; bool found = false;
    for (int base = 0; base < NP; base += 32) {
        int p = base + lane;
        float x = P[p*3+0], y = P[p*3+1], z = P[p*3+2];
        float dx = __fsub_rn(ax,x), dy = __fsub_rn(ay,y), dz = __fsub_rn(az,z);
        float d2 = __fadd_rn(__fadd_rn(__fmul_rn(dx,dx), __fmul_rn(dy,dy)), __fmul_rn(dz,dz));
        bool inside = d2 < RAD2;
        unsigned msk = __ballot_sync(0xffffffffu, inside);
        if (!found && msk) { first = base + __ffs(msk) - 1; found = true; }
        int pos = cnt + __popc(msk & ((1u << lane) - 1u));
        if (inside && pos < KSAMP) out[pos] = p;
        cnt += __popc(msk);
        if (cnt >= KSAMP) break;
    }
    if (lane >= cnt) out[lane] = found ? first : 0;
}

// ---------------- grouped conv + max pool ----------------------------------
__global__ __launch_bounds__(128) void conv_kernel(
    const float* __restrict__ xyzs, const float* __restrict__ oldf,
    const float* __restrict__ Wd, const float* __restrict__ Wf,
    float* __restrict__ dout)
{
    int tok = blockIdx.x;
    int b = tok / LTOK, loc = tok % LTOK, j = loc / MM;
    int tid = threadIdx.x;
    __shared__ float sd[KSAMP][4];
    __shared__ float sf[KSAMP][2];
    float ax = g_anchor[tok*3+0], ay = g_anchor[tok*3+1], az = g_anchor[tok*3+2];
    float wd[4][4], wf[4][2], vmax[4];
    #pragma unroll
    for (int r = 0; r < 4; r++) {
        int d = tid + 128*r;
        wd[r][0] = Wd[d*4+0]; wd[r][1] = Wd[d*4+1]; wd[r][2] = Wd[d*4+2]; wd[r][3] = Wd[d*4+3];
        wf[r][0] = Wf[d*2+0]; wf[r][1] = Wf[d*2+1];
        vmax[r] = -3.402823466e38f;
    }
    for (int o = 0; o < 3; o++) {
        int pf = 2*j + o;
        int of = (pf == 0) ? 0 : (pf - 1);
        const float* P = xyzs + (size_t)(b*NT + of)*NP*3;
        const float* F = oldf + (size_t)(b*NT + of)*2*NP;
        __syncthreads();
        if (tid < KSAMP) {
            int idx = g_ball[((size_t)o*NTOK + tok)*KSAMP + tid];
            sd[tid][0] = P[idx*3+0] - ax;
            sd[tid][1] = P[idx*3+1] - ay;
            sd[tid][2] = P[idx*3+2] - az;
            sd[tid][3] = (float)(o - 1);
            sf[tid][0] = F[idx];
            sf[tid][1] = F[NP + idx];
        }
        __syncthreads();
        #pragma unroll 4
        for (int k = 0; k < KSAMP; k++) {
            float d0 = sd[k][0], d1 = sd[k][1], d2 = sd[k][2], d3 = sd[k][3];
            float f0 = sf[k][0], f1 = sf[k][1];
            #pragma unroll
            for (int r = 0; r < 4; r++) {
                float de = wd[r][0]*d0 + wd[r][1]*d1 + wd[r][2]*d2 + wd[r][3]*d3;
                float fe = wf[r][0]*f0 + wf[r][1]*f1;
                vmax[r] = fmaxf(vmax[r], de*fe);
            }
        }
    }
    #pragma unroll
    for (int r = 0; r < 4; r++)
        dout[FEAT_OFF + (size_t)tok*EDIM + tid + 128*r] = vmax[r];
}

// ---------------- pos + contrastive + relu(pos+feat) -----------------------
__global__ __launch_bounds__(512) void embed_kernel(
    const float* __restrict__ pw, const float* __restrict__ pb,
    const float* __restrict__ cw, const float* __restrict__ cb,
    float* __restrict__ dout)
{
    int tok = blockIdx.x;
    int d = threadIdx.x;
    int loc = tok % LTOK, j = loc / MM;
    float ax = g_anchor[tok*3+0], ay = g_anchor[tok*3+1], az = g_anchor[tok*3+2];
    float tv = (float)(j + 1);
    float pos = pw[d*4+0]*ax + pw[d*4+1]*ay + pw[d*4+2]*az + pw[d*4+3]*tv + pb[d];
    float con = cw[d*4+0]*ax + cw[d*4+1]*ay + cw[d*4+2]*az + cw[d*4+3]*tv + cb[d];
    dout[CONTR_OFF + (size_t)tok*EDIM + d] = con;
    float feat = dout[FEAT_OFF + (size_t)tok*EDIM + d];
    g_x[(size_t)tok*EDIM + d] = fmaxf(pos + feat, 0.0f);
}

// ---------------- LayerNorm -> bf16 hi/lo ----------------------------------
__global__ __launch_bounds__(256) void ln_split_kernel(
    const float* __restrict__ x, const float* __restrict__ s,
    const float* __restrict__ bb,
    __nv_bfloat16* __restrict__ outh, __nv_bfloat16* __restrict__ outl)
{
    int tok = blockIdx.x;
    int tid = threadIdx.x;
    const float* row = x + (size_t)tok*EDIM;
    float v0 = row[tid], v1 = row[tid + 256];
    float sum = v0 + v1, sq = v0*v0 + v1*v1;
    #pragma unroll
    for (int off = 16; off; off >>= 1) {
        sum += __shfl_xor_sync(0xffffffffu, sum, off);
        sq  += __shfl_xor_sync(0xffffffffu, sq, off);
    }
    __shared__ float ssum[8], ssq[8];
    if ((tid & 31) == 0) { ssum[tid>>5] = sum; ssq[tid>>5] = sq; }
    __syncthreads();
    float ts = 0.f, tq = 0.f;
    #pragma unroll
    for (int w = 0; w < 8; w++) { ts += ssum[w]; tq += ssq[w]; }
    float mu = ts * (1.0f/512.0f);
    float var = tq * (1.0f/512.0f) - mu*mu;
    float rstd = rsqrtf(var + 1e-5f);
    float y0 = (v0 - mu)*rstd*s[tid] + bb[tid];
    float y1 = (v1 - mu)*rstd*s[tid+256] + bb[tid+256];
    __nv_bfloat16 h0 = __float2bfloat16(y0);
    __nv_bfloat16 h1 = __float2bfloat16(y1);
    outh[(size_t)tok*EDIM + tid]       = h0;
    outh[(size_t)tok*EDIM + tid + 256] = h1;
    outl[(size_t)tok*EDIM + tid]       = __float2bfloat16(y0 - __bfloat162float(h0));
    outl[(size_t)tok*EDIM + tid + 256] = __float2bfloat16(y1 - __bfloat162float(h1));
}

// ---------------- fp32 LayerNorm (head) ------------------------------------
__global__ __launch_bounds__(256) void ln_kernel(
    const float* __restrict__ x, const float* __restrict__ s,
    const float* __restrict__ bb, float* __restrict__ out)
{
    int tok = blockIdx.x;
    int tid = threadIdx.x;
    const float* row = x + (size_t)tok*EDIM;
    float v0 = row[tid], v1 = row[tid + 256];
    float sum = v0 + v1, sq = v0*v0 + v1*v1;
    #pragma unroll
    for (int off = 16; off; off >>= 1) {
        sum += __shfl_xor_sync(0xffffffffu, sum, off);
        sq  += __shfl_xor_sync(0xffffffffu, sq, off);
    }
    __shared__ float ssum[8], ssq[8];
    if ((tid & 31) == 0) { ssum[tid>>5] = sum; ssq[tid>>5] = sq; }
    __syncthreads();
    float ts = 0.f, tq = 0.f;
    #pragma unroll
    for (int w = 0; w < 8; w++) { ts += ssum[w]; tq += ssq[w]; }
    float mu = ts * (1.0f/512.0f);
    float var = tq * (1.0f/512.0f) - mu*mu;
    float rstd = rsqrtf(var + 1e-5f);
    out[(size_t)tok*EDIM + tid]       = (v0 - mu)*rstd*s[tid] + bb[tid];
    out[(size_t)tok*EDIM + tid + 256] = (v1 - mu)*rstd*s[tid+256] + bb[tid+256];
}

// ---------------- head ------------------------------------------------------
__global__ __launch_bounds__(512) void pool_kernel() {
    int b = blockIdx.x;
    int d = threadIdx.x;
    float v = -3.402823466e38f;
    const float* p = g_x + (size_t)b*LTOK*EDIM + d;
    for (int i = 0; i < LTOK; i++) v = fmaxf(v, p[(size_t)i*EDIM]);
    g_pool[b*EDIM + d] = v;
}
__global__ __launch_bounds__(256) void head1_kernel(
    const float* __restrict__ W, const float* __restrict__ bias)
{
    int out = blockIdx.x*8 + (threadIdx.x >> 5);
    int lane = threadIdx.x & 31;
    int b = out >> 10, jj = out & 1023;
    const float* xr = g_hln + b*EDIM;
    const float* wr = W + (size_t)jj*EDIM;
    float s = 0.f;
    for (int d = lane; d < EDIM; d += 32) s += xr[d]*wr[d];
    #pragma unroll
    for (int off = 16; off; off >>= 1) s += __shfl_xor_sync(0xffffffffu, s, off);
    if (lane == 0) g_h1[out] = gelu_exact(s + bias[jj]);
}
__global__ __launch_bounds__(128) void head2_kernel(
    const float* __restrict__ W, const float* __restrict__ bias,
    float* __restrict__ dout)
{
    int out = blockIdx.x*4 + (threadIdx.x >> 5);
    int lane = threadIdx.x & 31;
    int b = out / NCLS, c = out % NCLS;
    float s = 0.f;
    for (int d = lane; d < MLPD; d += 32) s += g_h1[b*MLPD + d]*W[(size_t)c*MLPD + d];
    #pragma unroll
    for (int off = 16; off; off >>= 1) s += __shfl_xor_sync(0xffffffffu, s, off);
    if (lane == 0) dout[out] = s + bias[c];
}

// ---------------- launch ---------------------------------------------------
extern "C" void kernel_launch(void* const* d_in, const int* in_sizes, int n_in,
                              void* d_out, int out_size) {
    const float* xyzs      = (const float*)d_in[0];
    const float* oldf      = (const float*)d_in[1];
    const float* conv_d_w  = (const float*)d_in[2];
    const float* conv_f_w  = (const float*)d_in[3];
    const float* pos_w     = (const float*)d_in[4];
    const float* pos_b     = (const float*)d_in[5];
    const float* contr_w   = (const float*)d_in[6];
    const float* contr_b   = (const float*)d_in[7];
    const float* ln1_s     = (const float*)d_in[8];
    const float* ln1_b     = (const float*)d_in[9];
    const float* qkv_w     = (const float*)d_in[10];
    const float* out_w     = (const float*)d_in[11];
    const float* out_b     = (const float*)d_in[12];
    const float* ln2_s     = (const float*)d_in[13];
    const float* ln2_b     = (const float*)d_in[14];
    const float* ff1_w     = (const float*)d_in[15];
    const float* ff1_b     = (const float*)d_in[16];
    const float* ff2_w     = (const float*)d_in[17];
    const float* ff2_b     = (const float*)d_in[18];
    const float* head_ln_s = (const float*)d_in[19];
    const float* head_ln_b = (const float*)d_in[20];
    const float* head1_w   = (const float*)d_in[21];
    const float* head1_b   = (const float*)d_in[22];
    const float* head2_w   = (const float*)d_in[23];
    const float* head2_b   = (const float*)d_in[24];
    float* out = (float*)d_out;

    float *px, *ppool, *phln;
    __nv_bfloat16 *pwh, *pwl, *phh, *phl, *pqh, *pql, *poh, *pol, *pf1h, *pf1l;
    cudaGetSymbolAddress((void**)&px,    g_x);
    cudaGetSymbolAddress((void**)&ppool, g_pool);
    cudaGetSymbolAddress((void**)&phln,  g_hln);
    cudaGetSymbolAddress((void**)&pwh,   g_wh);
    cudaGetSymbolAddress((void**)&pwl,   g_wl);
    cudaGetSymbolAddress((void**)&phh,   g_hh);
    cudaGetSymbolAddress((void**)&phl,   g_hl);
    cudaGetSymbolAddress((void**)&pqh,   g_qh);
    cudaGetSymbolAddress((void**)&pql,   g_ql);
    cudaGetSymbolAddress((void**)&poh,   g_oh);
    cudaGetSymbolAddress((void**)&pol,   g_ol);
    cudaGetSymbolAddress((void**)&pf1h,  g_f1h);
    cudaGetSymbolAddress((void**)&pf1l,  g_f1l);

    cudaFuncSetAttribute(flash_kernel, cudaFuncAttributeMaxDynamicSharedMemorySize, FA_SMEM);
    cudaFuncSetAttribute(tgemm_b, cudaFuncAttributeMaxDynamicSharedMemorySize, G_SMEM);
    cudaFuncSetAttribute(tgemm_b64, cudaFuncAttributeMaxDynamicSharedMemorySize, G64_SMEM);

    // ---- one-time weight splits (graph-safe, deterministic) ----
    wsplit_kernel<<<3145728/1024, 256>>>(qkv_w, pwh + WQKV_OFF, pwl + WQKV_OFF, 3145728);
    wsplit_kernel<<<1048576/1024, 256>>>(out_w, pwh + WOUT_OFF, pwl + WOUT_OFF, 1048576);
    wsplit_kernel<<<2097152/1024, 256>>>(ff1_w, pwh + WFF1_OFF, pwl + WFF1_OFF, 2097152);
    wsplit_kernel<<<2097152/1024, 256>>>(ff2_w, pwh + WFF2_OFF, pwl + WFF2_OFF, 2097152);

    fps_kernel<<<48, 512>>>(xyzs);
    ball_kernel<<<(3*NTOK)/4, 128>>>(xyzs);
    conv_kernel<<<NTOK, 128>>>(xyzs, oldf, conv_d_w, conv_f_w, out);
    embed_kernel<<<NTOK, 512>>>(pos_w, pos_b, contr_w, contr_b, out);

    for (int l = 0; l < 4; l++) {
        ln_split_kernel<<<NTOK, 256>>>(px, ln1_s + l*EDIM, ln1_b + l*EDIM, phh, phl);
        // QKV: split output (Q pre-scaled by 1/8)
        tgemm_b<<<dim3(12,48,1), 256, G_SMEM>>>(
            phh, phl, pwh + WQKV_OFF + (size_t)l*1536*512, pwl + WQKV_OFF + (size_t)l*1536*512,
            nullptr, nullptr, pqh, pql,
            512, 512, 512, 1536, 0,0,0, 1,1);
        // fused attention -> o hi/lo
        flash_kernel<<<dim3(LTOK/128, NB*NHEAD), 256, FA_SMEM>>>(pqh, pql, poh, pol);
        // out proj + residual (fp32 out) — BN=64 for wave fill
        tgemm_b64<<<dim3(8,48,1), 256, G64_SMEM>>>(
            poh, pol, pwh + WOUT_OFF + (size_t)l*512*512, pwl + WOUT_OFF + (size_t)l*512*512,
            out_b + l*EDIM, px, nullptr, nullptr,
            512, 512, 512, 512, 0,1,1, 0);
        ln_split_kernel<<<NTOK, 256>>>(px, ln2_s + l*EDIM, ln2_b + l*EDIM, phh, phl);
        // ff1 + gelu: split output — BN=64
        tgemm_b64<<<dim3(16,48,1), 256, G64_SMEM>>>(
            phh, phl, pwh + WFF1_OFF + (size_t)l*1024*512, pwl + WFF1_OFF + (size_t)l*1024*512,
            ff1_b + l*MLPD, nullptr, pf1h, pf1l,
            512, 512, 512, 1024, 1,0,1, 1);
        // ff2 + residual (fp32 out) — BN=64
        tgemm_b64<<<dim3(8,48,1), 256, G64_SMEM>>>(
            pf1h, pf1l, pwh + WFF2_OFF + (size_t)l*512*1024, pwl + WFF2_OFF + (size_t)l*512*1024,
            ff2_b + l*EDIM, px, nullptr, nullptr,
            1024, 1024, 1024, 512, 0,1,1, 0);
    }

    pool_kernel<<<NB, 512>>>();
    ln_kernel<<<NB, 256>>>(ppool, head_ln_s, head_ln_b, phln);
    head1_kernel<<<(NB*MLPD)/8, 256>>>(head1_w, head1_b);
    head2_kernel<<<NB*NCLS/4, 128>>>(head2_w, head2_b, out);
}

// round 9
// speedup vs baseline: 4.5718x; 1.0013x over previous
#include <cuda_runtime.h>
#include <cuda_bf16.h>
#include <cstdint>
#include <math.h>

#define NB 4
#define NT 24
#define NP 4096
#define MM 128
#define TO 12
#define LTOK 1536
#define NTOK 6144
#define EDIM 512
#define NHEAD 8
#define DHEAD 64
#define MLPD 1024
#define NCLS 30
#define KSAMP 32
#define RAD2 0.09f

#define CONTR_OFF 120
#define FEAT_OFF (120 + NTOK*EDIM)

// weight-split buffer offsets (elements)
#define WQKV_OFF 0
#define WOUT_OFF 3145728
#define WFF1_OFF 4194304
#define WFF2_OFF 6291456
#define WTOT     8388608

// ---------------- scratch (device globals; no cudaMalloc allowed) ----------
__device__ __align__(256) float g_anchor[NTOK*3];
__device__ __align__(256) int   g_ball[3*NTOK*KSAMP];
__device__ __align__(256) float g_x[NTOK*EDIM];
__device__ __align__(256) float g_pool[NB*EDIM];
__device__ __align__(256) float g_hln[NB*EDIM];
__device__ __align__(256) float g_h1[NB*MLPD];

__device__ __align__(256) __nv_bfloat16 g_wh[WTOT];
__device__ __align__(256) __nv_bfloat16 g_wl[WTOT];
__device__ __align__(256) __nv_bfloat16 g_hh[NTOK*EDIM];
__device__ __align__(256) __nv_bfloat16 g_hl[NTOK*EDIM];
__device__ __align__(256) __nv_bfloat16 g_qh[NTOK*1536];
__device__ __align__(256) __nv_bfloat16 g_ql[NTOK*1536];
__device__ __align__(256) __nv_bfloat16 g_oh[NTOK*EDIM];
__device__ __align__(256) __nv_bfloat16 g_ol[NTOK*EDIM];
__device__ __align__(256) __nv_bfloat16 g_f1h[NTOK*MLPD];
__device__ __align__(256) __nv_bfloat16 g_f1l[NTOK*MLPD];

__device__ __forceinline__ float gelu_exact(float x){
    return 0.5f*x*(1.0f+erff(x*0.70710678118654752440f));
}

// ==================== PTX helpers ==========================================
__device__ __forceinline__ void mma16816(float* c, const unsigned* a, const unsigned* b){
    asm volatile("mma.sync.aligned.m16n8k16.row.col.f32.bf16.bf16.f32 "
        "{%0,%1,%2,%3}, {%4,%5,%6,%7}, {%8,%9}, {%0,%1,%2,%3};"
        : "+f"(c[0]),"+f"(c[1]),"+f"(c[2]),"+f"(c[3])
        : "r"(a[0]),"r"(a[1]),"r"(a[2]),"r"(a[3]), "r"(b[0]),"r"(b[1]));
}
__device__ __forceinline__ void split2(float x, float y, unsigned& hi, unsigned& lo){
    __nv_bfloat16 hx = __float2bfloat16(x), hy = __float2bfloat16(y);
    float rx = x - __bfloat162float(hx), ry = y - __bfloat162float(hy);
    __nv_bfloat16 lx = __float2bfloat16(rx), ly = __float2bfloat16(ry);
    hi = (unsigned)__bfloat16_as_ushort(hx) | ((unsigned)__bfloat16_as_ushort(hy) << 16);
    lo = (unsigned)__bfloat16_as_ushort(lx) | ((unsigned)__bfloat16_as_ushort(ly) << 16);
}
__device__ __forceinline__ unsigned smem_u32(const void* p){
    unsigned a;
    asm("{ .reg .u64 t; cvta.to.shared.u64 t, %1; cvt.u32.u64 %0, t; }" : "=r"(a) : "l"(p));
    return a;
}
__device__ __forceinline__ void ldmx4(unsigned* r, unsigned addr){
    asm volatile("ldmatrix.sync.aligned.m8n8.x4.shared.b16 {%0,%1,%2,%3}, [%4];"
        : "=r"(r[0]),"=r"(r[1]),"=r"(r[2]),"=r"(r[3]) : "r"(addr));
}
__device__ __forceinline__ void ldmx4t(unsigned* r, unsigned addr){
    asm volatile("ldmatrix.sync.aligned.m8n8.x4.trans.shared.b16 {%0,%1,%2,%3}, [%4];"
        : "=r"(r[0]),"=r"(r[1]),"=r"(r[2]),"=r"(r[3]) : "r"(addr));
}
#define CP16(d, s) asm volatile("cp.async.cg.shared.global [%0], [%1], 16;" :: "r"(d), "l"(s) : "memory")
#define CPC() asm volatile("cp.async.commit_group;" ::: "memory")
#define CPW0() asm volatile("cp.async.wait_group 0;" ::: "memory")

// ---------------- fused weight split prep (single launch) -------------------
__global__ __launch_bounds__(256) void wsplit_all_kernel(
    const float* __restrict__ qkv_w, const float* __restrict__ out_w,
    const float* __restrict__ ff1_w, const float* __restrict__ ff2_w,
    __nv_bfloat16* __restrict__ hi, __nv_bfloat16* __restrict__ lo)
{
    int i = (blockIdx.x*256 + threadIdx.x)*4;
    if (i >= WTOT) return;
    const float* src;
    int off;
    if (i < WOUT_OFF)       { src = qkv_w; off = i - WQKV_OFF; }
    else if (i < WFF1_OFF)  { src = out_w; off = i - WOUT_OFF; }
    else if (i < WFF2_OFF)  { src = ff1_w; off = i - WFF1_OFF; }
    else                    { src = ff2_w; off = i - WFF2_OFF; }
    float4 v = *(const float4*)(src + off);
    unsigned h0, l0, h1, l1;
    split2(v.x, v.y, h0, l0); split2(v.z, v.w, h1, l1);
    *(unsigned*)(hi+i) = h0; *(unsigned*)(hi+i+2) = h1;
    *(unsigned*)(lo+i) = l0; *(unsigned*)(lo+i+2) = l1;
}

#define LDT 40                       // smem row stride in bf16 (32 + 8 pad)
#define GARR (128*LDT*2)             // 10240 B per 128-row array
#define GSTAGE (4*GARR)              // 40960 B per stage
#define G_SMEM (2*GSTAGE)            // 81920 B

// ============ GEMM BN=128, pre-split bf16, cp.async, ldmatrix ==============
// Single-sync mainloop: prefetch for chunk c+1 issued AFTER the entry barrier
// of chunk c — it targets stage (c+1)&1 while we read stage c&1, and the
// entry barrier of c guarantees all warps finished reading stage (c+1)&1 at
// iteration c-1. No trailing barrier needed.
__global__ __launch_bounds__(256) void tgemm_b(
    const __nv_bfloat16* __restrict__ AH_, const __nv_bfloat16* __restrict__ AL_,
    const __nv_bfloat16* __restrict__ WH_, const __nv_bfloat16* __restrict__ WL_,
    const float* __restrict__ bias, float* __restrict__ Cf,
    __nv_bfloat16* __restrict__ CH_, __nv_bfloat16* __restrict__ CL_,
    int K, int lda, int ldw, int ldc,
    int act, int resid, int hasb, int split, int qscale)
{
    extern __shared__ char smem[];
    unsigned sb = smem_u32(smem);

    int tid = threadIdx.x, wid = tid >> 5, lane = tid & 31;
    int g = lane >> 2, tg = lane & 3;
    int q8 = lane >> 3, lr8 = lane & 7;
    int rw = (wid >> 2) * 64, cw = (wid & 3) * 32;
    int bm = blockIdx.y * 128, bn = blockIdx.x * 128;

    float acc[4][4][4];
    #pragma unroll
    for (int i = 0; i < 4; i++)
        #pragma unroll
        for (int j = 0; j < 4; j++)
            #pragma unroll
            for (int p = 0; p < 4; p++) acc[i][j][p] = 0.f;

    int row = tid >> 1, half = tid & 1;
    int nch = K >> 5;

    {
        unsigned dst = sb + (row*LDT + half*16)*2;
        const __nv_bfloat16* a = AH_ + (size_t)(bm+row)*lda + half*16;
        const __nv_bfloat16* a2 = AL_ + (size_t)(bm+row)*lda + half*16;
        const __nv_bfloat16* w = WH_ + (size_t)(bn+row)*ldw + half*16;
        const __nv_bfloat16* w2 = WL_ + (size_t)(bn+row)*ldw + half*16;
        CP16(dst, a); CP16(dst+16, a+8);
        CP16(dst+GARR, a2); CP16(dst+GARR+16, a2+8);
        CP16(dst+2*GARR, w); CP16(dst+2*GARR+16, w+8);
        CP16(dst+3*GARR, w2); CP16(dst+3*GARR+16, w2+8);
        CPC();
    }

    for (int c = 0; c < nch; c++) {
        CPW0();
        __syncthreads();
        if (c + 1 < nch) {
            unsigned dst = sb + ((c+1)&1)*GSTAGE + (row*LDT + half*16)*2;
            const __nv_bfloat16* a = AH_ + (size_t)(bm+row)*lda + (c+1)*32 + half*16;
            const __nv_bfloat16* a2 = AL_ + (size_t)(bm+row)*lda + (c+1)*32 + half*16;
            const __nv_bfloat16* w = WH_ + (size_t)(bn+row)*ldw + (c+1)*32 + half*16;
            const __nv_bfloat16* w2 = WL_ + (size_t)(bn+row)*ldw + (c+1)*32 + half*16;
            CP16(dst, a); CP16(dst+16, a+8);
            CP16(dst+GARR, a2); CP16(dst+GARR+16, a2+8);
            CP16(dst+2*GARR, w); CP16(dst+2*GARR+16, w+8);
            CP16(dst+3*GARR, w2); CP16(dst+3*GARR+16, w2+8);
            CPC();
        }
        unsigned sAH = sb + (c&1)*GSTAGE;
        unsigned sAL = sAH + GARR;
        unsigned sWH = sAH + 2*GARR;
        unsigned sWL = sAH + 3*GARR;
        #pragma unroll
        for (int ks = 0; ks < 2; ks++) {
            int k0 = ks * 16;
            unsigned ah[4][4], al[4][4], bh[2][4], bl[2][4];
            #pragma unroll
            for (int mt = 0; mt < 4; mt++) {
                unsigned off = (unsigned)((rw + mt*16 + (q8&1)*8 + lr8)*LDT + k0 + (q8>>1)*8)*2;
                ldmx4(ah[mt], sAH + off);
                ldmx4(al[mt], sAL + off);
            }
            #pragma unroll
            for (int ntp = 0; ntp < 2; ntp++) {
                unsigned off = (unsigned)((cw + ntp*16 + (q8>>1)*8 + lr8)*LDT + k0 + (q8&1)*8)*2;
                ldmx4(bh[ntp], sWH + off);
                ldmx4(bl[ntp], sWL + off);
            }
            #pragma unroll
            for (int mt = 0; mt < 4; mt++)
                #pragma unroll
                for (int nt = 0; nt < 4; nt++) {
                    const unsigned* ph = &bh[nt>>1][(nt&1)*2];
                    const unsigned* pl = &bl[nt>>1][(nt&1)*2];
                    mma16816(acc[mt][nt], ah[mt], ph);
                    mma16816(acc[mt][nt], ah[mt], pl);
                    mma16816(acc[mt][nt], al[mt], ph);
                }
        }
    }
    #pragma unroll
    for (int mt = 0; mt < 4; mt++) {
        #pragma unroll
        for (int nt = 0; nt < 4; nt++) {
            int r0 = bm + rw + mt*16 + g;
            int col = bn + cw + nt*8 + tg*2;
            #pragma unroll
            for (int half2 = 0; half2 < 2; half2++) {
                int r = r0 + half2*8;
                float v0 = acc[mt][nt][half2*2+0];
                float v1 = acc[mt][nt][half2*2+1];
                if (hasb) { v0 += bias[col]; v1 += bias[col+1]; }
                if (act)  { v0 = gelu_exact(v0); v1 = gelu_exact(v1); }
                if (split) {
                    if (qscale && col < 512) { v0 *= 0.125f; v1 *= 0.125f; }
                    unsigned hh, ll;
                    split2(v0, v1, hh, ll);
                    *(unsigned*)(CH_ + (size_t)r*ldc + col) = hh;
                    *(unsigned*)(CL_ + (size_t)r*ldc + col) = ll;
                } else {
                    float* cp = Cf + (size_t)r * ldc + col;
                    if (resid) {
                        float2 old = *(float2*)cp;
                        v0 += old.x; v1 += old.y;
                    }
                    float2 ov = {v0, v1};
                    *(float2*)cp = ov;
                }
            }
        }
    }
}

// ============ GEMM BN=64 (wave fill for narrow N), single-sync mainloop ====
#define G64_WARR (64*LDT*2)              // 5120 B
#define G64_STAGE (2*GARR + 2*G64_WARR)  // 30720 B
#define G64_SMEM (2*G64_STAGE)           // 61440 B

__global__ __launch_bounds__(256) void tgemm_b64(
    const __nv_bfloat16* __restrict__ AH_, const __nv_bfloat16* __restrict__ AL_,
    const __nv_bfloat16* __restrict__ WH_, const __nv_bfloat16* __restrict__ WL_,
    const float* __restrict__ bias, float* __restrict__ Cf,
    __nv_bfloat16* __restrict__ CH_, __nv_bfloat16* __restrict__ CL_,
    int K, int lda, int ldw, int ldc,
    int act, int resid, int hasb, int split)
{
    extern __shared__ char smem[];
    unsigned sb = smem_u32(smem);

    int tid = threadIdx.x, wid = tid >> 5, lane = tid & 31;
    int g = lane >> 2, tg = lane & 3;
    int q8 = lane >> 3, lr8 = lane & 7;
    int rw = (wid >> 2) * 64, cw = (wid & 3) * 16;
    int bm = blockIdx.y * 128, bn = blockIdx.x * 64;

    float acc[4][2][4];
    #pragma unroll
    for (int i = 0; i < 4; i++)
        #pragma unroll
        for (int j = 0; j < 2; j++)
            #pragma unroll
            for (int p = 0; p < 4; p++) acc[i][j][p] = 0.f;

    int row = tid >> 1, half = tid & 1;
    int roww = tid >> 2, colq = (tid & 3) * 8;
    int nch = K >> 5;

    {
        unsigned dstA = sb + (row*LDT + half*16)*2;
        const __nv_bfloat16* a = AH_ + (size_t)(bm+row)*lda + half*16;
        const __nv_bfloat16* a2 = AL_ + (size_t)(bm+row)*lda + half*16;
        CP16(dstA, a); CP16(dstA+16, a+8);
        CP16(dstA+GARR, a2); CP16(dstA+GARR+16, a2+8);
        unsigned dstW = sb + 2*GARR + (roww*LDT + colq)*2;
        const __nv_bfloat16* w = WH_ + (size_t)(bn+roww)*ldw + colq;
        const __nv_bfloat16* w2 = WL_ + (size_t)(bn+roww)*ldw + colq;
        CP16(dstW, w);
        CP16(dstW+G64_WARR, w2);
        CPC();
    }

    for (int c = 0; c < nch; c++) {
        CPW0();
        __syncthreads();
        if (c + 1 < nch) {
            unsigned st = ((c+1)&1)*G64_STAGE;
            unsigned dstA = sb + st + (row*LDT + half*16)*2;
            const __nv_bfloat16* a = AH_ + (size_t)(bm+row)*lda + (c+1)*32 + half*16;
            const __nv_bfloat16* a2 = AL_ + (size_t)(bm+row)*lda + (c+1)*32 + half*16;
            CP16(dstA, a); CP16(dstA+16, a+8);
            CP16(dstA+GARR, a2); CP16(dstA+GARR+16, a2+8);
            unsigned dstW = sb + st + 2*GARR + (roww*LDT + colq)*2;
            const __nv_bfloat16* w = WH_ + (size_t)(bn+roww)*ldw + (c+1)*32 + colq;
            const __nv_bfloat16* w2 = WL_ + (size_t)(bn+roww)*ldw + (c+1)*32 + colq;
            CP16(dstW, w);
            CP16(dstW+G64_WARR, w2);
            CPC();
        }
        unsigned sAH = sb + (c&1)*G64_STAGE;
        unsigned sAL = sAH + GARR;
        unsigned sWH = sAH + 2*GARR;
        unsigned sWL = sWH + G64_WARR;
        #pragma unroll
        for (int ks = 0; ks < 2; ks++) {
            int k0 = ks * 16;
            unsigned ah[4][4], al[4][4], bh4[4], bl4[4];
            #pragma unroll
            for (int mt = 0; mt < 4; mt++) {
                unsigned off = (unsigned)((rw + mt*16 + (q8&1)*8 + lr8)*LDT + k0 + (q8>>1)*8)*2;
                ldmx4(ah[mt], sAH + off);
                ldmx4(al[mt], sAL + off);
            }
            {
                unsigned off = (unsigned)((cw + (q8>>1)*8 + lr8)*LDT + k0 + (q8&1)*8)*2;
                ldmx4(bh4, sWH + off);
                ldmx4(bl4, sWL + off);
            }
            #pragma unroll
            for (int mt = 0; mt < 4; mt++)
                #pragma unroll
                for (int nt = 0; nt < 2; nt++) {
                    mma16816(acc[mt][nt], ah[mt], bh4 + nt*2);
                    mma16816(acc[mt][nt], ah[mt], bl4 + nt*2);
                    mma16816(acc[mt][nt], al[mt], bh4 + nt*2);
                }
        }
    }
    #pragma unroll
    for (int mt = 0; mt < 4; mt++) {
        #pragma unroll
        for (int nt = 0; nt < 2; nt++) {
            int r0 = bm + rw + mt*16 + g;
            int col = bn + cw + nt*8 + tg*2;
            #pragma unroll
            for (int half2 = 0; half2 < 2; half2++) {
                int r = r0 + half2*8;
                float v0 = acc[mt][nt][half2*2+0];
                float v1 = acc[mt][nt][half2*2+1];
                if (hasb) { v0 += bias[col]; v1 += bias[col+1]; }
                if (act)  { v0 = gelu_exact(v0); v1 = gelu_exact(v1); }
                if (split) {
                    unsigned hh, ll;
                    split2(v0, v1, hh, ll);
                    *(unsigned*)(CH_ + (size_t)r*ldc + col) = hh;
                    *(unsigned*)(CL_ + (size_t)r*ldc + col) = ll;
                } else {
                    float* cp = Cf + (size_t)r * ldc + col;
                    if (resid) {
                        float2 old = *(float2*)cp;
                        v0 += old.x; v1 += old.y;
                    }
                    float2 ov = {v0, v1};
                    *(float2*)cp = ov;
                }
            }
        }
    }
}

// ==================== flash attention (single-sync tile loop) ==============
#define FQS 72
#define FARR (128*FQS*2)             // 18432 B
#define FQH 0
#define FQL FARR
#define FST(s) (2*FARR + (s)*4*FARR)
#define FA_SMEM (2*FARR + 2*4*FARR)  // 184320 B

__global__ __launch_bounds__(256) void flash_kernel(
    const __nv_bfloat16* __restrict__ qh, const __nv_bfloat16* __restrict__ ql,
    __nv_bfloat16* __restrict__ oh, __nv_bfloat16* __restrict__ ol)
{
    extern __shared__ char fsm[];
    unsigned sb = smem_u32(fsm);

    int tid = threadIdx.x, wid = tid >> 5, lane = tid & 31;
    int g = lane >> 2, tg = lane & 3;
    int q8 = lane >> 3, lr8 = lane & 7;
    int z = blockIdx.y;
    int b = z >> 3, h = z & 7;
    size_t base = (size_t)b * LTOK * 1536;
    int q0 = blockIdx.x * 128;

    int row = tid >> 1, half = tid & 1;

    {
        unsigned dq = sb + (row*FQS + half*32)*2;
        const __nv_bfloat16* sq = qh + base + (size_t)(q0+row)*1536 + h*64 + half*32;
        const __nv_bfloat16* sq2 = ql + base + (size_t)(q0+row)*1536 + h*64 + half*32;
        #pragma unroll
        for (int j = 0; j < 4; j++) {
            CP16(dq + j*16, sq + j*8);
            CP16(dq + FARR + j*16, sq2 + j*8);
        }
        unsigned dk = sb + FST(0) + (row*FQS + half*32)*2;
        const __nv_bfloat16* sk = qh + base + (size_t)row*1536 + 512 + h*64 + half*32;
        const __nv_bfloat16* sk2 = ql + base + (size_t)row*1536 + 512 + h*64 + half*32;
        const __nv_bfloat16* sv = qh + base + (size_t)row*1536 + 1024 + h*64 + half*32;
        const __nv_bfloat16* sv2 = ql + base + (size_t)row*1536 + 1024 + h*64 + half*32;
        #pragma unroll
        for (int j = 0; j < 4; j++) {
            CP16(dk + j*16, sk + j*8);
            CP16(dk + FARR + j*16, sk2 + j*8);
            CP16(dk + 2*FARR + j*16, sv + j*8);
            CP16(dk + 3*FARR + j*16, sv2 + j*8);
        }
        CPC();
    }

    float acco[8][4];
    #pragma unroll
    for (int i = 0; i < 8; i++)
        #pragma unroll
        for (int p = 0; p < 4; p++) acco[i][p] = 0.f;
    float m0 = -3.402823466e38f, m1 = -3.402823466e38f, l0s = 0.f, l1s = 0.f;

    for (int t = 0; t < LTOK/128; t++) {
        CPW0();
        __syncthreads();
        if (t + 1 < LTOK/128) {
            unsigned dk = sb + FST((t+1)&1) + (row*FQS + half*32)*2;
            size_t ro = base + (size_t)((t+1)*128+row)*1536 + h*64 + half*32;
            const __nv_bfloat16* sk = qh + ro + 512;
            const __nv_bfloat16* sk2 = ql + ro + 512;
            const __nv_bfloat16* sv = qh + ro + 1024;
            const __nv_bfloat16* sv2 = ql + ro + 1024;
            #pragma unroll
            for (int j = 0; j < 4; j++) {
                CP16(dk + j*16, sk + j*8);
                CP16(dk + FARR + j*16, sk2 + j*8);
                CP16(dk + 2*FARR + j*16, sv + j*8);
                CP16(dk + 3*FARR + j*16, sv2 + j*8);
            }
            CPC();
        }
        unsigned sKH = sb + FST(t&1);
        unsigned sKL = sKH + FARR;
        unsigned sVH = sKH + 2*FARR;
        unsigned sVL = sKH + 3*FARR;

        float accs[16][4];
        #pragma unroll
        for (int nt = 0; nt < 16; nt++)
            #pragma unroll
            for (int p = 0; p < 4; p++) accs[nt][p] = 0.f;
        #pragma unroll
        for (int ks = 0; ks < 4; ks++) {
            int k0 = ks*16;
            unsigned aqh[4], aql[4];
            unsigned aoff = (unsigned)((wid*16 + (q8&1)*8 + lr8)*FQS + k0 + (q8>>1)*8)*2;
            ldmx4(aqh, sb + FQH + aoff);
            ldmx4(aql, sb + FQL + aoff);
            #pragma unroll
            for (int ntp = 0; ntp < 8; ntp++) {
                unsigned boff = (unsigned)((ntp*16 + (q8>>1)*8 + lr8)*FQS + k0 + (q8&1)*8)*2;
                unsigned bh4[4], bl4[4];
                ldmx4(bh4, sKH + boff);
                ldmx4(bl4, sKL + boff);
                mma16816(accs[2*ntp],   aqh, bh4);
                mma16816(accs[2*ntp],   aqh, bl4);
                mma16816(accs[2*ntp],   aql, bh4);
                mma16816(accs[2*ntp+1], aqh, bh4+2);
                mma16816(accs[2*ntp+1], aqh, bl4+2);
                mma16816(accs[2*ntp+1], aql, bh4+2);
            }
        }

        float mx0 = -3.402823466e38f, mx1 = -3.402823466e38f;
        #pragma unroll
        for (int nt = 0; nt < 16; nt++) {
            mx0 = fmaxf(mx0, fmaxf(accs[nt][0], accs[nt][1]));
            mx1 = fmaxf(mx1, fmaxf(accs[nt][2], accs[nt][3]));
        }
        mx0 = fmaxf(mx0, __shfl_xor_sync(0xffffffffu, mx0, 1));
        mx0 = fmaxf(mx0, __shfl_xor_sync(0xffffffffu, mx0, 2));
        mx1 = fmaxf(mx1, __shfl_xor_sync(0xffffffffu, mx1, 1));
        mx1 = fmaxf(mx1, __shfl_xor_sync(0xffffffffu, mx1, 2));
        float mn0 = fmaxf(m0, mx0), mn1 = fmaxf(m1, mx1);
        float c0 = __expf(m0 - mn0), c1 = __expf(m1 - mn1);
        float s0 = 0.f, s1 = 0.f;
        #pragma unroll
        for (int nt = 0; nt < 16; nt++) {
            accs[nt][0] = __expf(accs[nt][0] - mn0);
            accs[nt][1] = __expf(accs[nt][1] - mn0);
            accs[nt][2] = __expf(accs[nt][2] - mn1);
            accs[nt][3] = __expf(accs[nt][3] - mn1);
            s0 += accs[nt][0] + accs[nt][1];
            s1 += accs[nt][2] + accs[nt][3];
        }
        s0 += __shfl_xor_sync(0xffffffffu, s0, 1);
        s0 += __shfl_xor_sync(0xffffffffu, s0, 2);
        s1 += __shfl_xor_sync(0xffffffffu, s1, 1);
        s1 += __shfl_xor_sync(0xffffffffu, s1, 2);
        l0s = l0s * c0 + s0;
        l1s = l1s * c1 + s1;
        m0 = mn0; m1 = mn1;
        #pragma unroll
        for (int i = 0; i < 8; i++) {
            acco[i][0] *= c0; acco[i][1] *= c0;
            acco[i][2] *= c1; acco[i][3] *= c1;
        }

        #pragma unroll
        for (int pks = 0; pks < 8; pks++) {
            unsigned aph[4], apl[4];
            split2(accs[2*pks][0],   accs[2*pks][1],   aph[0], apl[0]);
            split2(accs[2*pks][2],   accs[2*pks][3],   aph[1], apl[1]);
            split2(accs[2*pks+1][0], accs[2*pks+1][1], aph[2], apl[2]);
            split2(accs[2*pks+1][2], accs[2*pks+1][3], aph[3], apl[3]);
            #pragma unroll
            for (int ntp2 = 0; ntp2 < 4; ntp2++) {
                unsigned voff = (unsigned)((pks*16 + (q8&1)*8 + lr8)*FQS + ntp2*16 + (q8>>1)*8)*2;
                unsigned bvh[4], bvl[4];
                ldmx4t(bvh, sVH + voff);
                ldmx4t(bvl, sVL + voff);
                mma16816(acco[2*ntp2],   aph, bvh);
                mma16816(acco[2*ntp2],   aph, bvl);
                mma16816(acco[2*ntp2],   apl, bvh);
                mma16816(acco[2*ntp2+1], aph, bvh+2);
                mma16816(acco[2*ntp2+1], aph, bvl+2);
                mma16816(acco[2*ntp2+1], apl, bvh+2);
            }
        }
    }

    float inv0 = 1.0f / l0s, inv1 = 1.0f / l1s;
    int orow = q0 + wid*16 + g;
    #pragma unroll
    for (int nt2 = 0; nt2 < 8; nt2++) {
        int col = h*64 + nt2*8 + tg*2;
        unsigned hh, ll;
        split2(acco[nt2][0]*inv0, acco[nt2][1]*inv0, hh, ll);
        *(unsigned*)(oh + (size_t)(b*LTOK + orow) * EDIM + col) = hh;
        *(unsigned*)(ol + (size_t)(b*LTOK + orow) * EDIM + col) = ll;
        split2(acco[nt2][2]*inv1, acco[nt2][3]*inv1, hh, ll);
        *(unsigned*)(oh + (size_t)(b*LTOK + orow + 8) * EDIM + col) = hh;
        *(unsigned*)(ol + (size_t)(b*LTOK + orow + 8) * EDIM + col) = ll;
    }
}

// ---------------- FPS -------------------------------------------------------
__global__ __launch_bounds__(512) void fps_kernel(const float* __restrict__ xyzs) {
    int blk = blockIdx.x;
    int b = blk / TO, j = blk % TO;
    const float* P = xyzs + (size_t)(b*NT + 2*j)*NP*3;
    int tid = threadIdx.x;
    float px[8], py[8], pz[8], dist[8];
    #pragma unroll
    for (int i = 0; i < 8; i++) {
        int p = tid + i*512;
        px[i] = P[p*3+0]; py[i] = P[p*3+1]; pz[i] = P[p*3+2];
        dist[i] = 1e10f;
    }
    __shared__ float sbx, sby, sbz;
    __shared__ float swv[16];
    __shared__ int   swi[16];
    float* anch = g_anchor + (size_t)blk*MM*3;
    if (tid == 0) {
        sbx = P[0]; sby = P[1]; sbz = P[2];
        anch[0] = P[0]; anch[1] = P[1]; anch[2] = P[2];
    }
    __syncthreads();
    for (int s = 1; s < MM; s++) {
        float bx = sbx, by = sby, bz = sbz;
        float bestv = -1.0f; int besti = 0x7fffffff;
        #pragma unroll
        for (int i = 0; i < 8; i++) {
            float dx = __fsub_rn(px[i], bx);
            float dy = __fsub_rn(py[i], by);
            float dz = __fsub_rn(pz[i], bz);
            float d = __fadd_rn(__fadd_rn(__fmul_rn(dx,dx), __fmul_rn(dy,dy)), __fmul_rn(dz,dz));
            float nd = fminf(dist[i], d);
            dist[i] = nd;
            int p = tid + i*512;
            if (nd > bestv || (nd == bestv && p < besti)) { bestv = nd; besti = p; }
        }
        #pragma unroll
        for (int off = 16; off; off >>= 1) {
            float ov = __shfl_down_sync(0xffffffffu, bestv, off);
            int   oi = __shfl_down_sync(0xffffffffu, besti, off);
            if (ov > bestv || (ov == bestv && oi < besti)) { bestv = ov; besti = oi; }
        }
        if ((tid & 31) == 0) { swv[tid>>5] = bestv; swi[tid>>5] = besti; }
        __syncthreads();
        if (tid == 0) {
            float v = swv[0]; int ii = swi[0];
            #pragma unroll
            for (int w = 1; w < 16; w++)
                if (swv[w] > v || (swv[w] == v && swi[w] < ii)) { v = swv[w]; ii = swi[w]; }
            float x0 = P[ii*3+0], y0 = P[ii*3+1], z0 = P[ii*3+2];
            sbx = x0; sby = y0; sbz = z0;
            anch[s*3+0] = x0; anch[s*3+1] = y0; anch[s*3+2] = z0;
        }
        __syncthreads();
    }
}

// ---------------- Ball query ------------------------------------------------
__global__ __launch_bounds__(128) void ball_kernel(const float* __restrict__ xyzs) {
    int w = blockIdx.x*4 + (threadIdx.x >> 5);
    int lane = threadIdx.x & 31;
    int o = w / NTOK;
    int tok = w % NTOK;
    int b = tok / LTOK, loc = tok % LTOK, j = loc / MM;
    int pf = 2*j + o;
    int of = (pf == 0) ? 0 : (pf - 1);
    const float* P = xyzs + (size_t)(b*NT + of)*NP*3;
    float ax = g_anchor[tok*3+0], ay = g_anchor[tok*3+1], az = g_anchor[tok*3+2];
    int* out = g_ball + ((size_t)o*NTOK + tok)*KSAMP;
    int cnt = 0, first = 0; bool found = false;
    for (int base = 0; base < NP; base += 32) {
        int p = base + lane;
        float x = P[p*3+0], y = P[p*3+1], z = P[p*3+2];
        float dx = __fsub_rn(ax,x), dy = __fsub_rn(ay,y), dz = __fsub_rn(az,z);
        float d2 = __fadd_rn(__fadd_rn(__fmul_rn(dx,dx), __fmul_rn(dy,dy)), __fmul_rn(dz,dz));
        bool inside = d2 < RAD2;
        unsigned msk = __ballot_sync(0xffffffffu, inside);
        if (!found && msk) { first = base + __ffs(msk) - 1; found = true; }
        int pos = cnt + __popc(msk & ((1u << lane) - 1u));
        if (inside && pos < KSAMP) out[pos] = p;
        cnt += __popc(msk);
        if (cnt >= KSAMP) break;
    }
    if (lane >= cnt) out[lane] = found ? first : 0;
}

// ---------------- grouped conv + max pool ----------------------------------
__global__ __launch_bounds__(128) void conv_kernel(
    const float* __restrict__ xyzs, const float* __restrict__ oldf,
    const float* __restrict__ Wd, const float* __restrict__ Wf,
    float* __restrict__ dout)
{
    int tok = blockIdx.x;
    int b = tok / LTOK, loc = tok % LTOK, j = loc / MM;
    int tid = threadIdx.x;
    __shared__ float sd[KSAMP][4];
    __shared__ float sf[KSAMP][2];
    float ax = g_anchor[tok*3+0], ay = g_anchor[tok*3+1], az = g_anchor[tok*3+2];
    float wd[4][4], wf[4][2], vmax[4];
    #pragma unroll
    for (int r = 0; r < 4; r++) {
        int d = tid + 128*r;
        wd[r][0] = Wd[d*4+0]; wd[r][1] = Wd[d*4+1]; wd[r][2] = Wd[d*4+2]; wd[r][3] = Wd[d*4+3];
        wf[r][0] = Wf[d*2+0]; wf[r][1] = Wf[d*2+1];
        vmax[r] = -3.402823466e38f;
    }
    for (int o = 0; o < 3; o++) {
        int pf = 2*j + o;
        int of = (pf == 0) ? 0 : (pf - 1);
        const float* P = xyzs + (size_t)(b*NT + of)*NP*3;
        const float* F = oldf + (size_t)(b*NT + of)*2*NP;
        __syncthreads();
        if (tid < KSAMP) {
            int idx = g_ball[((size_t)o*NTOK + tok)*KSAMP + tid];
            sd[tid][0] = P[idx*3+0] - ax;
            sd[tid][1] = P[idx*3+1] - ay;
            sd[tid][2] = P[idx*3+2] - az;
            sd[tid][3] = (float)(o - 1);
            sf[tid][0] = F[idx];
            sf[tid][1] = F[NP + idx];
        }
        __syncthreads();
        #pragma unroll 4
        for (int k = 0; k < KSAMP; k++) {
            float d0 = sd[k][0], d1 = sd[k][1], d2 = sd[k][2], d3 = sd[k][3];
            float f0 = sf[k][0], f1 = sf[k][1];
            #pragma unroll
            for (int r = 0; r < 4; r++) {
                float de = wd[r][0]*d0 + wd[r][1]*d1 + wd[r][2]*d2 + wd[r][3]*d3;
                float fe = wf[r][0]*f0 + wf[r][1]*f1;
                vmax[r] = fmaxf(vmax[r], de*fe);
            }
        }
    }
    #pragma unroll
    for (int r = 0; r < 4; r++)
        dout[FEAT_OFF + (size_t)tok*EDIM + tid + 128*r] = vmax[r];
}

// ---------------- pos + contrastive + relu(pos+feat) -----------------------
__global__ __launch_bounds__(512) void embed_kernel(
    const float* __restrict__ pw, const float* __restrict__ pb,
    const float* __restrict__ cw, const float* __restrict__ cb,
    float* __restrict__ dout)
{
    int tok = blockIdx.x;
    int d = threadIdx.x;
    int loc = tok % LTOK, j = loc / MM;
    float ax = g_anchor[tok*3+0], ay = g_anchor[tok*3+1], az = g_anchor[tok*3+2];
    float tv = (float)(j + 1);
    float pos = pw[d*4+0]*ax + pw[d*4+1]*ay + pw[d*4+2]*az + pw[d*4+3]*tv + pb[d];
    float con = cw[d*4+0]*ax + cw[d*4+1]*ay + cw[d*4+2]*az + cw[d*4+3]*tv + cb[d];
    dout[CONTR_OFF + (size_t)tok*EDIM + d] = con;
    float feat = dout[FEAT_OFF + (size_t)tok*EDIM + d];
    g_x[(size_t)tok*EDIM + d] = fmaxf(pos + feat, 0.0f);
}

// ---------------- LayerNorm -> bf16 hi/lo ----------------------------------
__global__ __launch_bounds__(256) void ln_split_kernel(
    const float* __restrict__ x, const float* __restrict__ s,
    const float* __restrict__ bb,
    __nv_bfloat16* __restrict__ outh, __nv_bfloat16* __restrict__ outl)
{
    int tok = blockIdx.x;
    int tid = threadIdx.x;
    const float* row = x + (size_t)tok*EDIM;
    float v0 = row[tid], v1 = row[tid + 256];
    float sum = v0 + v1, sq = v0*v0 + v1*v1;
    #pragma unroll
    for (int off = 16; off; off >>= 1) {
        sum += __shfl_xor_sync(0xffffffffu, sum, off);
        sq  += __shfl_xor_sync(0xffffffffu, sq, off);
    }
    __shared__ float ssum[8], ssq[8];
    if ((tid & 31) == 0) { ssum[tid>>5] = sum; ssq[tid>>5] = sq; }
    __syncthreads();
    float ts = 0.f, tq = 0.f;
    #pragma unroll
    for (int w = 0; w < 8; w++) { ts += ssum[w]; tq += ssq[w]; }
    float mu = ts * (1.0f/512.0f);
    float var = tq * (1.0f/512.0f) - mu*mu;
    float rstd = rsqrtf(var + 1e-5f);
    float y0 = (v0 - mu)*rstd*s[tid] + bb[tid];
    float y1 = (v1 - mu)*rstd*s[tid+256] + bb[tid+256];
    __nv_bfloat16 h0 = __float2bfloat16(y0);
    __nv_bfloat16 h1 = __float2bfloat16(y1);
    outh[(size_t)tok*EDIM + tid]       = h0;
    outh[(size_t)tok*EDIM + tid + 256] = h1;
    outl[(size_t)tok*EDIM + tid]       = __float2bfloat16(y0 - __bfloat162float(h0));
    outl[(size_t)tok*EDIM + tid + 256] = __float2bfloat16(y1 - __bfloat162float(h1));
}

// ---------------- fp32 LayerNorm (head) ------------------------------------
__global__ __launch_bounds__(256) void ln_kernel(
    const float* __restrict__ x, const float* __restrict__ s,
    const float* __restrict__ bb, float* __restrict__ out)
{
    int tok = blockIdx.x;
    int tid = threadIdx.x;
    const float* row = x + (size_t)tok*EDIM;
    float v0 = row[tid], v1 = row[tid + 256];
    float sum = v0 + v1, sq = v0*v0 + v1*v1;
    #pragma unroll
    for (int off = 16; off; off >>= 1) {
        sum += __shfl_xor_sync(0xffffffffu, sum, off);
        sq  += __shfl_xor_sync(0xffffffffu, sq, off);
    }
    __shared__ float ssum[8], ssq[8];
    if ((tid & 31) == 0) { ssum[tid>>5] = sum; ssq[tid>>5] = sq; }
    __syncthreads();
    float ts = 0.f, tq = 0.f;
    #pragma unroll
    for (int w = 0; w < 8; w++) { ts += ssum[w]; tq += ssq[w]; }
    float mu = ts * (1.0f/512.0f);
    float var = tq * (1.0f/512.0f) - mu*mu;
    float rstd = rsqrtf(var + 1e-5f);
    out[(size_t)tok*EDIM + tid]       = (v0 - mu)*rstd*s[tid] + bb[tid];
    out[(size_t)tok*EDIM + tid + 256] = (v1 - mu)*rstd*s[tid+256] + bb[tid+256];
}

// ---------------- head ------------------------------------------------------
__global__ __launch_bounds__(512) void pool_kernel() {
    int b = blockIdx.x;
    int d = threadIdx.x;
    float v = -3.402823466e38f;
    const float* p = g_x + (size_t)b*LTOK*EDIM + d;
    for (int i = 0; i < LTOK; i++) v = fmaxf(v, p[(size_t)i*EDIM]);
    g_pool[b*EDIM + d] = v;
}
__global__ __launch_bounds__(256) void head1_kernel(
    const float* __restrict__ W, const float* __restrict__ bias)
{
    int out = blockIdx.x*8 + (threadIdx.x >> 5);
    int lane = threadIdx.x & 31;
    int b = out >> 10, jj = out & 1023;
    const float* xr = g_hln + b*EDIM;
    const float* wr = W + (size_t)jj*EDIM;
    float s = 0.f;
    for (int d = lane; d < EDIM; d += 32) s += xr[d]*wr[d];
    #pragma unroll
    for (int off = 16; off; off >>= 1) s += __shfl_xor_sync(0xffffffffu, s, off);
    if (lane == 0) g_h1[out] = gelu_exact(s + bias[jj]);
}
__global__ __launch_bounds__(128) void head2_kernel(
    const float* __restrict__ W, const float* __restrict__ bias,
    float* __restrict__ dout)
{
    int out = blockIdx.x*4 + (threadIdx.x >> 5);
    int lane = threadIdx.x & 31;
    int b = out / NCLS, c = out % NCLS;
    float s = 0.f;
    for (int d = lane; d < MLPD; d += 32) s += g_h1[b*MLPD + d]*W[(size_t)c*MLPD + d];
    #pragma unroll
    for (int off = 16; off; off >>= 1) s += __shfl_xor_sync(0xffffffffu, s, off);
    if (lane == 0) dout[out] = s + bias[c];
}

// ---------------- launch ---------------------------------------------------
extern "C" void kernel_launch(void* const* d_in, const int* in_sizes, int n_in,
                              void* d_out, int out_size) {
    const float* xyzs      = (const float*)d_in[0];
    const float* oldf      = (const float*)d_in[1];
    const float* conv_d_w  = (const float*)d_in[2];
    const float* conv_f_w  = (const float*)d_in[3];
    const float* pos_w     = (const float*)d_in[4];
    const float* pos_b     = (const float*)d_in[5];
    const float* contr_w   = (const float*)d_in[6];
    const float* contr_b   = (const float*)d_in[7];
    const float* ln1_s     = (const float*)d_in[8];
    const float* ln1_b     = (const float*)d_in[9];
    const float* qkv_w     = (const float*)d_in[10];
    const float* out_w     = (const float*)d_in[11];
    const float* out_b     = (const float*)d_in[12];
    const float* ln2_s     = (const float*)d_in[13];
    const float* ln2_b     = (const float*)d_in[14];
    const float* ff1_w     = (const float*)d_in[15];
    const float* ff1_b     = (const float*)d_in[16];
    const float* ff2_w     = (const float*)d_in[17];
    const float* ff2_b     = (const float*)d_in[18];
    const float* head_ln_s = (const float*)d_in[19];
    const float* head_ln_b = (const float*)d_in[20];
    const float* head1_w   = (const float*)d_in[21];
    const float* head1_b   = (const float*)d_in[22];
    const float* head2_w   = (const float*)d_in[23];
    const float* head2_b   = (const float*)d_in[24];
    float* out = (float*)d_out;

    float *px, *ppool, *phln;
    __nv_bfloat16 *pwh, *pwl, *phh, *phl, *pqh, *pql, *poh, *pol, *pf1h, *pf1l;
    cudaGetSymbolAddress((void**)&px,    g_x);
    cudaGetSymbolAddress((void**)&ppool, g_pool);
    cudaGetSymbolAddress((void**)&phln,  g_hln);
    cudaGetSymbolAddress((void**)&pwh,   g_wh);
    cudaGetSymbolAddress((void**)&pwl,   g_wl);
    cudaGetSymbolAddress((void**)&phh,   g_hh);
    cudaGetSymbolAddress((void**)&phl,   g_hl);
    cudaGetSymbolAddress((void**)&pqh,   g_qh);
    cudaGetSymbolAddress((void**)&pql,   g_ql);
    cudaGetSymbolAddress((void**)&poh,   g_oh);
    cudaGetSymbolAddress((void**)&pol,   g_ol);
    cudaGetSymbolAddress((void**)&pf1h,  g_f1h);
    cudaGetSymbolAddress((void**)&pf1l,  g_f1l);

    cudaFuncSetAttribute(flash_kernel, cudaFuncAttributeMaxDynamicSharedMemorySize, FA_SMEM);
    cudaFuncSetAttribute(tgemm_b, cudaFuncAttributeMaxDynamicSharedMemorySize, G_SMEM);
    cudaFuncSetAttribute(tgemm_b64, cudaFuncAttributeMaxDynamicSharedMemorySize, G64_SMEM);

    // ---- one-time weight split (single fused launch; graph-safe) ----
    wsplit_all_kernel<<<WTOT/1024, 256>>>(qkv_w, out_w, ff1_w, ff2_w, pwh, pwl);

    fps_kernel<<<48, 512>>>(xyzs);
    ball_kernel<<<(3*NTOK)/4, 128>>>(xyzs);
    conv_kernel<<<NTOK, 128>>>(xyzs, oldf, conv_d_w, conv_f_w, out);
    embed_kernel<<<NTOK, 512>>>(pos_w, pos_b, contr_w, contr_b, out);

    for (int l = 0; l < 4; l++) {
        ln_split_kernel<<<NTOK, 256>>>(px, ln1_s + l*EDIM, ln1_b + l*EDIM, phh, phl);
        // QKV: split output (Q pre-scaled by 1/8)
        tgemm_b<<<dim3(12,48,1), 256, G_SMEM>>>(
            phh, phl, pwh + WQKV_OFF + (size_t)l*1536*512, pwl + WQKV_OFF + (size_t)l*1536*512,
            nullptr, nullptr, pqh, pql,
            512, 512, 512, 1536, 0,0,0, 1,1);
        // fused attention -> o hi/lo
        flash_kernel<<<dim3(LTOK/128, NB*NHEAD), 256, FA_SMEM>>>(pqh, pql, poh, pol);
        // out proj + residual (fp32 out) — BN=64
        tgemm_b64<<<dim3(8,48,1), 256, G64_SMEM>>>(
            poh, pol, pwh + WOUT_OFF + (size_t)l*512*512, pwl + WOUT_OFF + (size_t)l*512*512,
            out_b + l*EDIM, px, nullptr, nullptr,
            512, 512, 512, 512, 0,1,1, 0);
        ln_split_kernel<<<NTOK, 256>>>(px, ln2_s + l*EDIM, ln2_b + l*EDIM, phh, phl);
        // ff1 + gelu: split output — BN=64
        tgemm_b64<<<dim3(16,48,1), 256, G64_SMEM>>>(
            phh, phl, pwh + WFF1_OFF + (size_t)l*1024*512, pwl + WFF1_OFF + (size_t)l*1024*512,
            ff1_b + l*MLPD, nullptr, pf1h, pf1l,
            512, 512, 512, 1024, 1,0,1, 1);
        // ff2 + residual (fp32 out) — BN=64
        tgemm_b64<<<dim3(8,48,1), 256, G64_SMEM>>>(
            pf1h, pf1l, pwh + WFF2_OFF + (size_t)l*512*1024, pwl + WFF2_OFF + (size_t)l*512*1024,
            ff2_b + l*EDIM, px, nullptr, nullptr,
            1024, 1024, 1024, 512, 0,1,1, 0);
    }

    pool_kernel<<<NB, 512>>>();
    ln_kernel<<<NB, 256>>>(ppool, head_ln_s, head_ln_b, phln);
    head1_kernel<<<(NB*MLPD)/8, 256>>>(head1_w, head1_b);
    head2_kernel<<<NB*NCLS/4, 128>>>(head2_w, head2_b, out);
}

// round 10
// speedup vs baseline: 4.6455x; 1.0161x over previous
#include <cuda_runtime.h>
#include <cuda_bf16.h>
#include <cstdint>
#include <math.h>

#define NB 4
#define NT 24
#define NP 4096
#define MM 128
#define TO 12
#define LTOK 1536
#define NTOK 6144
#define EDIM 512
#define NHEAD 8
#define DHEAD 64
#define MLPD 1024
#define NCLS 30
#define KSAMP 32
#define RAD2 0.09f

#define CONTR_OFF 120
#define FEAT_OFF (120 + NTOK*EDIM)

// weight-split buffer offsets (elements)
#define WQKV_OFF 0
#define WOUT_OFF 3145728
#define WFF1_OFF 4194304
#define WFF2_OFF 6291456
#define WTOT     8388608

// ---------------- scratch (device globals; no cudaMalloc allowed) ----------
__device__ __align__(256) float g_anchor[NTOK*3];
__device__ __align__(256) int   g_ball[3*NTOK*KSAMP];
__device__ __align__(256) float g_x[NTOK*EDIM];
__device__ __align__(256) float g_pool[NB*EDIM];
__device__ __align__(256) float g_poolp[NB*12*EDIM];
__device__ __align__(256) float g_hln[NB*EDIM];
__device__ __align__(256) float g_h1[NB*MLPD];

__device__ __align__(256) __nv_bfloat16 g_wh[WTOT];
__device__ __align__(256) __nv_bfloat16 g_wl[WTOT];
__device__ __align__(256) __nv_bfloat16 g_hh[NTOK*EDIM];
__device__ __align__(256) __nv_bfloat16 g_hl[NTOK*EDIM];
__device__ __align__(256) __nv_bfloat16 g_qh[NTOK*1536];
__device__ __align__(256) __nv_bfloat16 g_ql[NTOK*1536];
__device__ __align__(256) __nv_bfloat16 g_oh[NTOK*EDIM];
__device__ __align__(256) __nv_bfloat16 g_ol[NTOK*EDIM];
__device__ __align__(256) __nv_bfloat16 g_f1h[NTOK*MLPD];
__device__ __align__(256) __nv_bfloat16 g_f1l[NTOK*MLPD];

__device__ __forceinline__ float gelu_exact(float x){
    return 0.5f*x*(1.0f+erff(x*0.70710678118654752440f));
}

// ==================== PTX helpers ==========================================
__device__ __forceinline__ void mma16816(float* c, const unsigned* a, const unsigned* b){
    asm volatile("mma.sync.aligned.m16n8k16.row.col.f32.bf16.bf16.f32 "
        "{%0,%1,%2,%3}, {%4,%5,%6,%7}, {%8,%9}, {%0,%1,%2,%3};"
        : "+f"(c[0]),"+f"(c[1]),"+f"(c[2]),"+f"(c[3])
        : "r"(a[0]),"r"(a[1]),"r"(a[2]),"r"(a[3]), "r"(b[0]),"r"(b[1]));
}
__device__ __forceinline__ void split2(float x, float y, unsigned& hi, unsigned& lo){
    __nv_bfloat16 hx = __float2bfloat16(x), hy = __float2bfloat16(y);
    float rx = x - __bfloat162float(hx), ry = y - __bfloat162float(hy);
    __nv_bfloat16 lx = __float2bfloat16(rx), ly = __float2bfloat16(ry);
    hi = (unsigned)__bfloat16_as_ushort(hx) | ((unsigned)__bfloat16_as_ushort(hy) << 16);
    lo = (unsigned)__bfloat16_as_ushort(lx) | ((unsigned)__bfloat16_as_ushort(ly) << 16);
}
__device__ __forceinline__ unsigned smem_u32(const void* p){
    unsigned a;
    asm("{ .reg .u64 t; cvta.to.shared.u64 t, %1; cvt.u32.u64 %0, t; }" : "=r"(a) : "l"(p));
    return a;
}
__device__ __forceinline__ void ldmx4(unsigned* r, unsigned addr){
    asm volatile("ldmatrix.sync.aligned.m8n8.x4.shared.b16 {%0,%1,%2,%3}, [%4];"
        : "=r"(r[0]),"=r"(r[1]),"=r"(r[2]),"=r"(r[3]) : "r"(addr));
}
__device__ __forceinline__ void ldmx4t(unsigned* r, unsigned addr){
    asm volatile("ldmatrix.sync.aligned.m8n8.x4.trans.shared.b16 {%0,%1,%2,%3}, [%4];"
        : "=r"(r[0]),"=r"(r[1]),"=r"(r[2]),"=r"(r[3]) : "r"(addr));
}
#define CP16(d, s) asm volatile("cp.async.cg.shared.global [%0], [%1], 16;" :: "r"(d), "l"(s) : "memory")
#define CPC() asm volatile("cp.async.commit_group;" ::: "memory")
#define CPW0() asm volatile("cp.async.wait_group 0;" ::: "memory")

// packed fp32x2 (Blackwell, plain sm_100+ PTX feature)
typedef unsigned long long ull;
__device__ __forceinline__ ull pk2(float a, float b){
    ull r; asm("mov.b64 %0, {%1,%2};" : "=l"(r) : "f"(a), "f"(b)); return r;
}
__device__ __forceinline__ void upk2(float& a, float& b, ull r){
    asm("mov.b64 {%0,%1}, %2;" : "=f"(a), "=f"(b) : "l"(r));
}
__device__ __forceinline__ ull f2mul(ull a, ull b){
    ull d; asm("mul.rn.f32x2 %0,%1,%2;" : "=l"(d) : "l"(a), "l"(b)); return d;
}
__device__ __forceinline__ ull f2fma(ull a, ull b, ull c){
    ull d; asm("fma.rn.f32x2 %0,%1,%2,%3;" : "=l"(d) : "l"(a), "l"(b), "l"(c)); return d;
}

// ---------------- fused weight split prep (single launch) -------------------
__global__ __launch_bounds__(256) void wsplit_all_kernel(
    const float* __restrict__ qkv_w, const float* __restrict__ out_w,
    const float* __restrict__ ff1_w, const float* __restrict__ ff2_w,
    __nv_bfloat16* __restrict__ hi, __nv_bfloat16* __restrict__ lo)
{
    int i = (blockIdx.x*256 + threadIdx.x)*4;
    if (i >= WTOT) return;
    const float* src;
    int off;
    if (i < WOUT_OFF)       { src = qkv_w; off = i - WQKV_OFF; }
    else if (i < WFF1_OFF)  { src = out_w; off = i - WOUT_OFF; }
    else if (i < WFF2_OFF)  { src = ff1_w; off = i - WFF1_OFF; }
    else                    { src = ff2_w; off = i - WFF2_OFF; }
    float4 v = *(const float4*)(src + off);
    unsigned h0, l0, h1, l1;
    split2(v.x, v.y, h0, l0); split2(v.z, v.w, h1, l1);
    *(unsigned*)(hi+i) = h0; *(unsigned*)(hi+i+2) = h1;
    *(unsigned*)(lo+i) = l0; *(unsigned*)(lo+i+2) = l1;
}

#define LDT 40                       // smem row stride in bf16 (32 + 8 pad)
#define GARR (128*LDT*2)             // 10240 B per 128-row array
#define GSTAGE (4*GARR)              // 40960 B per stage
#define G_SMEM (2*GSTAGE)            // 81920 B

// ============ GEMM BN=128, pre-split bf16, cp.async, ldmatrix ==============
__global__ __launch_bounds__(256) void tgemm_b(
    const __nv_bfloat16* __restrict__ AH_, const __nv_bfloat16* __restrict__ AL_,
    const __nv_bfloat16* __restrict__ WH_, const __nv_bfloat16* __restrict__ WL_,
    const float* __restrict__ bias, float* __restrict__ Cf,
    __nv_bfloat16* __restrict__ CH_, __nv_bfloat16* __restrict__ CL_,
    int K, int lda, int ldw, int ldc,
    int act, int resid, int hasb, int split, int qscale)
{
    extern __shared__ char smem[];
    unsigned sb = smem_u32(smem);

    int tid = threadIdx.x, wid = tid >> 5, lane = tid & 31;
    int g = lane >> 2, tg = lane & 3;
    int q8 = lane >> 3, lr8 = lane & 7;
    int rw = (wid >> 2) * 64, cw = (wid & 3) * 32;
    int bm = blockIdx.y * 128, bn = blockIdx.x * 128;

    float acc[4][4][4];
    #pragma unroll
    for (int i = 0; i < 4; i++)
        #pragma unroll
        for (int j = 0; j < 4; j++)
            #pragma unroll
            for (int p = 0; p < 4; p++) acc[i][j][p] = 0.f;

    int row = tid >> 1, half = tid & 1;
    int nch = K >> 5;

    {
        unsigned dst = sb + (row*LDT + half*16)*2;
        const __nv_bfloat16* a = AH_ + (size_t)(bm+row)*lda + half*16;
        const __nv_bfloat16* a2 = AL_ + (size_t)(bm+row)*lda + half*16;
        const __nv_bfloat16* w = WH_ + (size_t)(bn+row)*ldw + half*16;
        const __nv_bfloat16* w2 = WL_ + (size_t)(bn+row)*ldw + half*16;
        CP16(dst, a); CP16(dst+16, a+8);
        CP16(dst+GARR, a2); CP16(dst+GARR+16, a2+8);
        CP16(dst+2*GARR, w); CP16(dst+2*GARR+16, w+8);
        CP16(dst+3*GARR, w2); CP16(dst+3*GARR+16, w2+8);
        CPC();
    }

    for (int c = 0; c < nch; c++) {
        CPW0();
        __syncthreads();
        if (c + 1 < nch) {
            unsigned dst = sb + ((c+1)&1)*GSTAGE + (row*LDT + half*16)*2;
            const __nv_bfloat16* a = AH_ + (size_t)(bm+row)*lda + (c+1)*32 + half*16;
            const __nv_bfloat16* a2 = AL_ + (size_t)(bm+row)*lda + (c+1)*32 + half*16;
            const __nv_bfloat16* w = WH_ + (size_t)(bn+row)*ldw + (c+1)*32 + half*16;
            const __nv_bfloat16* w2 = WL_ + (size_t)(bn+row)*ldw + (c+1)*32 + half*16;
            CP16(dst, a); CP16(dst+16, a+8);
            CP16(dst+GARR, a2); CP16(dst+GARR+16, a2+8);
            CP16(dst+2*GARR, w); CP16(dst+2*GARR+16, w+8);
            CP16(dst+3*GARR, w2); CP16(dst+3*GARR+16, w2+8);
            CPC();
        }
        unsigned sAH = sb + (c&1)*GSTAGE;
        unsigned sAL = sAH + GARR;
        unsigned sWH = sAH + 2*GARR;
        unsigned sWL = sAH + 3*GARR;
        #pragma unroll
        for (int ks = 0; ks < 2; ks++) {
            int k0 = ks * 16;
            unsigned ah[4][4], al[4][4], bh[2][4], bl[2][4];
            #pragma unroll
            for (int mt = 0; mt < 4; mt++) {
                unsigned off = (unsigned)((rw + mt*16 + (q8&1)*8 + lr8)*LDT + k0 + (q8>>1)*8)*2;
                ldmx4(ah[mt], sAH + off);
                ldmx4(al[mt], sAL + off);
            }
            #pragma unroll
            for (int ntp = 0; ntp < 2; ntp++) {
                unsigned off = (unsigned)((cw + ntp*16 + (q8>>1)*8 + lr8)*LDT + k0 + (q8&1)*8)*2;
                ldmx4(bh[ntp], sWH + off);
                ldmx4(bl[ntp], sWL + off);
            }
            #pragma unroll
            for (int mt = 0; mt < 4; mt++)
                #pragma unroll
                for (int nt = 0; nt < 4; nt++) {
                    const unsigned* ph = &bh[nt>>1][(nt&1)*2];
                    const unsigned* pl = &bl[nt>>1][(nt&1)*2];
                    mma16816(acc[mt][nt], ah[mt], ph);
                    mma16816(acc[mt][nt], ah[mt], pl);
                    mma16816(acc[mt][nt], al[mt], ph);
                }
        }
    }
    #pragma unroll
    for (int mt = 0; mt < 4; mt++) {
        #pragma unroll
        for (int nt = 0; nt < 4; nt++) {
            int r0 = bm + rw + mt*16 + g;
            int col = bn + cw + nt*8 + tg*2;
            #pragma unroll
            for (int half2 = 0; half2 < 2; half2++) {
                int r = r0 + half2*8;
                float v0 = acc[mt][nt][half2*2+0];
                float v1 = acc[mt][nt][half2*2+1];
                if (hasb) { v0 += bias[col]; v1 += bias[col+1]; }
                if (act)  { v0 = gelu_exact(v0); v1 = gelu_exact(v1); }
                if (split) {
                    if (qscale && col < 512) { v0 *= 0.125f; v1 *= 0.125f; }
                    unsigned hh, ll;
                    split2(v0, v1, hh, ll);
                    *(unsigned*)(CH_ + (size_t)r*ldc + col) = hh;
                    *(unsigned*)(CL_ + (size_t)r*ldc + col) = ll;
                } else {
                    float* cp = Cf + (size_t)r * ldc + col;
                    if (resid) {
                        float2 old = *(float2*)cp;
                        v0 += old.x; v1 += old.y;
                    }
                    float2 ov = {v0, v1};
                    *(float2*)cp = ov;
                }
            }
        }
    }
}

// ============ GEMM BN=64 (wave fill for narrow N) ==========================
#define G64_WARR (64*LDT*2)              // 5120 B
#define G64_STAGE (2*GARR + 2*G64_WARR)  // 30720 B
#define G64_SMEM (2*G64_STAGE)           // 61440 B

__global__ __launch_bounds__(256) void tgemm_b64(
    const __nv_bfloat16* __restrict__ AH_, const __nv_bfloat16* __restrict__ AL_,
    const __nv_bfloat16* __restrict__ WH_, const __nv_bfloat16* __restrict__ WL_,
    const float* __restrict__ bias, float* __restrict__ Cf,
    __nv_bfloat16* __restrict__ CH_, __nv_bfloat16* __restrict__ CL_,
    int K, int lda, int ldw, int ldc,
    int act, int resid, int hasb, int split)
{
    extern __shared__ char smem[];
    unsigned sb = smem_u32(smem);

    int tid = threadIdx.x, wid = tid >> 5, lane = tid & 31;
    int g = lane >> 2, tg = lane & 3;
    int q8 = lane >> 3, lr8 = lane & 7;
    int rw = (wid >> 2) * 64, cw = (wid & 3) * 16;
    int bm = blockIdx.y * 128, bn = blockIdx.x * 64;

    float acc[4][2][4];
    #pragma unroll
    for (int i = 0; i < 4; i++)
        #pragma unroll
        for (int j = 0; j < 2; j++)
            #pragma unroll
            for (int p = 0; p < 4; p++) acc[i][j][p] = 0.f;

    int row = tid >> 1, half = tid & 1;
    int roww = tid >> 2, colq = (tid & 3) * 8;
    int nch = K >> 5;

    {
        unsigned dstA = sb + (row*LDT + half*16)*2;
        const __nv_bfloat16* a = AH_ + (size_t)(bm+row)*lda + half*16;
        const __nv_bfloat16* a2 = AL_ + (size_t)(bm+row)*lda + half*16;
        CP16(dstA, a); CP16(dstA+16, a+8);
        CP16(dstA+GARR, a2); CP16(dstA+GARR+16, a2+8);
        unsigned dstW = sb + 2*GARR + (roww*LDT + colq)*2;
        const __nv_bfloat16* w = WH_ + (size_t)(bn+roww)*ldw + colq;
        const __nv_bfloat16* w2 = WL_ + (size_t)(bn+roww)*ldw + colq;
        CP16(dstW, w);
        CP16(dstW+G64_WARR, w2);
        CPC();
    }

    for (int c = 0; c < nch; c++) {
        CPW0();
        __syncthreads();
        if (c + 1 < nch) {
            unsigned st = ((c+1)&1)*G64_STAGE;
            unsigned dstA = sb + st + (row*LDT + half*16)*2;
            const __nv_bfloat16* a = AH_ + (size_t)(bm+row)*lda + (c+1)*32 + half*16;
            const __nv_bfloat16* a2 = AL_ + (size_t)(bm+row)*lda + (c+1)*32 + half*16;
            CP16(dstA, a); CP16(dstA+16, a+8);
            CP16(dstA+GARR, a2); CP16(dstA+GARR+16, a2+8);
            unsigned dstW = sb + st + 2*GARR + (roww*LDT + colq)*2;
            const __nv_bfloat16* w = WH_ + (size_t)(bn+roww)*ldw + (c+1)*32 + colq;
            const __nv_bfloat16* w2 = WL_ + (size_t)(bn+roww)*ldw + (c+1)*32 + colq;
            CP16(dstW, w);
            CP16(dstW+G64_WARR, w2);
            CPC();
        }
        unsigned sAH = sb + (c&1)*G64_STAGE;
        unsigned sAL = sAH + GARR;
        unsigned sWH = sAH + 2*GARR;
        unsigned sWL = sWH + G64_WARR;
        #pragma unroll
        for (int ks = 0; ks < 2; ks++) {
            int k0 = ks * 16;
            unsigned ah[4][4], al[4][4], bh4[4], bl4[4];
            #pragma unroll
            for (int mt = 0; mt < 4; mt++) {
                unsigned off = (unsigned)((rw + mt*16 + (q8&1)*8 + lr8)*LDT + k0 + (q8>>1)*8)*2;
                ldmx4(ah[mt], sAH + off);
                ldmx4(al[mt], sAL + off);
            }
            {
                unsigned off = (unsigned)((cw + (q8>>1)*8 + lr8)*LDT + k0 + (q8&1)*8)*2;
                ldmx4(bh4, sWH + off);
                ldmx4(bl4, sWL + off);
            }
            #pragma unroll
            for (int mt = 0; mt < 4; mt++)
                #pragma unroll
                for (int nt = 0; nt < 2; nt++) {
                    mma16816(acc[mt][nt], ah[mt], bh4 + nt*2);
                    mma16816(acc[mt][nt], ah[mt], bl4 + nt*2);
                    mma16816(acc[mt][nt], al[mt], bh4 + nt*2);
                }
        }
    }
    #pragma unroll
    for (int mt = 0; mt < 4; mt++) {
        #pragma unroll
        for (int nt = 0; nt < 2; nt++) {
            int r0 = bm + rw + mt*16 + g;
            int col = bn + cw + nt*8 + tg*2;
            #pragma unroll
            for (int half2 = 0; half2 < 2; half2++) {
                int r = r0 + half2*8;
                float v0 = acc[mt][nt][half2*2+0];
                float v1 = acc[mt][nt][half2*2+1];
                if (hasb) { v0 += bias[col]; v1 += bias[col+1]; }
                if (act)  { v0 = gelu_exact(v0); v1 = gelu_exact(v1); }
                if (split) {
                    unsigned hh, ll;
                    split2(v0, v1, hh, ll);
                    *(unsigned*)(CH_ + (size_t)r*ldc + col) = hh;
                    *(unsigned*)(CL_ + (size_t)r*ldc + col) = ll;
                } else {
                    float* cp = Cf + (size_t)r * ldc + col;
                    if (resid) {
                        float2 old = *(float2*)cp;
                        v0 += old.x; v1 += old.y;
                    }
                    float2 ov = {v0, v1};
                    *(float2*)cp = ov;
                }
            }
        }
    }
}

// ==================== flash attention ======================================
#define FQS 72
#define FARR (128*FQS*2)             // 18432 B
#define FQH 0
#define FQL FARR
#define FST(s) (2*FARR + (s)*4*FARR)
#define FA_SMEM (2*FARR + 2*4*FARR)  // 184320 B

__global__ __launch_bounds__(256) void flash_kernel(
    const __nv_bfloat16* __restrict__ qh, const __nv_bfloat16* __restrict__ ql,
    __nv_bfloat16* __restrict__ oh, __nv_bfloat16* __restrict__ ol)
{
    extern __shared__ char fsm[];
    unsigned sb = smem_u32(fsm);

    int tid = threadIdx.x, wid = tid >> 5, lane = tid & 31;
    int g = lane >> 2, tg = lane & 3;
    int q8 = lane >> 3, lr8 = lane & 7;
    int z = blockIdx.y;
    int b = z >> 3, h = z & 7;
    size_t base = (size_t)b * LTOK * 1536;
    int q0 = blockIdx.x * 128;

    int row = tid >> 1, half = tid & 1;

    {
        unsigned dq = sb + (row*FQS + half*32)*2;
        const __nv_bfloat16* sq = qh + base + (size_t)(q0+row)*1536 + h*64 + half*32;
        const __nv_bfloat16* sq2 = ql + base + (size_t)(q0+row)*1536 + h*64 + half*32;
        #pragma unroll
        for (int j = 0; j < 4; j++) {
            CP16(dq + j*16, sq + j*8);
            CP16(dq + FARR + j*16, sq2 + j*8);
        }
        unsigned dk = sb + FST(0) + (row*FQS + half*32)*2;
        const __nv_bfloat16* sk = qh + base + (size_t)row*1536 + 512 + h*64 + half*32;
        const __nv_bfloat16* sk2 = ql + base + (size_t)row*1536 + 512 + h*64 + half*32;
        const __nv_bfloat16* sv = qh + base + (size_t)row*1536 + 1024 + h*64 + half*32;
        const __nv_bfloat16* sv2 = ql + base + (size_t)row*1536 + 1024 + h*64 + half*32;
        #pragma unroll
        for (int j = 0; j < 4; j++) {
            CP16(dk + j*16, sk + j*8);
            CP16(dk + FARR + j*16, sk2 + j*8);
            CP16(dk + 2*FARR + j*16, sv + j*8);
            CP16(dk + 3*FARR + j*16, sv2 + j*8);
        }
        CPC();
    }

    float acco[8][4];
    #pragma unroll
    for (int i = 0; i < 8; i++)
        #pragma unroll
        for (int p = 0; p < 4; p++) acco[i][p] = 0.f;
    float m0 = -3.402823466e38f, m1 = -3.402823466e38f, l0s = 0.f, l1s = 0.f;

    for (int t = 0; t < LTOK/128; t++) {
        CPW0();
        __syncthreads();
        if (t + 1 < LTOK/128) {
            unsigned dk = sb + FST((t+1)&1) + (row*FQS + half*32)*2;
            size_t ro = base + (size_t)((t+1)*128+row)*1536 + h*64 + half*32;
            const __nv_bfloat16* sk = qh + ro + 512;
            const __nv_bfloat16* sk2 = ql + ro + 512;
            const __nv_bfloat16* sv = qh + ro + 1024;
            const __nv_bfloat16* sv2 = ql + ro + 1024;
            #pragma unroll
            for (int j = 0; j < 4; j++) {
                CP16(dk + j*16, sk + j*8);
                CP16(dk + FARR + j*16, sk2 + j*8);
                CP16(dk + 2*FARR + j*16, sv + j*8);
                CP16(dk + 3*FARR + j*16, sv2 + j*8);
            }
            CPC();
        }
        unsigned sKH = sb + FST(t&1);
        unsigned sKL = sKH + FARR;
        unsigned sVH = sKH + 2*FARR;
        unsigned sVL = sKH + 3*FARR;

        float accs[16][4];
        #pragma unroll
        for (int nt = 0; nt < 16; nt++)
            #pragma unroll
            for (int p = 0; p < 4; p++) accs[nt][p] = 0.f;
        #pragma unroll
        for (int ks = 0; ks < 4; ks++) {
            int k0 = ks*16;
            unsigned aqh[4], aql[4];
            unsigned aoff = (unsigned)((wid*16 + (q8&1)*8 + lr8)*FQS + k0 + (q8>>1)*8)*2;
            ldmx4(aqh, sb + FQH + aoff);
            ldmx4(aql, sb + FQL + aoff);
            #pragma unroll
            for (int ntp = 0; ntp < 8; ntp++) {
                unsigned boff = (unsigned)((ntp*16 + (q8>>1)*8 + lr8)*FQS + k0 + (q8&1)*8)*2;
                unsigned bh4[4], bl4[4];
                ldmx4(bh4, sKH + boff);
                ldmx4(bl4, sKL + boff);
                mma16816(accs[2*ntp],   aqh, bh4);
                mma16816(accs[2*ntp],   aqh, bl4);
                mma16816(accs[2*ntp],   aql, bh4);
                mma16816(accs[2*ntp+1], aqh, bh4+2);
                mma16816(accs[2*ntp+1], aqh, bl4+2);
                mma16816(accs[2*ntp+1], aql, bh4+2);
            }
        }

        float mx0 = -3.402823466e38f, mx1 = -3.402823466e38f;
        #pragma unroll
        for (int nt = 0; nt < 16; nt++) {
            mx0 = fmaxf(mx0, fmaxf(accs[nt][0], accs[nt][1]));
            mx1 = fmaxf(mx1, fmaxf(accs[nt][2], accs[nt][3]));
        }
        mx0 = fmaxf(mx0, __shfl_xor_sync(0xffffffffu, mx0, 1));
        mx0 = fmaxf(mx0, __shfl_xor_sync(0xffffffffu, mx0, 2));
        mx1 = fmaxf(mx1, __shfl_xor_sync(0xffffffffu, mx1, 1));
        mx1 = fmaxf(mx1, __shfl_xor_sync(0xffffffffu, mx1, 2));
        float mn0 = fmaxf(m0, mx0), mn1 = fmaxf(m1, mx1);
        float c0 = __expf(m0 - mn0), c1 = __expf(m1 - mn1);
        float s0 = 0.f, s1 = 0.f;
        #pragma unroll
        for (int nt = 0; nt < 16; nt++) {
            accs[nt][0] = __expf(accs[nt][0] - mn0);
            accs[nt][1] = __expf(accs[nt][1] - mn0);
            accs[nt][2] = __expf(accs[nt][2] - mn1);
            accs[nt][3] = __expf(accs[nt][3] - mn1);
            s0 += accs[nt][0] + accs[nt][1];
            s1 += accs[nt][2] + accs[nt][3];
        }
        s0 += __shfl_xor_sync(0xffffffffu, s0, 1);
        s0 += __shfl_xor_sync(0xffffffffu, s0, 2);
        s1 += __shfl_xor_sync(0xffffffffu, s1, 1);
        s1 += __shfl_xor_sync(0xffffffffu, s1, 2);
        l0s = l0s * c0 + s0;
        l1s = l1s * c1 + s1;
        m0 = mn0; m1 = mn1;
        #pragma unroll
        for (int i = 0; i < 8; i++) {
            acco[i][0] *= c0; acco[i][1] *= c0;
            acco[i][2] *= c1; acco[i][3] *= c1;
        }

        #pragma unroll
        for (int pks = 0; pks < 8; pks++) {
            unsigned aph[4], apl[4];
            split2(accs[2*pks][0],   accs[2*pks][1],   aph[0], apl[0]);
            split2(accs[2*pks][2],   accs[2*pks][3],   aph[1], apl[1]);
            split2(accs[2*pks+1][0], accs[2*pks+1][1], aph[2], apl[2]);
            split2(accs[2*pks+1][2], accs[2*pks+1][3], aph[3], apl[3]);
            #pragma unroll
            for (int ntp2 = 0; ntp2 < 4; ntp2++) {
                unsigned voff = (unsigned)((pks*16 + (q8&1)*8 + lr8)*FQS + ntp2*16 + (q8>>1)*8)*2;
                unsigned bvh[4], bvl[4];
                ldmx4t(bvh, sVH + voff);
                ldmx4t(bvl, sVL + voff);
                mma16816(acco[2*ntp2],   aph, bvh);
                mma16816(acco[2*ntp2],   aph, bvl);
                mma16816(acco[2*ntp2],   apl, bvh);
                mma16816(acco[2*ntp2+1], aph, bvh+2);
                mma16816(acco[2*ntp2+1], aph, bvl+2);
                mma16816(acco[2*ntp2+1], apl, bvh+2);
            }
        }
    }

    float inv0 = 1.0f / l0s, inv1 = 1.0f / l1s;
    int orow = q0 + wid*16 + g;
    #pragma unroll
    for (int nt2 = 0; nt2 < 8; nt2++) {
        int col = h*64 + nt2*8 + tg*2;
        unsigned hh, ll;
        split2(acco[nt2][0]*inv0, acco[nt2][1]*inv0, hh, ll);
        *(unsigned*)(oh + (size_t)(b*LTOK + orow) * EDIM + col) = hh;
        *(unsigned*)(ol + (size_t)(b*LTOK + orow) * EDIM + col) = ll;
        split2(acco[nt2][2]*inv1, acco[nt2][3]*inv1, hh, ll);
        *(unsigned*)(oh + (size_t)(b*LTOK + orow + 8) * EDIM + col) = hh;
        *(unsigned*)(ol + (size_t)(b*LTOK + orow + 8) * EDIM + col) = ll;
    }
}

// ---------------- FPS -------------------------------------------------------
__global__ __launch_bounds__(512) void fps_kernel(const float* __restrict__ xyzs) {
    int blk = blockIdx.x;
    int b = blk / TO, j = blk % TO;
    const float* P = xyzs + (size_t)(b*NT + 2*j)*NP*3;
    int tid = threadIdx.x;
    float px[8], py[8], pz[8], dist[8];
    #pragma unroll
    for (int i = 0; i < 8; i++) {
        int p = tid + i*512;
        px[i] = P[p*3+0]; py[i] = P[p*3+1]; pz[i] = P[p*3+2];
        dist[i] = 1e10f;
    }
    __shared__ float sbx, sby, sbz;
    __shared__ float swv[16];
    __shared__ int   swi[16];
    float* anch = g_anchor + (size_t)blk*MM*3;
    if (tid == 0) {
        sbx = P[0]; sby = P[1]; sbz = P[2];
        anch[0] = P[0]; anch[1] = P[1]; anch[2] = P[2];
    }
    __syncthreads();
    for (int s = 1; s < MM; s++) {
        float bx = sbx, by = sby, bz = sbz;
        float bestv = -1.0f; int besti = 0x7fffffff;
        #pragma unroll
        for (int i = 0; i < 8; i++) {
            float dx = __fsub_rn(px[i], bx);
            float dy = __fsub_rn(py[i], by);
            float dz = __fsub_rn(pz[i], bz);
            float d = __fadd_rn(__fadd_rn(__fmul_rn(dx,dx), __fmul_rn(dy,dy)), __fmul_rn(dz,dz));
            float nd = fminf(dist[i], d);
            dist[i] = nd;
            int p = tid + i*512;
            if (nd > bestv || (nd == bestv && p < besti)) { bestv = nd; besti = p; }
        }
        #pragma unroll
        for (int off = 16; off; off >>= 1) {
            float ov = __shfl_down_sync(0xffffffffu, bestv, off);
            int   oi = __shfl_down_sync(0xffffffffu, besti, off);
            if (ov > bestv || (ov == bestv && oi < besti)) { bestv = ov; besti = oi; }
        }
        if ((tid & 31) == 0) { swv[tid>>5] = bestv; swi[tid>>5] = besti; }
        __syncthreads();
        if (tid == 0) {
            float v = swv[0]; int ii = swi[0];
            #pragma unroll
            for (int w = 1; w < 16; w++)
                if (swv[w] > v || (swv[w] == v && swi[w] < ii)) { v = swv[w]; ii = swi[w]; }
            float x0 = P[ii*3+0], y0 = P[ii*3+1], z0 = P[ii*3+2];
            sbx = x0; sby = y0; sbz = z0;
            anch[s*3+0] = x0; anch[s*3+1] = y0; anch[s*3+2] = z0;
        }
        __syncthreads();
    }
}

// ---------------- Ball query ------------------------------------------------
__global__ __launch_bounds__(128) void ball_kernel(const float* __restrict__ xyzs) {
    int w = blockIdx.x*4 + (threadIdx.x >> 5);
    int lane = threadIdx.x & 31;
    int o = w / NTOK;
    int tok = w % NTOK;
    int b = tok / LTOK, loc = tok % LTOK, j = loc / MM;
    int pf = 2*j + o;
    int of = (pf == 0) ? 0 : (pf - 1);
    const float* P = xyzs + (size_t)(b*NT + of)*NP*3;
    float ax = g_anchor[tok*3+0], ay = g_anchor[tok*3+1], az = g_anchor[tok*3+2];
    int* out = g_ball + ((size_t)o*NTOK + tok)*KSAMP;
    int cnt = 0, first = 0; bool found = false;
    for (int base = 0; base < NP; base += 32) {
        int p = base + lane;
        float x = P[p*3+0], y = P[p*3+1], z = P[p*3+2];
        float dx = __fsub_rn(ax,x), dy = __fsub_rn(ay,y), dz = __fsub_rn(az,z);
        float d2 = __fadd_rn(__fadd_rn(__fmul_rn(dx,dx), __fmul_rn(dy,dy)), __fmul_rn(dz,dz));
        bool inside = d2 < RAD2;
        unsigned msk = __ballot_sync(0xffffffffu, inside);
        if (!found && msk) { first = base + __ffs(msk) - 1; found = true; }
        int pos = cnt + __popc(msk & ((1u << lane) - 1u));
        if (inside && pos < KSAMP) out[pos] = p;
        cnt += __popc(msk);
        if (cnt >= KSAMP) break;
    }
    if (lane >= cnt) out[lane] = found ? first : 0;
}

// ---------------- grouped conv + max pool (f32x2 packed over k-pairs) ------
__global__ __launch_bounds__(128) void conv_kernel(
    const float* __restrict__ xyzs, const float* __restrict__ oldf,
    const float* __restrict__ Wd, const float* __restrict__ Wf,
    float* __restrict__ dout)
{
    int tok = blockIdx.x;
    int b = tok / LTOK, loc = tok % LTOK, j = loc / MM;
    int tid = threadIdx.x;
    __shared__ float sd[KSAMP][4];
    __shared__ float sf[KSAMP][2];
    float ax = g_anchor[tok*3+0], ay = g_anchor[tok*3+1], az = g_anchor[tok*3+2];

    // weights packed {w,w} for broadcast across the k-pair
    ull pwd[4][4], pwf[4][2];
    float vmax[4];
    #pragma unroll
    for (int r = 0; r < 4; r++) {
        int d = tid + 128*r;
        #pragma unroll
        for (int c = 0; c < 4; c++) { float w = Wd[d*4+c]; pwd[r][c] = pk2(w, w); }
        #pragma unroll
        for (int c = 0; c < 2; c++) { float w = Wf[d*2+c]; pwf[r][c] = pk2(w, w); }
        vmax[r] = -3.402823466e38f;
    }
    for (int o = 0; o < 3; o++) {
        int pf = 2*j + o;
        int of = (pf == 0) ? 0 : (pf - 1);
        const float* P = xyzs + (size_t)(b*NT + of)*NP*3;
        const float* F = oldf + (size_t)(b*NT + of)*2*NP;
        __syncthreads();
        if (tid < KSAMP) {
            int idx = g_ball[((size_t)o*NTOK + tok)*KSAMP + tid];
            sd[tid][0] = P[idx*3+0] - ax;
            sd[tid][1] = P[idx*3+1] - ay;
            sd[tid][2] = P[idx*3+2] - az;
            sd[tid][3] = (float)(o - 1);
            sf[tid][0] = F[idx];
            sf[tid][1] = F[NP + idx];
        }
        __syncthreads();
        float o3 = (float)(o - 1);
        ull pd3 = pk2(o3, o3);
        #pragma unroll 4
        for (int k = 0; k < KSAMP; k += 2) {
            ull pd0 = pk2(sd[k][0], sd[k+1][0]);
            ull pd1 = pk2(sd[k][1], sd[k+1][1]);
            ull pd2 = pk2(sd[k][2], sd[k+1][2]);
            ull pf0 = pk2(sf[k][0], sf[k+1][0]);
            ull pf1 = pk2(sf[k][1], sf[k+1][1]);
            #pragma unroll
            for (int r = 0; r < 4; r++) {
                ull de = f2mul(pwd[r][0], pd0);
                de = f2fma(pwd[r][1], pd1, de);
                de = f2fma(pwd[r][2], pd2, de);
                de = f2fma(pwd[r][3], pd3, de);
                ull fe = f2mul(pwf[r][0], pf0);
                fe = f2fma(pwf[r][1], pf1, fe);
                ull pr = f2mul(de, fe);
                float a, bb2;
                upk2(a, bb2, pr);
                vmax[r] = fmaxf(vmax[r], fmaxf(a, bb2));
            }
        }
    }
    #pragma unroll
    for (int r = 0; r < 4; r++)
        dout[FEAT_OFF + (size_t)tok*EDIM + tid + 128*r] = vmax[r];
}

// ---------------- pos + contrastive + relu(pos+feat) -----------------------
__global__ __launch_bounds__(512) void embed_kernel(
    const float* __restrict__ pw, const float* __restrict__ pb,
    const float* __restrict__ cw, const float* __restrict__ cb,
    float* __restrict__ dout)
{
    int tok = blockIdx.x;
    int d = threadIdx.x;
    int loc = tok % LTOK, j = loc / MM;
    float ax = g_anchor[tok*3+0], ay = g_anchor[tok*3+1], az = g_anchor[tok*3+2];
    float tv = (float)(j + 1);
    float pos = pw[d*4+0]*ax + pw[d*4+1]*ay + pw[d*4+2]*az + pw[d*4+3]*tv + pb[d];
    float con = cw[d*4+0]*ax + cw[d*4+1]*ay + cw[d*4+2]*az + cw[d*4+3]*tv + cb[d];
    dout[CONTR_OFF + (size_t)tok*EDIM + d] = con;
    float feat = dout[FEAT_OFF + (size_t)tok*EDIM + d];
    g_x[(size_t)tok*EDIM + d] = fmaxf(pos + feat, 0.0f);
}

// ---------------- LayerNorm -> bf16 hi/lo ----------------------------------
__global__ __launch_bounds__(256) void ln_split_kernel(
    const float* __restrict__ x, const float* __restrict__ s,
    const float* __restrict__ bb,
    __nv_bfloat16* __restrict__ outh, __nv_bfloat16* __restrict__ outl)
{
    int tok = blockIdx.x;
    int tid = threadIdx.x;
    const float* row = x + (size_t)tok*EDIM;
    float v0 = row[tid], v1 = row[tid + 256];
    float sum = v0 + v1, sq = v0*v0 + v1*v1;
    #pragma unroll
    for (int off = 16; off; off >>= 1) {
        sum += __shfl_xor_sync(0xffffffffu, sum, off);
        sq  += __shfl_xor_sync(0xffffffffu, sq, off);
    }
    __shared__ float ssum[8], ssq[8];
    if ((tid & 31) == 0) { ssum[tid>>5] = sum; ssq[tid>>5] = sq; }
    __syncthreads();
    float ts = 0.f, tq = 0.f;
    #pragma unroll
    for (int w = 0; w < 8; w++) { ts += ssum[w]; tq += ssq[w]; }
    float mu = ts * (1.0f/512.0f);
    float var = tq * (1.0f/512.0f) - mu*mu;
    float rstd = rsqrtf(var + 1e-5f);
    float y0 = (v0 - mu)*rstd*s[tid] + bb[tid];
    float y1 = (v1 - mu)*rstd*s[tid+256] + bb[tid+256];
    __nv_bfloat16 h0 = __float2bfloat16(y0);
    __nv_bfloat16 h1 = __float2bfloat16(y1);
    outh[(size_t)tok*EDIM + tid]       = h0;
    outh[(size_t)tok*EDIM + tid + 256] = h1;
    outl[(size_t)tok*EDIM + tid]       = __float2bfloat16(y0 - __bfloat162float(h0));
    outl[(size_t)tok*EDIM + tid + 256] = __float2bfloat16(y1 - __bfloat162float(h1));
}

// ---------------- fp32 LayerNorm (head) ------------------------------------
__global__ __launch_bounds__(256) void ln_kernel(
    const float* __restrict__ x, const float* __restrict__ s,
    const float* __restrict__ bb, float* __restrict__ out)
{
    int tok = blockIdx.x;
    int tid = threadIdx.x;
    const float* row = x + (size_t)tok*EDIM;
    float v0 = row[tid], v1 = row[tid + 256];
    float sum = v0 + v1, sq = v0*v0 + v1*v1;
    #pragma unroll
    for (int off = 16; off; off >>= 1) {
        sum += __shfl_xor_sync(0xffffffffu, sum, off);
        sq  += __shfl_xor_sync(0xffffffffu, sq, off);
    }
    __shared__ float ssum[8], ssq[8];
    if ((tid & 31) == 0) { ssum[tid>>5] = sum; ssq[tid>>5] = sq; }
    __syncthreads();
    float ts = 0.f, tq = 0.f;
    #pragma unroll
    for (int w = 0; w < 8; w++) { ts += ssum[w]; tq += ssq[w]; }
    float mu = ts * (1.0f/512.0f);
    float var = tq * (1.0f/512.0f) - mu*mu;
    float rstd = rsqrtf(var + 1e-5f);
    out[(size_t)tok*EDIM + tid]       = (v0 - mu)*rstd*s[tid] + bb[tid];
    out[(size_t)tok*EDIM + tid + 256] = (v1 - mu)*rstd*s[tid+256] + bb[tid+256];
}

// ---------------- head ------------------------------------------------------
// two-phase max pool: 48 blocks of partials, then reduce 12 chunks
__global__ __launch_bounds__(512) void pool1_kernel() {
    int chunk = blockIdx.x, b = blockIdx.y;
    int d = threadIdx.x;
    float v = -3.402823466e38f;
    const float* p = g_x + ((size_t)b*LTOK + chunk*128)*EDIM + d;
    #pragma unroll 4
    for (int i = 0; i < 128; i++) v = fmaxf(v, p[(size_t)i*EDIM]);
    g_poolp[((size_t)b*12 + chunk)*EDIM + d] = v;
}
__global__ __launch_bounds__(512) void pool2_kernel() {
    int b = blockIdx.x;
    int d = threadIdx.x;
    float v = -3.402823466e38f;
    #pragma unroll
    for (int c = 0; c < 12; c++) v = fmaxf(v, g_poolp[((size_t)b*12 + c)*EDIM + d]);
    g_pool[b*EDIM + d] = v;
}
__global__ __launch_bounds__(256) void head1_kernel(
    const float* __restrict__ W, const float* __restrict__ bias)
{
    int out = blockIdx.x*8 + (threadIdx.x >> 5);
    int lane = threadIdx.x & 31;
    int b = out >> 10, jj = out & 1023;
    const float* xr = g_hln + b*EDIM;
    const float* wr = W + (size_t)jj*EDIM;
    float s = 0.f;
    for (int d = lane; d < EDIM; d += 32) s += xr[d]*wr[d];
    #pragma unroll
    for (int off = 16; off; off >>= 1) s += __shfl_xor_sync(0xffffffffu, s, off);
    if (lane == 0) g_h1[out] = gelu_exact(s + bias[jj]);
}
__global__ __launch_bounds__(128) void head2_kernel(
    const float* __restrict__ W, const float* __restrict__ bias,
    float* __restrict__ dout)
{
    int out = blockIdx.x*4 + (threadIdx.x >> 5);
    int lane = threadIdx.x & 31;
    int b = out / NCLS, c = out % NCLS;
    float s = 0.f;
    for (int d = lane; d < MLPD; d += 32) s += g_h1[b*MLPD + d]*W[(size_t)c*MLPD + d];
    #pragma unroll
    for (int off = 16; off; off >>= 1) s += __shfl_xor_sync(0xffffffffu, s, off);
    if (lane == 0) dout[out] = s + bias[c];
}

// ---------------- launch ---------------------------------------------------
extern "C" void kernel_launch(void* const* d_in, const int* in_sizes, int n_in,
                              void* d_out, int out_size) {
    const float* xyzs      = (const float*)d_in[0];
    const float* oldf      = (const float*)d_in[1];
    const float* conv_d_w  = (const float*)d_in[2];
    const float* conv_f_w  = (const float*)d_in[3];
    const float* pos_w     = (const float*)d_in[4];
    const float* pos_b     = (const float*)d_in[5];
    const float* contr_w   = (const float*)d_in[6];
    const float* contr_b   = (const float*)d_in[7];
    const float* ln1_s     = (const float*)d_in[8];
    const float* ln1_b     = (const float*)d_in[9];
    const float* qkv_w     = (const float*)d_in[10];
    const float* out_w     = (const float*)d_in[11];
    const float* out_b     = (const float*)d_in[12];
    const float* ln2_s     = (const float*)d_in[13];
    const float* ln2_b     = (const float*)d_in[14];
    const float* ff1_w     = (const float*)d_in[15];
    const float* ff1_b     = (const float*)d_in[16];
    const float* ff2_w     = (const float*)d_in[17];
    const float* ff2_b     = (const float*)d_in[18];
    const float* head_ln_s = (const float*)d_in[19];
    const float* head_ln_b = (const float*)d_in[20];
    const float* head1_w   = (const float*)d_in[21];
    const float* head1_b   = (const float*)d_in[22];
    const float* head2_w   = (const float*)d_in[23];
    const float* head2_b   = (const float*)d_in[24];
    float* out = (float*)d_out;

    float *px, *ppool, *phln;
    __nv_bfloat16 *pwh, *pwl, *phh, *phl, *pqh, *pql, *poh, *pol, *pf1h, *pf1l;
    cudaGetSymbolAddress((void**)&px,    g_x);
    cudaGetSymbolAddress((void**)&ppool, g_pool);
    cudaGetSymbolAddress((void**)&phln,  g_hln);
    cudaGetSymbolAddress((void**)&pwh,   g_wh);
    cudaGetSymbolAddress((void**)&pwl,   g_wl);
    cudaGetSymbolAddress((void**)&phh,   g_hh);
    cudaGetSymbolAddress((void**)&phl,   g_hl);
    cudaGetSymbolAddress((void**)&pqh,   g_qh);
    cudaGetSymbolAddress((void**)&pql,   g_ql);
    cudaGetSymbolAddress((void**)&poh,   g_oh);
    cudaGetSymbolAddress((void**)&pol,   g_ol);
    cudaGetSymbolAddress((void**)&pf1h,  g_f1h);
    cudaGetSymbolAddress((void**)&pf1l,  g_f1l);

    cudaFuncSetAttribute(flash_kernel, cudaFuncAttributeMaxDynamicSharedMemorySize, FA_SMEM);
    cudaFuncSetAttribute(tgemm_b, cudaFuncAttributeMaxDynamicSharedMemorySize, G_SMEM);
    cudaFuncSetAttribute(tgemm_b64, cudaFuncAttributeMaxDynamicSharedMemorySize, G64_SMEM);

    // ---- one-time weight split (single fused launch; graph-safe) ----
    wsplit_all_kernel<<<WTOT/1024, 256>>>(qkv_w, out_w, ff1_w, ff2_w, pwh, pwl);

    fps_kernel<<<48, 512>>>(xyzs);
    ball_kernel<<<(3*NTOK)/4, 128>>>(xyzs);
    conv_kernel<<<NTOK, 128>>>(xyzs, oldf, conv_d_w, conv_f_w, out);
    embed_kernel<<<NTOK, 512>>>(pos_w, pos_b, contr_w, contr_b, out);

    for (int l = 0; l < 4; l++) {
        ln_split_kernel<<<NTOK, 256>>>(px, ln1_s + l*EDIM, ln1_b + l*EDIM, phh, phl);
        // QKV: split output (Q pre-scaled by 1/8)
        tgemm_b<<<dim3(12,48,1), 256, G_SMEM>>>(
            phh, phl, pwh + WQKV_OFF + (size_t)l*1536*512, pwl + WQKV_OFF + (size_t)l*1536*512,
            nullptr, nullptr, pqh, pql,
            512, 512, 512, 1536, 0,0,0, 1,1);
        // fused attention -> o hi/lo
        flash_kernel<<<dim3(LTOK/128, NB*NHEAD), 256, FA_SMEM>>>(pqh, pql, poh, pol);
        // out proj + residual (fp32 out) — BN=64
        tgemm_b64<<<dim3(8,48,1), 256, G64_SMEM>>>(
            poh, pol, pwh + WOUT_OFF + (size_t)l*512*512, pwl + WOUT_OFF + (size_t)l*512*512,
            out_b + l*EDIM, px, nullptr, nullptr,
            512, 512, 512, 512, 0,1,1, 0);
        ln_split_kernel<<<NTOK, 256>>>(px, ln2_s + l*EDIM, ln2_b + l*EDIM, phh, phl);
        // ff1 + gelu: split output — BN=64
        tgemm_b64<<<dim3(16,48,1), 256, G64_SMEM>>>(
            phh, phl, pwh + WFF1_OFF + (size_t)l*1024*512, pwl + WFF1_OFF + (size_t)l*1024*512,
            ff1_b + l*MLPD, nullptr, pf1h, pf1l,
            512, 512, 512, 1024, 1,0,1, 1);
        // ff2 + residual (fp32 out) — BN=64
        tgemm_b64<<<dim3(8,48,1), 256, G64_SMEM>>>(
            pf1h, pf1l, pwh + WFF2_OFF + (size_t)l*512*1024, pwl + WFF2_OFF + (size_t)l*512*1024,
            ff2_b + l*EDIM, px, nullptr, nullptr,
            1024, 1024, 1024, 512, 0,1,1, 0);
    }

    pool1_kernel<<<dim3(12, NB), 512>>>();
    pool2_kernel<<<NB, 512>>>();
    ln_kernel<<<NB, 256>>>(ppool, head_ln_s, head_ln_b, phln);
    head1_kernel<<<(NB*MLPD)/8, 256>>>(head1_w, head1_b);
    head2_kernel<<<NB*NCLS/4, 128>>>(head2_w, head2_b, out);
}